// round 1
// baseline (speedup 1.0000x reference)
#include <cuda_runtime.h>
#include <math.h>
#include <cuda_bf16.h>

// Problem constants
#define BSZ 4
#define TT 1024
#define DD 768
#define HH 12
#define KH 64          // head size
#define LL 6
#define VV 32000
#define FF 3072        // 4*D
#define HD 9216        // H*D (concat-head width)
#define ROWS (BSZ*TT)  // 4096

// ---------------- scratch (device globals; no allocation allowed) -------------
__device__ float g_x[(size_t)ROWS*DD];
__device__ float g_h[(size_t)ROWS*DD];
__device__ float g_q[(size_t)ROWS*DD];
__device__ float g_k[(size_t)ROWS*DD];
__device__ float g_v[(size_t)ROWS*HD];
__device__ float g_o[(size_t)ROWS*HD];
__device__ float g_p[(size_t)BSZ*HH*TT*TT];  // attention probs
__device__ float g_f[(size_t)ROWS*FF];       // MLP intermediate
__device__ float g_rl[ROWS];                 // per-row loss

// ---------------- embedding --------------------------------------------------
__global__ void embed_k(const int* __restrict__ ids, const float* __restrict__ tok,
                        const float* __restrict__ pos, float* __restrict__ x) {
    int row = blockIdx.x;
    int t = row % TT;
    int id = ids[row];
    const float* te = tok + (size_t)id * DD;
    const float* pe = pos + (size_t)t * DD;
    float* xr = x + (size_t)row * DD;
    for (int i = threadIdx.x; i < DD; i += blockDim.x)
        xr[i] = te[i] + pe[i];
}

// ---------------- layernorm --------------------------------------------------
__global__ void ln_k(const float* __restrict__ x, float* __restrict__ y,
                     const float* __restrict__ g, const float* __restrict__ b) {
    __shared__ float s1[256], s2[256];
    int row = blockIdx.x, tid = threadIdx.x;
    const float* xr = x + (size_t)row * DD;
    float sum = 0.f, sq = 0.f;
    for (int i = tid; i < DD; i += 256) { float v = xr[i]; sum += v; sq += v * v; }
    s1[tid] = sum; s2[tid] = sq; __syncthreads();
    for (int s = 128; s > 0; s >>= 1) {
        if (tid < s) { s1[tid] += s1[tid + s]; s2[tid] += s2[tid + s]; }
        __syncthreads();
    }
    float mu = s1[0] * (1.0f / DD);
    float var = s2[0] * (1.0f / DD) - mu * mu;
    float rstd = rsqrtf(var + 1e-5f);
    float* yr = y + (size_t)row * DD;
    for (int i = tid; i < DD; i += 256)
        yr[i] = (xr[i] - mu) * rstd * g[i] + b[i];
}

// ---------------- generic tiled GEMM -----------------------------------------
// C[M,N] (+)= A[M,K] * B[K,N]  (+ bias)(relu)
// B addressing supports head-blocked layouts:
//   element (d, j) at  B + (j/Nh)*hstride + d*ldb + (j%Nh)
// (standard row-major: Nh = N, hstride = 0, ldb = N)
// Batched via blockIdx.z split as z = zo*batchH + zi with per-axis offsets.
// flags: 1 = add bias, 2 = relu, 4 = accumulate into existing C
__global__ void gemm_k(const float* __restrict__ A, const float* __restrict__ Bm,
                       float* __restrict__ C,
                       int K, int lda, int ldb, int ldc,
                       int Nh, size_t hstride,
                       const float* __restrict__ bias, int flags,
                       int batchH,
                       size_t aOuter, size_t aInner,
                       size_t bOuter, size_t bInner,
                       size_t cOuter, size_t cInner) {
    int z = blockIdx.z;
    int zo = z / batchH, zi = z - zo * batchH;
    A  += zo * aOuter + zi * aInner;
    Bm += zo * bOuter + zi * bInner;
    C  += zo * cOuter + zi * cInner;

    __shared__ float As[64][17];
    __shared__ __align__(16) float Bs[16][68];

    int tid = threadIdx.x;             // 256 threads
    int tx = tid & 15, ty = tid >> 4;
    int m0 = blockIdx.y * 64;
    int n0 = blockIdx.x * 64;

    // global-load mappings (float4 per thread per tile)
    int arow = tid >> 2, acol = (tid & 3) << 2;   // A: 64x16
    int brow = tid >> 4, bcol = (tid & 15) << 2;  // B: 16x64
    int gcol = n0 + bcol;
    size_t bbase = (size_t)(gcol / Nh) * hstride + (size_t)(gcol % Nh);
    const float* aptr = A + (size_t)(m0 + arow) * lda + acol;
    const float* bptr = Bm + bbase;

    float acc[4][4] = {};
    for (int k0 = 0; k0 < K; k0 += 16) {
        float4 av = *(const float4*)(aptr + k0);
        As[arow][acol + 0] = av.x; As[arow][acol + 1] = av.y;
        As[arow][acol + 2] = av.z; As[arow][acol + 3] = av.w;
        float4 bv = *(const float4*)(bptr + (size_t)(k0 + brow) * ldb);
        Bs[brow][bcol + 0] = bv.x; Bs[brow][bcol + 1] = bv.y;
        Bs[brow][bcol + 2] = bv.z; Bs[brow][bcol + 3] = bv.w;
        __syncthreads();
#pragma unroll
        for (int kk = 0; kk < 16; kk++) {
            float a0 = As[ty * 4 + 0][kk];
            float a1 = As[ty * 4 + 1][kk];
            float a2 = As[ty * 4 + 2][kk];
            float a3 = As[ty * 4 + 3][kk];
            float4 bq = *(const float4*)&Bs[kk][tx * 4];
            acc[0][0] += a0 * bq.x; acc[0][1] += a0 * bq.y; acc[0][2] += a0 * bq.z; acc[0][3] += a0 * bq.w;
            acc[1][0] += a1 * bq.x; acc[1][1] += a1 * bq.y; acc[1][2] += a1 * bq.z; acc[1][3] += a1 * bq.w;
            acc[2][0] += a2 * bq.x; acc[2][1] += a2 * bq.y; acc[2][2] += a2 * bq.z; acc[2][3] += a2 * bq.w;
            acc[3][0] += a3 * bq.x; acc[3][1] += a3 * bq.y; acc[3][2] += a3 * bq.z; acc[3][3] += a3 * bq.w;
        }
        __syncthreads();
    }
#pragma unroll
    for (int i = 0; i < 4; i++) {
        int row = m0 + ty * 4 + i;
        float* cr = C + (size_t)row * ldc + n0 + tx * 4;
#pragma unroll
        for (int j = 0; j < 4; j++) {
            float v = acc[i][j];
            if (flags & 1) v += bias[n0 + tx * 4 + j];
            if (flags & 2) v = fmaxf(v, 0.f);
            if (flags & 4) v += cr[j];
            cr[j] = v;
        }
    }
}

// ---------------- attention scores + causal softmax ---------------------------
// one block per (t, h, b); writes prob row of length T (zeros beyond diagonal)
__global__ void attn_k(const float* __restrict__ q, const float* __restrict__ k,
                       float* __restrict__ p) {
    int t = blockIdx.x, h = blockIdx.y, b = blockIdx.z;
    int tid = threadIdx.x;  // 256
    __shared__ float qs[KH];
    __shared__ float red[256];
    const float* qr = q + (size_t)(b * TT + t) * DD + h * KH;
    if (tid < KH) qs[tid] = qr[tid];
    __syncthreads();

    float sc[4];
#pragma unroll
    for (int i = 0; i < 4; i++) {
        int s = tid + i * 256;
        if (s <= t) {
            const float* kr = k + (size_t)(b * TT + s) * DD + h * KH;
            float acc = 0.f;
#pragma unroll
            for (int kk = 0; kk < KH; kk++) acc += qs[kk] * kr[kk];
            sc[i] = acc * 0.125f;  // 1/sqrt(64)
        } else {
            sc[i] = -INFINITY;
        }
    }
    float m = fmaxf(fmaxf(sc[0], sc[1]), fmaxf(sc[2], sc[3]));
    red[tid] = m; __syncthreads();
    for (int s = 128; s > 0; s >>= 1) { if (tid < s) red[tid] = fmaxf(red[tid], red[tid + s]); __syncthreads(); }
    m = red[0]; __syncthreads();
    float lsum = 0.f;
#pragma unroll
    for (int i = 0; i < 4; i++) {
        sc[i] = (sc[i] == -INFINITY) ? 0.f : expf(sc[i] - m);
        lsum += sc[i];
    }
    red[tid] = lsum; __syncthreads();
    for (int s = 128; s > 0; s >>= 1) { if (tid < s) red[tid] += red[tid + s]; __syncthreads(); }
    float inv = 1.f / red[0];
    float* pr = p + ((size_t)(b * HH + h) * TT + t) * TT;
#pragma unroll
    for (int i = 0; i < 4; i++) pr[tid + i * 256] = sc[i] * inv;
}

// ---------------- loss --------------------------------------------------------
__global__ void loss_row_k(const float* __restrict__ logits, const int* __restrict__ tgt,
                           float* __restrict__ rl) {
    int row = blockIdx.x, tid = threadIdx.x;
    const float* lr = logits + (size_t)row * VV;
    __shared__ float red[256];
    float m = -INFINITY;
    for (int i = tid; i < VV; i += 256) m = fmaxf(m, lr[i]);
    red[tid] = m; __syncthreads();
    for (int s = 128; s > 0; s >>= 1) { if (tid < s) red[tid] = fmaxf(red[tid], red[tid + s]); __syncthreads(); }
    m = red[0]; __syncthreads();
    float sum = 0.f;
    for (int i = tid; i < VV; i += 256) sum += expf(lr[i] - m);
    red[tid] = sum; __syncthreads();
    for (int s = 128; s > 0; s >>= 1) { if (tid < s) red[tid] += red[tid + s]; __syncthreads(); }
    if (tid == 0) {
        float lse = m + logf(red[0]);
        rl[row] = lse - lr[tgt[row]];
    }
}

__global__ void loss_final_k(const float* __restrict__ rl, float* __restrict__ out) {
    __shared__ float red[256];
    int tid = threadIdx.x;
    float s = 0.f;
    for (int i = tid; i < ROWS; i += 256) s += rl[i];
    red[tid] = s; __syncthreads();
    for (int k = 128; k > 0; k >>= 1) { if (tid < k) red[tid] += red[tid + k]; __syncthreads(); }
    if (tid == 0) out[0] = red[0] * (1.0f / ROWS);
}

__global__ void fill0_k(float* p, size_t n) {
    size_t i = (size_t)blockIdx.x * blockDim.x + threadIdx.x;
    if (i < n) p[i] = 0.f;
}

// ---------------- host-side launcher helper -----------------------------------
static inline void gemm(const float* A, const float* B, float* C,
                        int M, int N, int K, int lda, int ldb, int ldc,
                        int Nh, size_t hs, const float* bias, int flags,
                        int batch = 1, int batchH = 1,
                        size_t aO = 0, size_t aI = 0,
                        size_t bO = 0, size_t bI = 0,
                        size_t cO = 0, size_t cI = 0) {
    dim3 grid(N / 64, M / 64, batch);
    gemm_k<<<grid, 256>>>(A, B, C, K, lda, ldb, ldc, Nh, hs, bias, flags,
                          batchH, aO, aI, bO, bI, cO, cI);
}

extern "C" void kernel_launch(void* const* d_in, const int* in_sizes, int n_in,
                              void* d_out, int out_size) {
    const int*   ids   = (const int*)d_in[0];
    const int*   tgt   = (const int*)d_in[1];
    const float* tok   = (const float*)d_in[2];
    const float* pos   = (const float*)d_in[3];
    const float* Wq    = (const float*)d_in[4];
    const float* Wk    = (const float*)d_in[5];
    const float* Wv    = (const float*)d_in[6];
    const float* Wproj = (const float*)d_in[7];
    const float* bproj = (const float*)d_in[8];
    const float* ln1g  = (const float*)d_in[9];
    const float* ln1b  = (const float*)d_in[10];
    const float* ln2g  = (const float*)d_in[11];
    const float* ln2b  = (const float*)d_in[12];
    const float* W1    = (const float*)d_in[13];
    const float* b1    = (const float*)d_in[14];
    const float* W2    = (const float*)d_in[15];
    const float* b2    = (const float*)d_in[16];
    const float* lnfg  = (const float*)d_in[17];
    const float* lnfb  = (const float*)d_in[18];
    const float* Whead = (const float*)d_in[19];
    const float* bhead = (const float*)d_in[20];

    float *x, *h, *q, *k, *v, *o, *p, *f, *rl;
    cudaGetSymbolAddress((void**)&x, g_x);
    cudaGetSymbolAddress((void**)&h, g_h);
    cudaGetSymbolAddress((void**)&q, g_q);
    cudaGetSymbolAddress((void**)&k, g_k);
    cudaGetSymbolAddress((void**)&v, g_v);
    cudaGetSymbolAddress((void**)&o, g_o);
    cudaGetSymbolAddress((void**)&p, g_p);
    cudaGetSymbolAddress((void**)&f, g_f);
    cudaGetSymbolAddress((void**)&rl, g_rl);

    float* out = (float*)d_out;
    const size_t NL = (size_t)ROWS * VV;  // logits element count

    // x = tok_emb[ids] + pos_emb
    embed_k<<<ROWS, 256>>>(ids, tok, pos, x);

    for (int l = 0; l < LL; l++) {
        // h = ln1(x)
        ln_k<<<ROWS, 256>>>(x, h, ln1g + l * DD, ln1b + l * DD);
        // q,k: (ROWS,768) x per-head (768,64)  -> layout [row][h*64+k]
        gemm(h, Wq + (size_t)l * HH * DD * KH, q, ROWS, DD, DD, DD, KH, DD,
             KH, (size_t)DD * KH, nullptr, 0);
        gemm(h, Wk + (size_t)l * HH * DD * KH, k, ROWS, DD, DD, DD, KH, DD,
             KH, (size_t)DD * KH, nullptr, 0);
        // v: (ROWS,768) x per-head (768,768) -> layout [row][h*768+e]
        gemm(h, Wv + (size_t)l * HH * DD * DD, v, ROWS, HD, DD, DD, DD, HD,
             DD, (size_t)DD * DD, nullptr, 0);
        // scores + causal softmax -> probs
        {
            dim3 grid(TT, HH, BSZ);
            attn_k<<<grid, 256>>>(q, k, p);
        }
        // o[b,t,h*768+e] = probs[b,h] @ v[b,:,h]   (48 batched GEMMs)
        gemm(p, v, o, TT, DD, TT, TT, HD, HD, DD, 0, nullptr, 0,
             BSZ * HH, HH,
             (size_t)HH * TT * TT, (size_t)TT * TT,
             (size_t)TT * HD, (size_t)DD,
             (size_t)TT * HD, (size_t)DD);
        // x += o @ Wproj + bproj
        gemm(o, Wproj + (size_t)l * HD * DD, x, ROWS, DD, HD, HD, DD, DD,
             DD, 0, bproj + l * DD, 1 | 4);
        // h = ln2(x)
        ln_k<<<ROWS, 256>>>(x, h, ln2g + l * DD, ln2b + l * DD);
        // f = relu(h @ W1 + b1)
        gemm(h, W1 + (size_t)l * DD * FF, f, ROWS, FF, DD, DD, FF, FF,
             FF, 0, b1 + l * FF, 1 | 2);
        // x += f @ W2 + b2
        gemm(f, W2 + (size_t)l * FF * DD, x, ROWS, DD, FF, FF, DD, DD,
             DD, 0, b2 + l * DD, 1 | 4);
    }

    // final LN + head
    ln_k<<<ROWS, 256>>>(x, h, lnfg, lnfb);

    if ((size_t)out_size >= NL) {
        gemm(h, Whead, out, ROWS, VV, DD, DD, VV, VV, VV, 0, bhead, 1);
        loss_row_k<<<ROWS, 256>>>(out, tgt, rl);
        if ((size_t)out_size >= NL + 1) {
            loss_final_k<<<1, 256>>>(rl, out + NL);
            size_t tail = (size_t)out_size - (NL + 1);
            if (tail > 0)
                fill0_k<<<(int)((tail + 255) / 256), 256>>>(out + NL + 1, tail);
        }
    } else {
        // unexpected output layout: compute loss only into out[0]
        gemm(h, Whead, f /*unused scratch alias; too small for logits, but
             this branch should not occur given out_size = B*T*V+1*/,
             ROWS, VV, DD, DD, VV, VV, VV, 0, bhead, 1);
    }
}

// round 2
// speedup vs baseline: 1.0209x; 1.0209x over previous
#include <cuda_runtime.h>
#include <math.h>
#include <stdint.h>
#include <cuda_bf16.h>

// Problem constants
#define BSZ 4
#define TT 1024
#define DD 768
#define HH 12
#define KH 64          // head size
#define LL 6
#define VV 32000
#define FF 3072        // 4*D
#define HD 9216        // H*D (concat-head width)
#define ROWS (BSZ*TT)  // 4096

// ---------------- scratch (device globals; no allocation allowed) -------------
__device__ float g_x[(size_t)ROWS*DD];
__device__ float g_h[(size_t)ROWS*DD];
__device__ float g_q[(size_t)ROWS*DD];
__device__ float g_k[(size_t)ROWS*DD];
__device__ float g_v[(size_t)ROWS*HD];
__device__ float g_o[(size_t)ROWS*HD];
__device__ float g_p[(size_t)BSZ*HH*TT*TT];  // attention probs
__device__ float g_f[(size_t)ROWS*FF];       // MLP intermediate
__device__ float g_rl[ROWS];                 // per-row loss

// ---------------- embedding --------------------------------------------------
__global__ void embed_k(const int* __restrict__ ids, const float* __restrict__ tok,
                        const float* __restrict__ pos, float* __restrict__ x) {
    int row = blockIdx.x;
    int t = row % TT;
    int id = ids[row];
    const float* te = tok + (size_t)id * DD;
    const float* pe = pos + (size_t)t * DD;
    float* xr = x + (size_t)row * DD;
    for (int i = threadIdx.x; i < DD; i += blockDim.x)
        xr[i] = te[i] + pe[i];
}

// ---------------- layernorm --------------------------------------------------
__global__ void ln_k(const float* __restrict__ x, float* __restrict__ y,
                     const float* __restrict__ g, const float* __restrict__ b) {
    __shared__ float s1[256], s2[256];
    int row = blockIdx.x, tid = threadIdx.x;
    const float* xr = x + (size_t)row * DD;
    float sum = 0.f, sq = 0.f;
    for (int i = tid; i < DD; i += 256) { float v = xr[i]; sum += v; sq += v * v; }
    s1[tid] = sum; s2[tid] = sq; __syncthreads();
    for (int s = 128; s > 0; s >>= 1) {
        if (tid < s) { s1[tid] += s1[tid + s]; s2[tid] += s2[tid + s]; }
        __syncthreads();
    }
    float mu = s1[0] * (1.0f / DD);
    float var = s2[0] * (1.0f / DD) - mu * mu;
    float rstd = rsqrtf(var + 1e-5f);
    float* yr = y + (size_t)row * DD;
    for (int i = tid; i < DD; i += 256)
        yr[i] = (xr[i] - mu) * rstd * g[i] + b[i];
}

// ---------------- tf32 helpers -----------------------------------------------
__device__ __forceinline__ uint32_t f2tf32(float f) {
    uint32_t r;
    asm("cvt.rna.tf32.f32 %0, %1;" : "=r"(r) : "f"(f));
    return r;
}

__device__ __forceinline__ void mma_tf32(float c[4], const uint32_t a[4], const uint32_t b[2]) {
    asm volatile(
        "mma.sync.aligned.m16n8k8.row.col.f32.tf32.tf32.f32 "
        "{%0,%1,%2,%3},{%4,%5,%6,%7},{%8,%9},{%0,%1,%2,%3};"
        : "+f"(c[0]), "+f"(c[1]), "+f"(c[2]), "+f"(c[3])
        : "r"(a[0]), "r"(a[1]), "r"(a[2]), "r"(a[3]), "r"(b[0]), "r"(b[1]));
}

// ---------------- tensor-core tiled GEMM (tf32) --------------------------------
// C[M,N] (+)= A[M,K] * B[K,N]  (+ bias)(relu)
// B addressing supports head-blocked layouts:
//   element (d, j) at  B + (j/Nh)*hstride + d*ldb + (j%Nh)
// Batched via blockIdx.z split as z = zo*batchH + zi with per-axis offsets.
// flags: 1 = add bias, 2 = relu, 4 = accumulate into existing C
// Requires: M % 128 == 0, N % 128 == 0, K % 16 == 0 (true for all call sites)
__global__ __launch_bounds__(256, 2)
void gemm_tc(const float* __restrict__ A, const float* __restrict__ Bm,
             float* __restrict__ C,
             int K, int lda, int ldb, int ldc,
             int Nh, size_t hstride,
             const float* __restrict__ bias, int flags,
             int batchH,
             size_t aOuter, size_t aInner,
             size_t bOuter, size_t bInner,
             size_t cOuter, size_t cInner) {
    int z = blockIdx.z;
    int zo = z / batchH, zi = z - zo * batchH;
    A  += zo * aOuter + zi * aInner;
    Bm += zo * bOuter + zi * bInner;
    C  += zo * cOuter + zi * cInner;

    // padded pitches chosen for conflict-free mma fragment reads
    __shared__ uint32_t As[2][128][20];   // [m][k], pitch 20
    __shared__ uint32_t Bs[2][16][136];   // [k][n], pitch 136

    const int tid  = threadIdx.x;
    const int lane = tid & 31;
    const int warp = tid >> 5;          // 8 warps: 4 along M x 2 along N
    const int wm = warp & 3;
    const int wn = warp >> 2;
    const int m0 = blockIdx.y * 128;
    const int n0 = blockIdx.x * 128;

    // global load mappings
    const int aRow = tid >> 2;            // 0..63 (and +64 for 2nd load)
    const int aCol = (tid & 3) << 2;      // 0,4,8,12
    const int bRow = tid >> 5;            // 0..7 (and +8 for 2nd load)
    const int bCol = (tid & 31) << 2;     // 0..124

    const float* aP = A + (size_t)(m0 + aRow) * lda + aCol;
    const int gcol = n0 + bCol;
    const float* bP = Bm + (size_t)(gcol / Nh) * hstride + (size_t)(gcol % Nh);

    float acc[2][8][4];
#pragma unroll
    for (int t = 0; t < 2; t++)
#pragma unroll
        for (int n = 0; n < 8; n++)
#pragma unroll
            for (int i = 0; i < 4; i++) acc[t][n][i] = 0.f;

    const int steps = K >> 4;
    float4 a0g, a1g, b0g, b1g;

    // prologue: load tile 0
    a0g = *(const float4*)(aP);
    a1g = *(const float4*)(aP + (size_t)64 * lda);
    b0g = *(const float4*)(bP + (size_t)bRow * ldb);
    b1g = *(const float4*)(bP + (size_t)(bRow + 8) * ldb);
    {
        uint32_t* asr = &As[0][aRow][aCol];
        asr[0] = f2tf32(a0g.x); asr[1] = f2tf32(a0g.y); asr[2] = f2tf32(a0g.z); asr[3] = f2tf32(a0g.w);
        uint32_t* asr2 = &As[0][aRow + 64][aCol];
        asr2[0] = f2tf32(a1g.x); asr2[1] = f2tf32(a1g.y); asr2[2] = f2tf32(a1g.z); asr2[3] = f2tf32(a1g.w);
        uint32_t* bsr = &Bs[0][bRow][bCol];
        bsr[0] = f2tf32(b0g.x); bsr[1] = f2tf32(b0g.y); bsr[2] = f2tf32(b0g.z); bsr[3] = f2tf32(b0g.w);
        uint32_t* bsr2 = &Bs[0][bRow + 8][bCol];
        bsr2[0] = f2tf32(b1g.x); bsr2[1] = f2tf32(b1g.y); bsr2[2] = f2tf32(b1g.z); bsr2[3] = f2tf32(b1g.w);
    }
    __syncthreads();

    for (int s = 0; s < steps; s++) {
        const int buf = s & 1;
        const bool more = (s + 1) < steps;
        if (more) {
            const int k0 = (s + 1) << 4;
            a0g = *(const float4*)(aP + k0);
            a1g = *(const float4*)(aP + (size_t)64 * lda + k0);
            b0g = *(const float4*)(bP + (size_t)(k0 + bRow) * ldb);
            b1g = *(const float4*)(bP + (size_t)(k0 + bRow + 8) * ldb);
        }

        // compute on current buffer
#pragma unroll
        for (int ks = 0; ks < 2; ks++) {
            const int kk = ks << 3;
            uint32_t af[2][4];
            uint32_t bf[8][2];
            const int rA = wm * 32 + (lane >> 2);
            const int cA = kk + (lane & 3);
#pragma unroll
            for (int t = 0; t < 2; t++) {
                af[t][0] = As[buf][rA + t * 16][cA];
                af[t][1] = As[buf][rA + t * 16 + 8][cA];
                af[t][2] = As[buf][rA + t * 16][cA + 4];
                af[t][3] = As[buf][rA + t * 16 + 8][cA + 4];
            }
            const int cB = wn * 64 + (lane >> 2);
            const int rB = kk + (lane & 3);
#pragma unroll
            for (int n = 0; n < 8; n++) {
                bf[n][0] = Bs[buf][rB][cB + n * 8];
                bf[n][1] = Bs[buf][rB + 4][cB + n * 8];
            }
#pragma unroll
            for (int t = 0; t < 2; t++)
#pragma unroll
                for (int n = 0; n < 8; n++)
                    mma_tf32(acc[t][n], af[t], bf[n]);
        }

        if (more) {
            const int nb = buf ^ 1;
            uint32_t* asr = &As[nb][aRow][aCol];
            asr[0] = f2tf32(a0g.x); asr[1] = f2tf32(a0g.y); asr[2] = f2tf32(a0g.z); asr[3] = f2tf32(a0g.w);
            uint32_t* asr2 = &As[nb][aRow + 64][aCol];
            asr2[0] = f2tf32(a1g.x); asr2[1] = f2tf32(a1g.y); asr2[2] = f2tf32(a1g.z); asr2[3] = f2tf32(a1g.w);
            uint32_t* bsr = &Bs[nb][bRow][bCol];
            bsr[0] = f2tf32(b0g.x); bsr[1] = f2tf32(b0g.y); bsr[2] = f2tf32(b0g.z); bsr[3] = f2tf32(b0g.w);
            uint32_t* bsr2 = &Bs[nb][bRow + 8][bCol];
            bsr2[0] = f2tf32(b1g.x); bsr2[1] = f2tf32(b1g.y); bsr2[2] = f2tf32(b1g.z); bsr2[3] = f2tf32(b1g.w);
        }
        __syncthreads();
    }

    // epilogue
#pragma unroll
    for (int t = 0; t < 2; t++) {
        const int row = m0 + wm * 32 + t * 16 + (lane >> 2);
#pragma unroll
        for (int n = 0; n < 8; n++) {
            const int col = n0 + wn * 64 + n * 8 + (lane & 3) * 2;
            float2 bi = make_float2(0.f, 0.f);
            if (flags & 1) bi = *(const float2*)(bias + col);

            float2 v0 = make_float2(acc[t][n][0] + bi.x, acc[t][n][1] + bi.y);
            float2 v1 = make_float2(acc[t][n][2] + bi.x, acc[t][n][3] + bi.y);
            if (flags & 2) {
                v0.x = fmaxf(v0.x, 0.f); v0.y = fmaxf(v0.y, 0.f);
                v1.x = fmaxf(v1.x, 0.f); v1.y = fmaxf(v1.y, 0.f);
            }
            float* c0 = C + (size_t)row * ldc + col;
            float* c1 = C + (size_t)(row + 8) * ldc + col;
            if (flags & 4) {
                float2 o0 = *(float2*)c0, o1 = *(float2*)c1;
                v0.x += o0.x; v0.y += o0.y; v1.x += o1.x; v1.y += o1.y;
            }
            *(float2*)c0 = v0;
            *(float2*)c1 = v1;
        }
    }
}

// ---------------- attention scores + causal softmax ---------------------------
// one block per (t, h, b); writes prob row of length T (zeros beyond diagonal)
__global__ void attn_k(const float* __restrict__ q, const float* __restrict__ k,
                       float* __restrict__ p) {
    int t = blockIdx.x, h = blockIdx.y, b = blockIdx.z;
    int tid = threadIdx.x;  // 256
    __shared__ float qs[KH];
    __shared__ float red[256];
    const float* qr = q + (size_t)(b * TT + t) * DD + h * KH;
    if (tid < KH) qs[tid] = qr[tid];
    __syncthreads();

    float sc[4];
#pragma unroll
    for (int i = 0; i < 4; i++) {
        int s = tid + i * 256;
        if (s <= t) {
            const float* kr = k + (size_t)(b * TT + s) * DD + h * KH;
            float acc = 0.f;
#pragma unroll
            for (int kk = 0; kk < KH; kk++) acc += qs[kk] * kr[kk];
            sc[i] = acc * 0.125f;  // 1/sqrt(64)
        } else {
            sc[i] = -INFINITY;
        }
    }
    float m = fmaxf(fmaxf(sc[0], sc[1]), fmaxf(sc[2], sc[3]));
    red[tid] = m; __syncthreads();
    for (int s = 128; s > 0; s >>= 1) { if (tid < s) red[tid] = fmaxf(red[tid], red[tid + s]); __syncthreads(); }
    m = red[0]; __syncthreads();
    float lsum = 0.f;
#pragma unroll
    for (int i = 0; i < 4; i++) {
        sc[i] = (sc[i] == -INFINITY) ? 0.f : expf(sc[i] - m);
        lsum += sc[i];
    }
    red[tid] = lsum; __syncthreads();
    for (int s = 128; s > 0; s >>= 1) { if (tid < s) red[tid] += red[tid + s]; __syncthreads(); }
    float inv = 1.f / red[0];
    float* pr = p + ((size_t)(b * HH + h) * TT + t) * TT;
#pragma unroll
    for (int i = 0; i < 4; i++) pr[tid + i * 256] = sc[i] * inv;
}

// ---------------- loss --------------------------------------------------------
__global__ void loss_row_k(const float* __restrict__ logits, const int* __restrict__ tgt,
                           float* __restrict__ rl) {
    int row = blockIdx.x, tid = threadIdx.x;
    const float* lr = logits + (size_t)row * VV;
    __shared__ float red[256];
    float m = -INFINITY;
    for (int i = tid; i < VV; i += 256) m = fmaxf(m, lr[i]);
    red[tid] = m; __syncthreads();
    for (int s = 128; s > 0; s >>= 1) { if (tid < s) red[tid] = fmaxf(red[tid], red[tid + s]); __syncthreads(); }
    m = red[0]; __syncthreads();
    float sum = 0.f;
    for (int i = tid; i < VV; i += 256) sum += expf(lr[i] - m);
    red[tid] = sum; __syncthreads();
    for (int s = 128; s > 0; s >>= 1) { if (tid < s) red[tid] += red[tid + s]; __syncthreads(); }
    if (tid == 0) {
        float lse = m + logf(red[0]);
        rl[row] = lse - lr[tgt[row]];
    }
}

__global__ void loss_final_k(const float* __restrict__ rl, float* __restrict__ out) {
    __shared__ float red[256];
    int tid = threadIdx.x;
    float s = 0.f;
    for (int i = tid; i < ROWS; i += 256) s += rl[i];
    red[tid] = s; __syncthreads();
    for (int k = 128; k > 0; k >>= 1) { if (tid < k) red[tid] += red[tid + k]; __syncthreads(); }
    if (tid == 0) out[0] = red[0] * (1.0f / ROWS);
}

__global__ void fill0_k(float* p, size_t n) {
    size_t i = (size_t)blockIdx.x * blockDim.x + threadIdx.x;
    if (i < n) p[i] = 0.f;
}

// ---------------- host-side launcher helper -----------------------------------
static inline void gemm(const float* A, const float* B, float* C,
                        int M, int N, int K, int lda, int ldb, int ldc,
                        int Nh, size_t hs, const float* bias, int flags,
                        int batch = 1, int batchH = 1,
                        size_t aO = 0, size_t aI = 0,
                        size_t bO = 0, size_t bI = 0,
                        size_t cO = 0, size_t cI = 0) {
    dim3 grid(N / 128, M / 128, batch);
    gemm_tc<<<grid, 256>>>(A, B, C, K, lda, ldb, ldc, Nh, hs, bias, flags,
                           batchH, aO, aI, bO, bI, cO, cI);
}

extern "C" void kernel_launch(void* const* d_in, const int* in_sizes, int n_in,
                              void* d_out, int out_size) {
    const int*   ids   = (const int*)d_in[0];
    const int*   tgt   = (const int*)d_in[1];
    const float* tok   = (const float*)d_in[2];
    const float* pos   = (const float*)d_in[3];
    const float* Wq    = (const float*)d_in[4];
    const float* Wk    = (const float*)d_in[5];
    const float* Wv    = (const float*)d_in[6];
    const float* Wproj = (const float*)d_in[7];
    const float* bproj = (const float*)d_in[8];
    const float* ln1g  = (const float*)d_in[9];
    const float* ln1b  = (const float*)d_in[10];
    const float* ln2g  = (const float*)d_in[11];
    const float* ln2b  = (const float*)d_in[12];
    const float* W1    = (const float*)d_in[13];
    const float* b1    = (const float*)d_in[14];
    const float* W2    = (const float*)d_in[15];
    const float* b2    = (const float*)d_in[16];
    const float* lnfg  = (const float*)d_in[17];
    const float* lnfb  = (const float*)d_in[18];
    const float* Whead = (const float*)d_in[19];
    const float* bhead = (const float*)d_in[20];

    float *x, *h, *q, *k, *v, *o, *p, *f, *rl;
    cudaGetSymbolAddress((void**)&x, g_x);
    cudaGetSymbolAddress((void**)&h, g_h);
    cudaGetSymbolAddress((void**)&q, g_q);
    cudaGetSymbolAddress((void**)&k, g_k);
    cudaGetSymbolAddress((void**)&v, g_v);
    cudaGetSymbolAddress((void**)&o, g_o);
    cudaGetSymbolAddress((void**)&p, g_p);
    cudaGetSymbolAddress((void**)&f, g_f);
    cudaGetSymbolAddress((void**)&rl, g_rl);

    float* out = (float*)d_out;
    const size_t NL = (size_t)ROWS * VV;  // logits element count

    // x = tok_emb[ids] + pos_emb
    embed_k<<<ROWS, 256>>>(ids, tok, pos, x);

    for (int l = 0; l < LL; l++) {
        // h = ln1(x)
        ln_k<<<ROWS, 256>>>(x, h, ln1g + l * DD, ln1b + l * DD);
        // q,k: (ROWS,768) x per-head (768,64)  -> layout [row][h*64+k]
        gemm(h, Wq + (size_t)l * HH * DD * KH, q, ROWS, DD, DD, DD, KH, DD,
             KH, (size_t)DD * KH, nullptr, 0);
        gemm(h, Wk + (size_t)l * HH * DD * KH, k, ROWS, DD, DD, DD, KH, DD,
             KH, (size_t)DD * KH, nullptr, 0);
        // v: (ROWS,768) x per-head (768,768) -> layout [row][h*768+e]
        gemm(h, Wv + (size_t)l * HH * DD * DD, v, ROWS, HD, DD, DD, DD, HD,
             DD, (size_t)DD * DD, nullptr, 0);
        // scores + causal softmax -> probs
        {
            dim3 grid(TT, HH, BSZ);
            attn_k<<<grid, 256>>>(q, k, p);
        }
        // o[b,t,h*768+e] = probs[b,h] @ v[b,:,h]   (48 batched GEMMs)
        gemm(p, v, o, TT, DD, TT, TT, HD, HD, DD, 0, nullptr, 0,
             BSZ * HH, HH,
             (size_t)HH * TT * TT, (size_t)TT * TT,
             (size_t)TT * HD, (size_t)DD,
             (size_t)TT * HD, (size_t)DD);
        // x += o @ Wproj + bproj
        gemm(o, Wproj + (size_t)l * HD * DD, x, ROWS, DD, HD, HD, DD, DD,
             DD, 0, bproj + l * DD, 1 | 4);
        // h = ln2(x)
        ln_k<<<ROWS, 256>>>(x, h, ln2g + l * DD, ln2b + l * DD);
        // f = relu(h @ W1 + b1)
        gemm(h, W1 + (size_t)l * DD * FF, f, ROWS, FF, DD, DD, FF, FF,
             FF, 0, b1 + l * FF, 1 | 2);
        // x += f @ W2 + b2
        gemm(f, W2 + (size_t)l * FF * DD, x, ROWS, DD, FF, FF, DD, DD,
             DD, 0, b2 + l * DD, 1 | 4);
    }

    // final LN + head
    ln_k<<<ROWS, 256>>>(x, h, lnfg, lnfb);

    // logits -> d_out, then loss
    gemm(h, Whead, out, ROWS, VV, DD, DD, VV, VV, VV, 0, bhead, 1);
    loss_row_k<<<ROWS, 256>>>(out, tgt, rl);
    if ((size_t)out_size >= NL + 1) {
        loss_final_k<<<1, 256>>>(rl, out + NL);
        size_t tail = (size_t)out_size - (NL + 1);
        if (tail > 0)
            fill0_k<<<(int)((tail + 255) / 256), 256>>>(out + NL + 1, tail);
    }
}

// round 3
// speedup vs baseline: 1.7696x; 1.7335x over previous
#include <cuda_runtime.h>
#include <math.h>
#include <stdint.h>
#include <cuda_bf16.h>

// Problem constants
#define BSZ 4
#define TT 1024
#define DD 768
#define HH 12
#define KH 64          // head size
#define LL 6
#define VV 32000
#define FF 3072        // 4*D
#define HD 9216        // H*D (concat-head width)
#define ROWS (BSZ*TT)  // 4096

// ---------------- scratch (device globals; no allocation allowed) -------------
__device__ float g_x[(size_t)ROWS*DD];
__device__ float g_h[(size_t)ROWS*DD];
__device__ float g_q[(size_t)ROWS*DD];
__device__ float g_k[(size_t)ROWS*DD];
__device__ float g_v[(size_t)ROWS*HD];
__device__ float g_o[(size_t)ROWS*HD];
__device__ float g_p[(size_t)BSZ*HH*TT*TT];  // attention probs
__device__ float g_f[(size_t)ROWS*FF];       // MLP intermediate
__device__ float g_rl[ROWS];                 // per-row loss

// ---------------- embedding --------------------------------------------------
__global__ void embed_k(const int* __restrict__ ids, const float* __restrict__ tok,
                        const float* __restrict__ pos, float* __restrict__ x) {
    int row = blockIdx.x;
    int t = row % TT;
    int id = ids[row];
    const float* te = tok + (size_t)id * DD;
    const float* pe = pos + (size_t)t * DD;
    float* xr = x + (size_t)row * DD;
    for (int i = threadIdx.x; i < DD; i += blockDim.x)
        xr[i] = te[i] + pe[i];
}

// ---------------- layernorm --------------------------------------------------
__global__ void ln_k(const float* __restrict__ x, float* __restrict__ y,
                     const float* __restrict__ g, const float* __restrict__ b) {
    __shared__ float s1[256], s2[256];
    int row = blockIdx.x, tid = threadIdx.x;
    const float* xr = x + (size_t)row * DD;
    float sum = 0.f, sq = 0.f;
    for (int i = tid; i < DD; i += 256) { float v = xr[i]; sum += v; sq += v * v; }
    s1[tid] = sum; s2[tid] = sq; __syncthreads();
    for (int s = 128; s > 0; s >>= 1) {
        if (tid < s) { s1[tid] += s1[tid + s]; s2[tid] += s2[tid + s]; }
        __syncthreads();
    }
    float mu = s1[0] * (1.0f / DD);
    float var = s2[0] * (1.0f / DD) - mu * mu;
    float rstd = rsqrtf(var + 1e-5f);
    float* yr = y + (size_t)row * DD;
    for (int i = tid; i < DD; i += 256)
        yr[i] = (xr[i] - mu) * rstd * g[i] + b[i];
}

// ---------------- tf32 helpers -----------------------------------------------
__device__ __forceinline__ uint32_t f2tf32(float f) {
    uint32_t r;
    asm("cvt.rna.tf32.f32 %0, %1;" : "=r"(r) : "f"(f));
    return r;
}

__device__ __forceinline__ void mma_tf32(float c[4], const uint32_t a[4], const uint32_t b0, const uint32_t b1) {
    asm volatile(
        "mma.sync.aligned.m16n8k8.row.col.f32.tf32.tf32.f32 "
        "{%0,%1,%2,%3},{%4,%5,%6,%7},{%8,%9},{%0,%1,%2,%3};"
        : "+f"(c[0]), "+f"(c[1]), "+f"(c[2]), "+f"(c[3])
        : "r"(a[0]), "r"(a[1]), "r"(a[2]), "r"(a[3]), "r"(b0), "r"(b1));
}

__device__ __forceinline__ void ldsm4(uint32_t r[4], uint32_t addr) {
    asm volatile("ldmatrix.sync.aligned.m8n8.x4.shared.b16 {%0,%1,%2,%3}, [%4];"
        : "=r"(r[0]), "=r"(r[1]), "=r"(r[2]), "=r"(r[3]) : "r"(addr));
}

// ---------------- tensor-core tiled GEMM (tf32, ldmatrix) ----------------------
// C[M,N] (+)= A[M,K] * B[K,N]  (+ bias)(relu)
// B head-blocked addressing: element (d, j) at B + (j/Nh)*hstride + d*ldb + (j%Nh)
// flags: 1 = bias, 2 = relu, 4 = accumulate, 8 = causal-K (K_eff=(by+1)*128)
// CTA tile 128x128, 4 warps (warp tile 64x64), BK=16, double buffered.
// Requires: M%128==0, N%128==0, K%16==0.
#define APITCH 20   // floats per A smem row (odd multiple of 16B -> ldmatrix conflict-free)
#define BPITCH 136  // floats per B smem row (8k+n bank pattern -> conflict-free)
__global__ __launch_bounds__(128, 2)
void gemm_tc(const float* __restrict__ A, const float* __restrict__ Bm,
             float* __restrict__ C,
             int K, int lda, int ldb, int ldc,
             int Nh, size_t hstride,
             const float* __restrict__ bias, int flags,
             int batchH,
             size_t aOuter, size_t aInner,
             size_t bOuter, size_t bInner,
             size_t cOuter, size_t cInner) {
    int z = blockIdx.z;
    int zo = z / batchH, zi = z - zo * batchH;
    A  += zo * aOuter + zi * aInner;
    Bm += zo * bOuter + zi * bInner;
    C  += zo * cOuter + zi * cInner;

    __shared__ __align__(16) uint32_t As[2][128][APITCH];
    __shared__ __align__(16) uint32_t Bs[2][16][BPITCH];

    const int tid  = threadIdx.x;   // 128 threads
    const int lane = tid & 31;
    const int warp = tid >> 5;      // 4 warps: 2x2
    const int wm = warp >> 1;
    const int wn = warp & 1;
    const int m0 = blockIdx.y * 128;
    const int n0 = blockIdx.x * 128;

    int Kc = K;
    if (flags & 8) { int ke = (blockIdx.y + 1) * 128; if (ke < Kc) Kc = ke; }

    // global load mapping: A 128x16 (4 float4/thread), B 16x128 (4 float4/thread)
    const int ar = tid >> 2;            // 0..31 (+32j)
    const int ac = (tid & 3) << 2;      // 0,4,8,12
    const int br = tid >> 5;            // 0..3 (+4j)
    const int bc = (tid & 31) << 2;     // 0..124
    const float* aP = A + (size_t)(m0 + ar) * lda + ac;
    const int gcol = n0 + bc;
    const float* bP = Bm + (size_t)(gcol / Nh) * hstride + (size_t)(gcol % Nh);

    float acc[4][8][4];
#pragma unroll
    for (int mt = 0; mt < 4; mt++)
#pragma unroll
        for (int nt = 0; nt < 8; nt++)
#pragma unroll
            for (int i = 0; i < 4; i++) acc[mt][nt][i] = 0.f;

    // ldmatrix per-thread A address pieces
    const int aRowF = wm * 64 + (lane & 7) + ((lane >> 3) & 1) * 8;  // + mt*16
    const int aColF = ((lane >> 4) & 1) * 4;                          // + ks*8
    uint32_t asBase;
    {
        uint64_t p = __cvta_generic_to_shared(&As[0][0][0]);
        asBase = (uint32_t)p + (uint32_t)((aRowF * APITCH + aColF) * 4);
    }
    const int bRowF = lane & 3;            // + ks*8 (+4)
    const int bColF = wn * 64 + (lane >> 2);

    const int steps = Kc >> 4;
    float4 ag[4], bg[4];

    // prologue: load tile 0
#pragma unroll
    for (int j = 0; j < 4; j++) {
        ag[j] = *(const float4*)(aP + (size_t)(j * 32) * lda);
        bg[j] = *(const float4*)(bP + (size_t)(br + j * 4) * ldb);
    }
#pragma unroll
    for (int j = 0; j < 4; j++) {
        uint4 u;
        u.x = f2tf32(ag[j].x); u.y = f2tf32(ag[j].y); u.z = f2tf32(ag[j].z); u.w = f2tf32(ag[j].w);
        *(uint4*)&As[0][ar + j * 32][ac] = u;
        uint4 v;
        v.x = f2tf32(bg[j].x); v.y = f2tf32(bg[j].y); v.z = f2tf32(bg[j].z); v.w = f2tf32(bg[j].w);
        *(uint4*)&Bs[0][br + j * 4][bc] = v;
    }
    __syncthreads();

    for (int s = 0; s < steps; s++) {
        const int buf = s & 1;
        const bool more = (s + 1) < steps;
        if (more) {
            const int k0 = (s + 1) << 4;
#pragma unroll
            for (int j = 0; j < 4; j++) {
                ag[j] = *(const float4*)(aP + (size_t)(j * 32) * lda + k0);
                bg[j] = *(const float4*)(bP + (size_t)(k0 + br + j * 4) * ldb);
            }
        }

        const uint32_t aBufBase = asBase + (uint32_t)buf * (128 * APITCH * 4);
#pragma unroll
        for (int ks = 0; ks < 2; ks++) {
            uint32_t af[4][4];
#pragma unroll
            for (int mt = 0; mt < 4; mt++)
                ldsm4(af[mt], aBufBase + (uint32_t)(mt * 16 * APITCH + ks * 8) * 4);
            const uint32_t* b0p = &Bs[buf][ks * 8 + bRowF][bColF];
            const uint32_t* b1p = b0p + 4 * BPITCH;
#pragma unroll
            for (int nt = 0; nt < 8; nt++) {
                uint32_t b0 = b0p[nt * 8];
                uint32_t b1 = b1p[nt * 8];
#pragma unroll
                for (int mt = 0; mt < 4; mt++)
                    mma_tf32(acc[mt][nt], af[mt], b0, b1);
            }
        }

        if (more) {
            const int nb = buf ^ 1;
#pragma unroll
            for (int j = 0; j < 4; j++) {
                uint4 u;
                u.x = f2tf32(ag[j].x); u.y = f2tf32(ag[j].y); u.z = f2tf32(ag[j].z); u.w = f2tf32(ag[j].w);
                *(uint4*)&As[nb][ar + j * 32][ac] = u;
                uint4 v;
                v.x = f2tf32(bg[j].x); v.y = f2tf32(bg[j].y); v.z = f2tf32(bg[j].z); v.w = f2tf32(bg[j].w);
                *(uint4*)&Bs[nb][br + j * 4][bc] = v;
            }
        }
        __syncthreads();
    }

    // epilogue
#pragma unroll
    for (int mt = 0; mt < 4; mt++) {
        const int row = m0 + wm * 64 + mt * 16 + (lane >> 2);
#pragma unroll
        for (int nt = 0; nt < 8; nt++) {
            const int col = n0 + wn * 64 + nt * 8 + (lane & 3) * 2;
            float2 bi = make_float2(0.f, 0.f);
            if (flags & 1) bi = *(const float2*)(bias + col);
            float2 v0 = make_float2(acc[mt][nt][0] + bi.x, acc[mt][nt][1] + bi.y);
            float2 v1 = make_float2(acc[mt][nt][2] + bi.x, acc[mt][nt][3] + bi.y);
            if (flags & 2) {
                v0.x = fmaxf(v0.x, 0.f); v0.y = fmaxf(v0.y, 0.f);
                v1.x = fmaxf(v1.x, 0.f); v1.y = fmaxf(v1.y, 0.f);
            }
            float* c0 = C + (size_t)row * ldc + col;
            float* c1 = C + (size_t)(row + 8) * ldc + col;
            if (flags & 4) {
                float2 o0 = *(float2*)c0, o1 = *(float2*)c1;
                v0.x += o0.x; v0.y += o0.y; v1.x += o1.x; v1.y += o1.y;
            }
            *(float2*)c0 = v0;
            *(float2*)c1 = v1;
        }
    }
}

// ---------------- attention scores + causal softmax ---------------------------
__global__ void attn_k(const float* __restrict__ q, const float* __restrict__ k,
                       float* __restrict__ p) {
    int t = blockIdx.x, h = blockIdx.y, b = blockIdx.z;
    int tid = threadIdx.x;  // 256
    __shared__ float qs[KH];
    __shared__ float red[256];
    const float* qr = q + (size_t)(b * TT + t) * DD + h * KH;
    if (tid < KH) qs[tid] = qr[tid];
    __syncthreads();

    float sc[4];
#pragma unroll
    for (int i = 0; i < 4; i++) {
        int s = tid + i * 256;
        if (s <= t) {
            const float* kr = k + (size_t)(b * TT + s) * DD + h * KH;
            float acc = 0.f;
#pragma unroll
            for (int kk = 0; kk < KH; kk++) acc += qs[kk] * kr[kk];
            sc[i] = acc * 0.125f;
        } else {
            sc[i] = -INFINITY;
        }
    }
    float m = fmaxf(fmaxf(sc[0], sc[1]), fmaxf(sc[2], sc[3]));
    red[tid] = m; __syncthreads();
    for (int s = 128; s > 0; s >>= 1) { if (tid < s) red[tid] = fmaxf(red[tid], red[tid + s]); __syncthreads(); }
    m = red[0]; __syncthreads();
    float lsum = 0.f;
#pragma unroll
    for (int i = 0; i < 4; i++) {
        sc[i] = (sc[i] == -INFINITY) ? 0.f : expf(sc[i] - m);
        lsum += sc[i];
    }
    red[tid] = lsum; __syncthreads();
    for (int s = 128; s > 0; s >>= 1) { if (tid < s) red[tid] += red[tid + s]; __syncthreads(); }
    float inv = 1.f / red[0];
    float* pr = p + ((size_t)(b * HH + h) * TT + t) * TT;
#pragma unroll
    for (int i = 0; i < 4; i++) pr[tid + i * 256] = sc[i] * inv;
}

// ---------------- loss --------------------------------------------------------
__global__ void loss_row_k(const float* __restrict__ logits, const int* __restrict__ tgt,
                           float* __restrict__ rl) {
    int row = blockIdx.x, tid = threadIdx.x;
    const float* lr = logits + (size_t)row * VV;
    __shared__ float red[256];
    float m = -INFINITY;
    for (int i = tid; i < VV; i += 256) m = fmaxf(m, lr[i]);
    red[tid] = m; __syncthreads();
    for (int s = 128; s > 0; s >>= 1) { if (tid < s) red[tid] = fmaxf(red[tid], red[tid + s]); __syncthreads(); }
    m = red[0]; __syncthreads();
    float sum = 0.f;
    for (int i = tid; i < VV; i += 256) sum += expf(lr[i] - m);
    red[tid] = sum; __syncthreads();
    for (int s = 128; s > 0; s >>= 1) { if (tid < s) red[tid] += red[tid + s]; __syncthreads(); }
    if (tid == 0) {
        float lse = m + logf(red[0]);
        rl[row] = lse - lr[tgt[row]];
    }
}

__global__ void loss_final_k(const float* __restrict__ rl, float* __restrict__ out) {
    __shared__ float red[256];
    int tid = threadIdx.x;
    float s = 0.f;
    for (int i = tid; i < ROWS; i += 256) s += rl[i];
    red[tid] = s; __syncthreads();
    for (int k = 128; k > 0; k >>= 1) { if (tid < k) red[tid] += red[tid + k]; __syncthreads(); }
    if (tid == 0) out[0] = red[0] * (1.0f / ROWS);
}

__global__ void fill0_k(float* p, size_t n) {
    size_t i = (size_t)blockIdx.x * blockDim.x + threadIdx.x;
    if (i < n) p[i] = 0.f;
}

// ---------------- host-side launcher helper -----------------------------------
static inline void gemm(const float* A, const float* B, float* C,
                        int M, int N, int K, int lda, int ldb, int ldc,
                        int Nh, size_t hs, const float* bias, int flags,
                        int batch = 1, int batchH = 1,
                        size_t aO = 0, size_t aI = 0,
                        size_t bO = 0, size_t bI = 0,
                        size_t cO = 0, size_t cI = 0) {
    dim3 grid(N / 128, M / 128, batch);
    gemm_tc<<<grid, 128>>>(A, B, C, K, lda, ldb, ldc, Nh, hs, bias, flags,
                           batchH, aO, aI, bO, bI, cO, cI);
}

extern "C" void kernel_launch(void* const* d_in, const int* in_sizes, int n_in,
                              void* d_out, int out_size) {
    const int*   ids   = (const int*)d_in[0];
    const int*   tgt   = (const int*)d_in[1];
    const float* tok   = (const float*)d_in[2];
    const float* pos   = (const float*)d_in[3];
    const float* Wq    = (const float*)d_in[4];
    const float* Wk    = (const float*)d_in[5];
    const float* Wv    = (const float*)d_in[6];
    const float* Wproj = (const float*)d_in[7];
    const float* bproj = (const float*)d_in[8];
    const float* ln1g  = (const float*)d_in[9];
    const float* ln1b  = (const float*)d_in[10];
    const float* ln2g  = (const float*)d_in[11];
    const float* ln2b  = (const float*)d_in[12];
    const float* W1    = (const float*)d_in[13];
    const float* b1    = (const float*)d_in[14];
    const float* W2    = (const float*)d_in[15];
    const float* b2    = (const float*)d_in[16];
    const float* lnfg  = (const float*)d_in[17];
    const float* lnfb  = (const float*)d_in[18];
    const float* Whead = (const float*)d_in[19];
    const float* bhead = (const float*)d_in[20];

    float *x, *h, *q, *k, *v, *o, *p, *f, *rl;
    cudaGetSymbolAddress((void**)&x, g_x);
    cudaGetSymbolAddress((void**)&h, g_h);
    cudaGetSymbolAddress((void**)&q, g_q);
    cudaGetSymbolAddress((void**)&k, g_k);
    cudaGetSymbolAddress((void**)&v, g_v);
    cudaGetSymbolAddress((void**)&o, g_o);
    cudaGetSymbolAddress((void**)&p, g_p);
    cudaGetSymbolAddress((void**)&f, g_f);
    cudaGetSymbolAddress((void**)&rl, g_rl);

    float* out = (float*)d_out;
    const size_t NL = (size_t)ROWS * VV;

    embed_k<<<ROWS, 256>>>(ids, tok, pos, x);

    for (int l = 0; l < LL; l++) {
        ln_k<<<ROWS, 256>>>(x, h, ln1g + l * DD, ln1b + l * DD);
        gemm(h, Wq + (size_t)l * HH * DD * KH, q, ROWS, DD, DD, DD, KH, DD,
             KH, (size_t)DD * KH, nullptr, 0);
        gemm(h, Wk + (size_t)l * HH * DD * KH, k, ROWS, DD, DD, DD, KH, DD,
             KH, (size_t)DD * KH, nullptr, 0);
        gemm(h, Wv + (size_t)l * HH * DD * DD, v, ROWS, HD, DD, DD, DD, HD,
             DD, (size_t)DD * DD, nullptr, 0);
        {
            dim3 grid(TT, HH, BSZ);
            attn_k<<<grid, 256>>>(q, k, p);
        }
        // o = probs @ v, causal-K (flag 8): K_eff = (t_tile+1)*128
        gemm(p, v, o, TT, DD, TT, TT, HD, HD, DD, 0, nullptr, 8,
             BSZ * HH, HH,
             (size_t)HH * TT * TT, (size_t)TT * TT,
             (size_t)TT * HD, (size_t)DD,
             (size_t)TT * HD, (size_t)DD);
        gemm(o, Wproj + (size_t)l * HD * DD, x, ROWS, DD, HD, HD, DD, DD,
             DD, 0, bproj + l * DD, 1 | 4);
        ln_k<<<ROWS, 256>>>(x, h, ln2g + l * DD, ln2b + l * DD);
        gemm(h, W1 + (size_t)l * DD * FF, f, ROWS, FF, DD, DD, FF, FF,
             FF, 0, b1 + l * FF, 1 | 2);
        gemm(f, W2 + (size_t)l * FF * DD, x, ROWS, DD, FF, FF, DD, DD,
             DD, 0, b2 + l * DD, 1 | 4);
    }

    ln_k<<<ROWS, 256>>>(x, h, lnfg, lnfb);

    gemm(h, Whead, out, ROWS, VV, DD, DD, VV, VV, VV, 0, bhead, 1);
    loss_row_k<<<ROWS, 256>>>(out, tgt, rl);
    if ((size_t)out_size >= NL + 1) {
        loss_final_k<<<1, 256>>>(rl, out + NL);
        size_t tail = (size_t)out_size - (NL + 1);
        if (tail > 0)
            fill0_k<<<(int)((tail + 255) / 256), 256>>>(out + NL + 1, tail);
    }
}

// round 4
// speedup vs baseline: 1.7828x; 1.0074x over previous
#include <cuda_runtime.h>
#include <math.h>
#include <stdint.h>
#include <cuda_bf16.h>

// Problem constants
#define BSZ 4
#define TT 1024
#define DD 768
#define HH 12
#define KH 64
#define LL 6
#define VV 32000
#define FF 3072
#define HD 9216
#define ROWS (BSZ*TT)  // 4096

// ---------------- scratch ------------------------------------------------------
__device__ float g_x[(size_t)ROWS*DD];
__device__ float g_h[(size_t)ROWS*DD];
__device__ float g_q[(size_t)ROWS*DD];
__device__ float g_k[(size_t)ROWS*DD];
__device__ float g_v[(size_t)ROWS*HD];
__device__ float g_o[(size_t)ROWS*HD];
__device__ float g_p[(size_t)BSZ*HH*TT*TT];
__device__ float g_f[(size_t)ROWS*FF];
__device__ float g_rl[ROWS];

// tf32-rounded weights
#define WQ_SZ  3538944    // 6*12*768*64
#define WV_SZ  42467328   // 6*12*768*768
#define WP_SZ  42467328   // 6*9216*768
#define W1_SZ  14155776   // 6*768*3072
#define WH_SZ  24576000   // 768*32000
#define O_WQ   0
#define O_WK   (O_WQ + WQ_SZ)
#define O_WV   (O_WK + WQ_SZ)
#define O_WP   (O_WV + WV_SZ)
#define O_W1   (O_WP + WP_SZ)
#define O_W2   (O_W1 + W1_SZ)
#define O_WH   (O_W2 + W1_SZ)
#define WC_TOTAL (O_WH + WH_SZ)
__device__ float g_wc[(size_t)WC_TOTAL];

// ---------------- helpers ------------------------------------------------------
__device__ __forceinline__ uint32_t f2tf32(float f) {
    uint32_t r;
    asm("cvt.rna.tf32.f32 %0, %1;" : "=r"(r) : "f"(f));
    return r;
}
__device__ __forceinline__ float roundtf(float f) { return __uint_as_float(f2tf32(f)); }

__device__ __forceinline__ void mma_tf32(float c[4], const uint32_t a[4], uint32_t b0, uint32_t b1) {
    asm volatile(
        "mma.sync.aligned.m16n8k8.row.col.f32.tf32.tf32.f32 "
        "{%0,%1,%2,%3},{%4,%5,%6,%7},{%8,%9},{%0,%1,%2,%3};"
        : "+f"(c[0]), "+f"(c[1]), "+f"(c[2]), "+f"(c[3])
        : "r"(a[0]), "r"(a[1]), "r"(a[2]), "r"(a[3]), "r"(b0), "r"(b1));
}
__device__ __forceinline__ void ldsm4(uint32_t r[4], uint32_t addr) {
    asm volatile("ldmatrix.sync.aligned.m8n8.x4.shared.b16 {%0,%1,%2,%3}, [%4];"
        : "=r"(r[0]), "=r"(r[1]), "=r"(r[2]), "=r"(r[3]) : "r"(addr));
}
#define CP16(dst, src) asm volatile("cp.async.cg.shared.global [%0], [%1], 16;" :: "r"(dst), "l"(src))
#define CP_COMMIT() asm volatile("cp.async.commit_group;")
#define CP_WAIT1() asm volatile("cp.async.wait_group 1;")

// ---------------- small kernels ------------------------------------------------
__global__ void cvt_k(const float* __restrict__ s, float* __restrict__ d, size_t n) {
    size_t i = (size_t)blockIdx.x * blockDim.x + threadIdx.x;
    size_t stride = (size_t)gridDim.x * blockDim.x;
    for (; i < n; i += stride) d[i] = roundtf(s[i]);
}

__global__ void embed_k(const int* __restrict__ ids, const float* __restrict__ tok,
                        const float* __restrict__ pos, float* __restrict__ x) {
    int row = blockIdx.x;
    int t = row % TT;
    int id = ids[row];
    const float* te = tok + (size_t)id * DD;
    const float* pe = pos + (size_t)t * DD;
    float* xr = x + (size_t)row * DD;
    for (int i = threadIdx.x; i < DD; i += blockDim.x)
        xr[i] = te[i] + pe[i];
}

// layernorm; output rounded to tf32 (it always feeds an mma A operand)
__global__ void ln_k(const float* __restrict__ x, float* __restrict__ y,
                     const float* __restrict__ g, const float* __restrict__ b) {
    __shared__ float s1[256], s2[256];
    int row = blockIdx.x, tid = threadIdx.x;
    const float* xr = x + (size_t)row * DD;
    float sum = 0.f, sq = 0.f;
    for (int i = tid; i < DD; i += 256) { float v = xr[i]; sum += v; sq += v * v; }
    s1[tid] = sum; s2[tid] = sq; __syncthreads();
    for (int s = 128; s > 0; s >>= 1) {
        if (tid < s) { s1[tid] += s1[tid + s]; s2[tid] += s2[tid + s]; }
        __syncthreads();
    }
    float mu = s1[0] * (1.0f / DD);
    float var = s2[0] * (1.0f / DD) - mu * mu;
    float rstd = rsqrtf(var + 1e-5f);
    float* yr = y + (size_t)row * DD;
    for (int i = tid; i < DD; i += 256)
        yr[i] = roundtf((xr[i] - mu) * rstd * g[i] + b[i]);
}

// ---------------- tensor-core GEMM (tf32, cp.async 3-stage) --------------------
// C[M,N] (+)= A[M,K]*B[K,N]; B head-blocked: (d,j) at B + (j/Nh)*hstride + d*ldb + j%Nh
// flags: 1 bias, 2 relu, 4 accumulate, 8 causal-K, 16 round-store-tf32
// CTA 128x128, 256 thr (8 warps 2x4, warp tile 64x32), BK=16, 3-stage cp.async.
#define APITCH 20
#define BPITCH 136
#define AWORDS (128*APITCH)          // per stage
#define BWORDS (16*BPITCH)
#define STG_WORDS (AWORDS + BWORDS)  // 4736
#define SMEM_BYTES (3*STG_WORDS*4)   // 56832
__global__ __launch_bounds__(256, 2)
void gemm_tc(const float* __restrict__ A, const float* __restrict__ Bm,
             float* __restrict__ C,
             int K, int lda, int ldb, int ldc,
             int Nh, size_t hstride,
             const float* __restrict__ bias, int flags,
             int batchH,
             size_t aOuter, size_t aInner,
             size_t bOuter, size_t bInner,
             size_t cOuter, size_t cInner) {
    extern __shared__ __align__(16) uint32_t smem[];
    int z = blockIdx.z;
    int zo = z / batchH, zi = z - zo * batchH;
    A  += zo * aOuter + zi * aInner;
    Bm += zo * bOuter + zi * bInner;
    C  += zo * cOuter + zi * cInner;

    const int tid  = threadIdx.x;
    const int lane = tid & 31;
    const int warp = tid >> 5;
    const int wm = warp >> 2;       // 0..1
    const int wn = warp & 3;        // 0..3
    const int m0 = blockIdx.y * 128;
    const int n0 = blockIdx.x * 128;

    int Kc = K;
    if (flags & 8) { int ke = (blockIdx.y + 1) * 128; if (ke < Kc) Kc = ke; }
    const int steps = Kc >> 4;

    // cp.async source mapping
    const int ar = tid >> 2;           // 0..63 (+64)
    const int ac = (tid & 3) << 2;
    const int brr = tid >> 5;          // 0..7 (+8)
    const int bcc = (tid & 31) << 2;
    const float* aP = A + (size_t)(m0 + ar) * lda + ac;
    const int gcol = n0 + bcc;
    const float* bP = Bm + (size_t)(gcol / Nh) * hstride + (size_t)(gcol % Nh);

    const uint32_t smemBase = (uint32_t)__cvta_generic_to_shared(smem);
    // dest addresses (stage 0)
    const uint32_t aDst0 = smemBase + (uint32_t)((ar * APITCH + ac) * 4);
    const uint32_t aDst1 = smemBase + (uint32_t)(((ar + 64) * APITCH + ac) * 4);
    const uint32_t bDst0 = smemBase + (uint32_t)((AWORDS + brr * BPITCH + bcc) * 4);
    const uint32_t bDst1 = smemBase + (uint32_t)((AWORDS + (brr + 8) * BPITCH + bcc) * 4);

    float acc[4][4][4];
#pragma unroll
    for (int mt = 0; mt < 4; mt++)
#pragma unroll
        for (int nt = 0; nt < 4; nt++)
#pragma unroll
            for (int i = 0; i < 4; i++) acc[mt][nt][i] = 0.f;

    // ldmatrix A fragment address pieces
    const int aRowF = wm * 64 + (lane & 7) + ((lane >> 3) & 1) * 8;
    const int aColF = ((lane >> 4) & 1) * 4;
    const uint32_t aFragBase = smemBase + (uint32_t)((aRowF * APITCH + aColF) * 4);
    const int bRowF = lane & 3;
    const int bColF = wn * 32 + (lane >> 2);

    // prologue: issue loads for tiles 0,1
#pragma unroll
    for (int pt = 0; pt < 2; pt++) {
        if (pt < steps) {
            const uint32_t so = (uint32_t)(pt * STG_WORDS * 4);
            const int k0 = pt << 4;
            CP16(aDst0 + so, aP + k0);
            CP16(aDst1 + so, aP + (size_t)64 * lda + k0);
            CP16(bDst0 + so, bP + (size_t)(k0 + brr) * ldb);
            CP16(bDst1 + so, bP + (size_t)(k0 + brr + 8) * ldb);
        }
        CP_COMMIT();
    }

    int stg = 0;
    for (int s = 0; s < steps; s++) {
        CP_WAIT1();
        __syncthreads();

        // issue loads for tile s+2 into the stage just vacated
        {
            const int nt_ = s + 2;
            if (nt_ < steps) {
                int ns = stg + 2; if (ns >= 3) ns -= 3;
                const uint32_t so = (uint32_t)(ns * STG_WORDS * 4);
                const int k0 = nt_ << 4;
                CP16(aDst0 + so, aP + k0);
                CP16(aDst1 + so, aP + (size_t)64 * lda + k0);
                CP16(bDst0 + so, bP + (size_t)(k0 + brr) * ldb);
                CP16(bDst1 + so, bP + (size_t)(k0 + brr + 8) * ldb);
            }
            CP_COMMIT();
        }

        const uint32_t aSt = aFragBase + (uint32_t)(stg * STG_WORDS * 4);
        const uint32_t* bBase = smem + stg * STG_WORDS + AWORDS;
#pragma unroll
        for (int ks = 0; ks < 2; ks++) {
            uint32_t af[4][4];
#pragma unroll
            for (int mt = 0; mt < 4; mt++)
                ldsm4(af[mt], aSt + (uint32_t)((mt * 16 * APITCH + ks * 8) * 4));
            const uint32_t* b0p = bBase + (ks * 8 + bRowF) * BPITCH + bColF;
            const uint32_t* b1p = b0p + 4 * BPITCH;
#pragma unroll
            for (int nt = 0; nt < 4; nt++) {
                uint32_t b0 = b0p[nt * 8];
                uint32_t b1 = b1p[nt * 8];
#pragma unroll
                for (int mt = 0; mt < 4; mt++)
                    mma_tf32(acc[mt][nt], af[mt], b0, b1);
            }
        }
        __syncthreads();
        stg++; if (stg >= 3) stg = 0;
    }

    // epilogue
#pragma unroll
    for (int mt = 0; mt < 4; mt++) {
        const int row = m0 + wm * 64 + mt * 16 + (lane >> 2);
#pragma unroll
        for (int nt = 0; nt < 4; nt++) {
            const int col = n0 + wn * 32 + nt * 8 + (lane & 3) * 2;
            float2 bi = make_float2(0.f, 0.f);
            if (flags & 1) bi = *(const float2*)(bias + col);
            float2 v0 = make_float2(acc[mt][nt][0] + bi.x, acc[mt][nt][1] + bi.y);
            float2 v1 = make_float2(acc[mt][nt][2] + bi.x, acc[mt][nt][3] + bi.y);
            if (flags & 2) {
                v0.x = fmaxf(v0.x, 0.f); v0.y = fmaxf(v0.y, 0.f);
                v1.x = fmaxf(v1.x, 0.f); v1.y = fmaxf(v1.y, 0.f);
            }
            float* c0 = C + (size_t)row * ldc + col;
            float* c1 = C + (size_t)(row + 8) * ldc + col;
            if (flags & 4) {
                float2 o0 = *(float2*)c0, o1 = *(float2*)c1;
                v0.x += o0.x; v0.y += o0.y; v1.x += o1.x; v1.y += o1.y;
            }
            if (flags & 16) {
                v0.x = roundtf(v0.x); v0.y = roundtf(v0.y);
                v1.x = roundtf(v1.x); v1.y = roundtf(v1.y);
            }
            *(float2*)c0 = v0;
            *(float2*)c1 = v1;
        }
    }
}

// ---------------- attention scores + causal softmax ---------------------------
__global__ void attn_k(const float* __restrict__ q, const float* __restrict__ k,
                       float* __restrict__ p) {
    int t = blockIdx.x, h = blockIdx.y, b = blockIdx.z;
    int tid = threadIdx.x;  // 256
    __shared__ float qs[KH];
    __shared__ float red[256];
    const float* qr = q + (size_t)(b * TT + t) * DD + h * KH;
    if (tid < KH) qs[tid] = qr[tid];
    __syncthreads();

    float sc[4];
#pragma unroll
    for (int i = 0; i < 4; i++) {
        int s = tid + i * 256;
        if (s <= t) {
            const float* kr = k + (size_t)(b * TT + s) * DD + h * KH;
            float acc = 0.f;
#pragma unroll
            for (int kk = 0; kk < KH; kk++) acc += qs[kk] * kr[kk];
            sc[i] = acc * 0.125f;
        } else {
            sc[i] = -INFINITY;
        }
    }
    float m = fmaxf(fmaxf(sc[0], sc[1]), fmaxf(sc[2], sc[3]));
    red[tid] = m; __syncthreads();
    for (int s = 128; s > 0; s >>= 1) { if (tid < s) red[tid] = fmaxf(red[tid], red[tid + s]); __syncthreads(); }
    m = red[0]; __syncthreads();
    float lsum = 0.f;
#pragma unroll
    for (int i = 0; i < 4; i++) {
        sc[i] = (sc[i] == -INFINITY) ? 0.f : expf(sc[i] - m);
        lsum += sc[i];
    }
    red[tid] = lsum; __syncthreads();
    for (int s = 128; s > 0; s >>= 1) { if (tid < s) red[tid] += red[tid + s]; __syncthreads(); }
    float inv = 1.f / red[0];
    float* pr = p + ((size_t)(b * HH + h) * TT + t) * TT;
#pragma unroll
    for (int i = 0; i < 4; i++) pr[tid + i * 256] = roundtf(sc[i] * inv);
}

// ---------------- loss --------------------------------------------------------
__global__ void loss_row_k(const float* __restrict__ logits, const int* __restrict__ tgt,
                           float* __restrict__ rl) {
    int row = blockIdx.x, tid = threadIdx.x;
    const float* lr = logits + (size_t)row * VV;
    __shared__ float red[256];
    float m = -INFINITY;
    for (int i = tid; i < VV; i += 256) m = fmaxf(m, lr[i]);
    red[tid] = m; __syncthreads();
    for (int s = 128; s > 0; s >>= 1) { if (tid < s) red[tid] = fmaxf(red[tid], red[tid + s]); __syncthreads(); }
    m = red[0]; __syncthreads();
    float sum = 0.f;
    for (int i = tid; i < VV; i += 256) sum += expf(lr[i] - m);
    red[tid] = sum; __syncthreads();
    for (int s = 128; s > 0; s >>= 1) { if (tid < s) red[tid] += red[tid + s]; __syncthreads(); }
    if (tid == 0) {
        float lse = m + logf(red[0]);
        rl[row] = lse - lr[tgt[row]];
    }
}

__global__ void loss_final_k(const float* __restrict__ rl, float* __restrict__ out) {
    __shared__ float red[256];
    int tid = threadIdx.x;
    float s = 0.f;
    for (int i = tid; i < ROWS; i += 256) s += rl[i];
    red[tid] = s; __syncthreads();
    for (int k = 128; k > 0; k >>= 1) { if (tid < k) red[tid] += red[tid + k]; __syncthreads(); }
    if (tid == 0) out[0] = red[0] * (1.0f / ROWS);
}

__global__ void fill0_k(float* p, size_t n) {
    size_t i = (size_t)blockIdx.x * blockDim.x + threadIdx.x;
    if (i < n) p[i] = 0.f;
}

// ---------------- host-side launcher -------------------------------------------
static inline void gemm(const float* A, const float* B, float* C,
                        int M, int N, int K, int lda, int ldb, int ldc,
                        int Nh, size_t hs, const float* bias, int flags,
                        int batch = 1, int batchH = 1,
                        size_t aO = 0, size_t aI = 0,
                        size_t bO = 0, size_t bI = 0,
                        size_t cO = 0, size_t cI = 0) {
    dim3 grid(N / 128, M / 128, batch);
    gemm_tc<<<grid, 256, SMEM_BYTES>>>(A, B, C, K, lda, ldb, ldc, Nh, hs, bias, flags,
                                       batchH, aO, aI, bO, bI, cO, cI);
}

extern "C" void kernel_launch(void* const* d_in, const int* in_sizes, int n_in,
                              void* d_out, int out_size) {
    const int*   ids   = (const int*)d_in[0];
    const int*   tgt   = (const int*)d_in[1];
    const float* tok   = (const float*)d_in[2];
    const float* pos   = (const float*)d_in[3];
    const float* Wq_i  = (const float*)d_in[4];
    const float* Wk_i  = (const float*)d_in[5];
    const float* Wv_i  = (const float*)d_in[6];
    const float* Wp_i  = (const float*)d_in[7];
    const float* bproj = (const float*)d_in[8];
    const float* ln1g  = (const float*)d_in[9];
    const float* ln1b  = (const float*)d_in[10];
    const float* ln2g  = (const float*)d_in[11];
    const float* ln2b  = (const float*)d_in[12];
    const float* W1_i  = (const float*)d_in[13];
    const float* b1    = (const float*)d_in[14];
    const float* W2_i  = (const float*)d_in[15];
    const float* b2    = (const float*)d_in[16];
    const float* lnfg  = (const float*)d_in[17];
    const float* lnfb  = (const float*)d_in[18];
    const float* Wh_i  = (const float*)d_in[19];
    const float* bhead = (const float*)d_in[20];

    float *x, *h, *q, *k, *v, *o, *p, *f, *rl, *wc;
    cudaGetSymbolAddress((void**)&x, g_x);
    cudaGetSymbolAddress((void**)&h, g_h);
    cudaGetSymbolAddress((void**)&q, g_q);
    cudaGetSymbolAddress((void**)&k, g_k);
    cudaGetSymbolAddress((void**)&v, g_v);
    cudaGetSymbolAddress((void**)&o, g_o);
    cudaGetSymbolAddress((void**)&p, g_p);
    cudaGetSymbolAddress((void**)&f, g_f);
    cudaGetSymbolAddress((void**)&rl, g_rl);
    cudaGetSymbolAddress((void**)&wc, g_wc);

    static bool attrSet = false;
    if (!attrSet) {
        cudaFuncSetAttribute(gemm_tc, cudaFuncAttributeMaxDynamicSharedMemorySize, SMEM_BYTES);
        attrSet = true;
    }

    float* Wq = wc + O_WQ;  float* Wk = wc + O_WK;  float* Wv = wc + O_WV;
    float* Wp = wc + O_WP;  float* W1 = wc + O_W1;  float* W2 = wc + O_W2;
    float* Wh = wc + O_WH;

    // round weights to tf32 (idempotent, deterministic)
    cvt_k<<<2048, 256>>>(Wq_i, Wq, (size_t)WQ_SZ);
    cvt_k<<<2048, 256>>>(Wk_i, Wk, (size_t)WQ_SZ);
    cvt_k<<<4096, 256>>>(Wv_i, Wv, (size_t)WV_SZ);
    cvt_k<<<4096, 256>>>(Wp_i, Wp, (size_t)WP_SZ);
    cvt_k<<<2048, 256>>>(W1_i, W1, (size_t)W1_SZ);
    cvt_k<<<2048, 256>>>(W2_i, W2, (size_t)W1_SZ);
    cvt_k<<<4096, 256>>>(Wh_i, Wh, (size_t)WH_SZ);

    float* out = (float*)d_out;
    const size_t NL = (size_t)ROWS * VV;

    embed_k<<<ROWS, 256>>>(ids, tok, pos, x);

    for (int l = 0; l < LL; l++) {
        ln_k<<<ROWS, 256>>>(x, h, ln1g + l * DD, ln1b + l * DD);
        gemm(h, Wq + (size_t)l * HH * DD * KH, q, ROWS, DD, DD, DD, KH, DD,
             KH, (size_t)DD * KH, nullptr, 0);
        gemm(h, Wk + (size_t)l * HH * DD * KH, k, ROWS, DD, DD, DD, KH, DD,
             KH, (size_t)DD * KH, nullptr, 0);
        gemm(h, Wv + (size_t)l * HH * DD * DD, v, ROWS, HD, DD, DD, DD, HD,
             DD, (size_t)DD * DD, nullptr, 16);
        {
            dim3 grid(TT, HH, BSZ);
            attn_k<<<grid, 256>>>(q, k, p);
        }
        gemm(p, v, o, TT, DD, TT, TT, HD, HD, DD, 0, nullptr, 8 | 16,
             BSZ * HH, HH,
             (size_t)HH * TT * TT, (size_t)TT * TT,
             (size_t)TT * HD, (size_t)DD,
             (size_t)TT * HD, (size_t)DD);
        gemm(o, Wp + (size_t)l * HD * DD, x, ROWS, DD, HD, HD, DD, DD,
             DD, 0, bproj + l * DD, 1 | 4);
        ln_k<<<ROWS, 256>>>(x, h, ln2g + l * DD, ln2b + l * DD);
        gemm(h, W1 + (size_t)l * DD * FF, f, ROWS, FF, DD, DD, FF, FF,
             FF, 0, b1 + l * FF, 1 | 2 | 16);
        gemm(f, W2 + (size_t)l * FF * DD, x, ROWS, DD, FF, FF, DD, DD,
             DD, 0, b2 + l * DD, 1 | 4);
    }

    ln_k<<<ROWS, 256>>>(x, h, lnfg, lnfb);

    gemm(h, Wh, out, ROWS, VV, DD, DD, VV, VV, VV, 0, bhead, 1);
    loss_row_k<<<ROWS, 256>>>(out, tgt, rl);
    if ((size_t)out_size >= NL + 1) {
        loss_final_k<<<1, 256>>>(rl, out + NL);
        size_t tail = (size_t)out_size - (NL + 1);
        if (tail > 0)
            fill0_k<<<(int)((tail + 255) / 256), 256>>>(out + NL + 1, tail);
    }
}

// round 6
// speedup vs baseline: 6.3529x; 3.5634x over previous
#include <cuda_runtime.h>
#include <math.h>
#include <stdint.h>
#include <cuda_bf16.h>

// Problem constants
#define BSZ 4
#define TT 1024
#define DD 768
#define HH 12
#define KH 64
#define LL 6
#define VV 32000
#define FF 3072
#define HD 9216
#define ROWS (BSZ*TT)  // 4096

// ---------------- scratch ------------------------------------------------------
__device__ float g_x[(size_t)ROWS*DD];
__device__ float g_h[(size_t)ROWS*DD];
__device__ float g_q[(size_t)ROWS*DD];
__device__ float g_k[(size_t)ROWS*DD];
__device__ float g_v[(size_t)ROWS*HD];
__device__ float g_o[(size_t)ROWS*HD];
__device__ float g_p[(size_t)BSZ*HH*TT*TT];
__device__ float g_f[(size_t)ROWS*FF];
__device__ float g_rl[ROWS];

// tf32-rounded weights
#define WQ_SZ  3538944
#define WV_SZ  42467328
#define WP_SZ  42467328
#define W1_SZ  14155776
#define WH_SZ  24576000
#define O_WQ   0
#define O_WK   (O_WQ + WQ_SZ)
#define O_WV   (O_WK + WQ_SZ)
#define O_WP   (O_WV + WV_SZ)
#define O_W1   (O_WP + WP_SZ)
#define O_W2   (O_W1 + W1_SZ)
#define O_WH   (O_W2 + W1_SZ)
#define WC_TOTAL (O_WH + WH_SZ)
__device__ float g_wc[(size_t)WC_TOTAL];

// ---------------- helpers ------------------------------------------------------
__device__ __forceinline__ uint32_t f2tf32(float f) {
    uint32_t r;
    asm("cvt.rna.tf32.f32 %0, %1;" : "=r"(r) : "f"(f));
    return r;
}
__device__ __forceinline__ float roundtf(float f) { return __uint_as_float(f2tf32(f)); }

__device__ __forceinline__ void mma_tf32(float c[4], const uint32_t a[4], uint32_t b0, uint32_t b1) {
    asm volatile(
        "mma.sync.aligned.m16n8k8.row.col.f32.tf32.tf32.f32 "
        "{%0,%1,%2,%3},{%4,%5,%6,%7},{%8,%9},{%0,%1,%2,%3};"
        : "+f"(c[0]), "+f"(c[1]), "+f"(c[2]), "+f"(c[3])
        : "r"(a[0]), "r"(a[1]), "r"(a[2]), "r"(a[3]), "r"(b0), "r"(b1));
}
__device__ __forceinline__ void ldsm4(uint32_t r[4], uint32_t addr) {
    asm volatile("ldmatrix.sync.aligned.m8n8.x4.shared.b16 {%0,%1,%2,%3}, [%4];"
        : "=r"(r[0]), "=r"(r[1]), "=r"(r[2]), "=r"(r[3]) : "r"(addr));
}
#define CP16(dst, src) asm volatile("cp.async.cg.shared.global [%0], [%1], 16;" :: "r"(dst), "l"(src))
#define CP_COMMIT() asm volatile("cp.async.commit_group;")
#define CP_WAIT2() asm volatile("cp.async.wait_group 2;")
#define CP_WAIT0() asm volatile("cp.async.wait_group 0;")

// ---------------- small kernels ------------------------------------------------
__global__ void cvt_k(const float* __restrict__ s, float* __restrict__ d, size_t n) {
    size_t i = (size_t)blockIdx.x * blockDim.x + threadIdx.x;
    size_t stride = (size_t)gridDim.x * blockDim.x;
    for (; i < n; i += stride) d[i] = roundtf(s[i]);
}

__global__ void embed_k(const int* __restrict__ ids, const float* __restrict__ tok,
                        const float* __restrict__ pos, float* __restrict__ x) {
    int row = blockIdx.x;
    int t = row % TT;
    int id = ids[row];
    const float* te = tok + (size_t)id * DD;
    const float* pe = pos + (size_t)t * DD;
    float* xr = x + (size_t)row * DD;
    for (int i = threadIdx.x; i < DD; i += blockDim.x)
        xr[i] = te[i] + pe[i];
}

__global__ void ln_k(const float* __restrict__ x, float* __restrict__ y,
                     const float* __restrict__ g, const float* __restrict__ b) {
    __shared__ float s1[256], s2[256];
    int row = blockIdx.x, tid = threadIdx.x;
    const float* xr = x + (size_t)row * DD;
    float sum = 0.f, sq = 0.f;
    for (int i = tid; i < DD; i += 256) { float v = xr[i]; sum += v; sq += v * v; }
    s1[tid] = sum; s2[tid] = sq; __syncthreads();
    for (int s = 128; s > 0; s >>= 1) {
        if (tid < s) { s1[tid] += s1[tid + s]; s2[tid] += s2[tid + s]; }
        __syncthreads();
    }
    float mu = s1[0] * (1.0f / DD);
    float var = s2[0] * (1.0f / DD) - mu * mu;
    float rstd = rsqrtf(var + 1e-5f);
    float* yr = y + (size_t)row * DD;
    for (int i = tid; i < DD; i += 256)
        yr[i] = roundtf((xr[i] - mu) * rstd * g[i] + b[i]);
}

// ---------------- tensor-core GEMM (tf32, cp.async 4-stage) --------------------
// flags: 1 bias, 2 relu, 4 accumulate, 8 causal-K, 16 round-store-tf32
#define APITCH 20
#define BPITCH 136
#define AWORDS (128*APITCH)
#define BWORDS (16*BPITCH)
#define STG_WORDS (AWORDS + BWORDS)   // 4736
#define NSTG 4
#define SMEM_BYTES (NSTG*STG_WORDS*4) // 75776
__global__ __launch_bounds__(256, 2)
void gemm_tc(const float* __restrict__ A, const float* __restrict__ Bm,
             float* __restrict__ C,
             int K, int lda, int ldb, int ldc,
             int Nh, size_t hstride,
             const float* __restrict__ bias, int flags,
             int batchH,
             size_t aOuter, size_t aInner,
             size_t bOuter, size_t bInner,
             size_t cOuter, size_t cInner) {
    extern __shared__ __align__(16) uint32_t smem[];
    int z = blockIdx.z;
    int zo = z / batchH, zi = z - zo * batchH;
    A  += zo * aOuter + zi * aInner;
    Bm += zo * bOuter + zi * bInner;
    C  += zo * cOuter + zi * cInner;

    const int tid  = threadIdx.x;
    const int lane = tid & 31;
    const int warp = tid >> 5;
    const int wm = warp >> 2;
    const int wn = warp & 3;
    const int m0 = blockIdx.y * 128;
    const int n0 = blockIdx.x * 128;

    int Kc = K;
    if (flags & 8) { int ke = (blockIdx.y + 1) * 128; if (ke < Kc) Kc = ke; }
    const int steps = Kc >> 4;

    const int ar = tid >> 2;
    const int ac = (tid & 3) << 2;
    const int brr = tid >> 5;
    const int bcc = (tid & 31) << 2;
    const float* aP = A + (size_t)(m0 + ar) * lda + ac;
    const int gcol = n0 + bcc;
    const float* bP = Bm + (size_t)(gcol / Nh) * hstride + (size_t)(gcol % Nh);

    const uint32_t smemBase = (uint32_t)__cvta_generic_to_shared(smem);
    const uint32_t aDst0 = smemBase + (uint32_t)((ar * APITCH + ac) * 4);
    const uint32_t aDst1 = smemBase + (uint32_t)(((ar + 64) * APITCH + ac) * 4);
    const uint32_t bDst0 = smemBase + (uint32_t)((AWORDS + brr * BPITCH + bcc) * 4);
    const uint32_t bDst1 = smemBase + (uint32_t)((AWORDS + (brr + 8) * BPITCH + bcc) * 4);

    float acc[4][4][4];
#pragma unroll
    for (int mt = 0; mt < 4; mt++)
#pragma unroll
        for (int nt = 0; nt < 4; nt++)
#pragma unroll
            for (int i = 0; i < 4; i++) acc[mt][nt][i] = 0.f;

    const int aRowF = wm * 64 + (lane & 7) + ((lane >> 3) & 1) * 8;
    const int aColF = ((lane >> 4) & 1) * 4;
    const uint32_t aFragBase = smemBase + (uint32_t)((aRowF * APITCH + aColF) * 4);
    const int bRowF = lane & 3;
    const int bColF = wn * 32 + (lane >> 2);

    // prologue: issue loads for tiles 0..2
#pragma unroll
    for (int pt = 0; pt < NSTG - 1; pt++) {
        if (pt < steps) {
            const uint32_t so = (uint32_t)(pt * STG_WORDS * 4);
            const int k0 = pt << 4;
            CP16(aDst0 + so, aP + k0);
            CP16(aDst1 + so, aP + (size_t)64 * lda + k0);
            CP16(bDst0 + so, bP + (size_t)(k0 + brr) * ldb);
            CP16(bDst1 + so, bP + (size_t)(k0 + brr + 8) * ldb);
        }
        CP_COMMIT();
    }

    int stg = 0;
    for (int s = 0; s < steps; s++) {
        CP_WAIT2();
        __syncthreads();

        {
            const int nt_ = s + NSTG - 1;
            if (nt_ < steps) {
                int ns = stg + NSTG - 1; if (ns >= NSTG) ns -= NSTG;
                const uint32_t so = (uint32_t)(ns * STG_WORDS * 4);
                const int k0 = nt_ << 4;
                CP16(aDst0 + so, aP + k0);
                CP16(aDst1 + so, aP + (size_t)64 * lda + k0);
                CP16(bDst0 + so, bP + (size_t)(k0 + brr) * ldb);
                CP16(bDst1 + so, bP + (size_t)(k0 + brr + 8) * ldb);
            }
            CP_COMMIT();
        }

        const uint32_t aSt = aFragBase + (uint32_t)(stg * STG_WORDS * 4);
        const uint32_t* bBase = smem + stg * STG_WORDS + AWORDS;
#pragma unroll
        for (int ks = 0; ks < 2; ks++) {
            uint32_t af[4][4];
#pragma unroll
            for (int mt = 0; mt < 4; mt++)
                ldsm4(af[mt], aSt + (uint32_t)((mt * 16 * APITCH + ks * 8) * 4));
            const uint32_t* b0p = bBase + (ks * 8 + bRowF) * BPITCH + bColF;
            const uint32_t* b1p = b0p + 4 * BPITCH;
#pragma unroll
            for (int nt = 0; nt < 4; nt++) {
                uint32_t b0 = b0p[nt * 8];
                uint32_t b1 = b1p[nt * 8];
#pragma unroll
                for (int mt = 0; mt < 4; mt++)
                    mma_tf32(acc[mt][nt], af[mt], b0, b1);
            }
        }
        __syncthreads();
        stg++; if (stg >= NSTG) stg = 0;
    }

    // epilogue
#pragma unroll
    for (int mt = 0; mt < 4; mt++) {
        const int row = m0 + wm * 64 + mt * 16 + (lane >> 2);
#pragma unroll
        for (int nt = 0; nt < 4; nt++) {
            const int col = n0 + wn * 32 + nt * 8 + (lane & 3) * 2;
            float2 bi = make_float2(0.f, 0.f);
            if (flags & 1) bi = *(const float2*)(bias + col);
            float2 v0 = make_float2(acc[mt][nt][0] + bi.x, acc[mt][nt][1] + bi.y);
            float2 v1 = make_float2(acc[mt][nt][2] + bi.x, acc[mt][nt][3] + bi.y);
            if (flags & 2) {
                v0.x = fmaxf(v0.x, 0.f); v0.y = fmaxf(v0.y, 0.f);
                v1.x = fmaxf(v1.x, 0.f); v1.y = fmaxf(v1.y, 0.f);
            }
            float* c0 = C + (size_t)row * ldc + col;
            float* c1 = C + (size_t)(row + 8) * ldc + col;
            if (flags & 4) {
                float2 o0 = *(float2*)c0, o1 = *(float2*)c1;
                v0.x += o0.x; v0.y += o0.y; v1.x += o1.x; v1.y += o1.y;
            }
            if (flags & 16) {
                v0.x = roundtf(v0.x); v0.y = roundtf(v0.y);
                v1.x = roundtf(v1.x); v1.y = roundtf(v1.y);
            }
            *(float2*)c0 = v0;
            *(float2*)c1 = v1;
        }
    }
}

// ---------------- attention scores on tensor cores ------------------------------
// S[128x128] = Q_tile @ K_tile^T per (b,h). K=64, single shot.
// q/k layout: row-major (b*1024+t, h*64+d), width 768.
// Writes scaled scores into p[z*T*T + ...]. Skips tiles fully above diagonal.
#define SPITCH 68
#define S_AWORDS (128*SPITCH)
#define SCORE_SMEM (2*S_AWORDS*4)   // 69632 bytes
__global__ __launch_bounds__(256, 2)
void score_tc(const float* __restrict__ q, const float* __restrict__ k,
              float* __restrict__ p) {
    extern __shared__ __align__(16) uint32_t ss[];
    const int z = blockIdx.z;           // b*HH + h
    const int b = z / HH, h = z - b * HH;
    const int m0 = blockIdx.y * 128;
    const int n0 = blockIdx.x * 128;
    if (n0 > m0 + 127) return;          // fully masked tile

    const int tid  = threadIdx.x;
    const int lane = tid & 31;
    const int warp = tid >> 5;
    const int wm = warp >> 2;           // 0..1
    const int wn = warp & 3;            // 0..3

    const float* qb = q + ((size_t)(b * TT + m0)) * DD + h * KH;
    const float* kb = k + ((size_t)(b * TT + n0)) * DD + h * KH;

    const uint32_t base = (uint32_t)__cvta_generic_to_shared(ss);
    // load both 128x64 tiles (pitch 68)
#pragma unroll
    for (int i = 0; i < 8; i++) {
        int lin = tid + i * 256;          // 0..2047
        int row = lin >> 4;
        int col = (lin & 15) << 2;
        CP16(base + (uint32_t)((row * SPITCH + col) * 4), qb + (size_t)row * DD + col);
        CP16(base + (uint32_t)((S_AWORDS + row * SPITCH + col) * 4), kb + (size_t)row * DD + col);
    }
    CP_COMMIT();
    CP_WAIT0();
    __syncthreads();

    float acc[4][4][4];
#pragma unroll
    for (int mt = 0; mt < 4; mt++)
#pragma unroll
        for (int nt = 0; nt < 4; nt++)
#pragma unroll
            for (int i = 0; i < 4; i++) acc[mt][nt][i] = 0.f;

    const uint32_t aFragBase = base +
        (uint32_t)(((wm * 64 + (lane & 7) + ((lane >> 3) & 1) * 8) * SPITCH +
                    ((lane >> 4) & 1) * 4) * 4);
    const uint32_t* Ks = ss + S_AWORDS;
    const int bN = wn * 32 + (lane >> 2);
    const int bK = lane & 3;

#pragma unroll
    for (int ks = 0; ks < 8; ks++) {
        uint32_t af[4][4];
#pragma unroll
        for (int mt = 0; mt < 4; mt++)
            ldsm4(af[mt], aFragBase + (uint32_t)((mt * 16 * SPITCH + ks * 8) * 4));
#pragma unroll
        for (int nt = 0; nt < 4; nt++) {
            uint32_t b0 = Ks[(bN + nt * 8) * SPITCH + ks * 8 + bK];
            uint32_t b1 = Ks[(bN + nt * 8) * SPITCH + ks * 8 + 4 + bK];
#pragma unroll
            for (int mt = 0; mt < 4; mt++)
                mma_tf32(acc[mt][nt], af[mt], b0, b1);
        }
    }

    float* pz = p + (size_t)z * TT * TT;
#pragma unroll
    for (int mt = 0; mt < 4; mt++) {
        const int row = m0 + wm * 64 + mt * 16 + (lane >> 2);
#pragma unroll
        for (int nt = 0; nt < 4; nt++) {
            const int col = n0 + wn * 32 + nt * 8 + (lane & 3) * 2;
            float2 v0 = make_float2(acc[mt][nt][0] * 0.125f, acc[mt][nt][1] * 0.125f);
            float2 v1 = make_float2(acc[mt][nt][2] * 0.125f, acc[mt][nt][3] * 0.125f);
            *(float2*)(pz + (size_t)row * TT + col) = v0;
            *(float2*)(pz + (size_t)(row + 8) * TT + col) = v1;
        }
    }
}

// ---------------- causal softmax over score rows (in place) --------------------
__global__ void attn_sm(float* __restrict__ p) {
    int t = blockIdx.x, h = blockIdx.y, b = blockIdx.z;
    int tid = threadIdx.x;  // 256
    __shared__ float red[256];
    float* row = p + ((size_t)((b * HH + h) * TT + t)) * TT;

    float sc[4];
#pragma unroll
    for (int i = 0; i < 4; i++) {
        int s = tid + i * 256;
        sc[i] = (s <= t) ? row[s] : -INFINITY;
    }
    float m = fmaxf(fmaxf(sc[0], sc[1]), fmaxf(sc[2], sc[3]));
    red[tid] = m; __syncthreads();
    for (int s = 128; s > 0; s >>= 1) { if (tid < s) red[tid] = fmaxf(red[tid], red[tid + s]); __syncthreads(); }
    m = red[0]; __syncthreads();
    float lsum = 0.f;
#pragma unroll
    for (int i = 0; i < 4; i++) {
        sc[i] = (sc[i] == -INFINITY) ? 0.f : expf(sc[i] - m);
        lsum += sc[i];
    }
    red[tid] = lsum; __syncthreads();
    for (int s = 128; s > 0; s >>= 1) { if (tid < s) red[tid] += red[tid + s]; __syncthreads(); }
    float inv = 1.f / red[0];
#pragma unroll
    for (int i = 0; i < 4; i++) row[tid + i * 256] = roundtf(sc[i] * inv);
}

// ---------------- loss ----------------------------------------------------------
__global__ void loss_row_k(const float* __restrict__ logits, const int* __restrict__ tgt,
                           float* __restrict__ rl) {
    int row = blockIdx.x, tid = threadIdx.x;
    const float* lr = logits + (size_t)row * VV;
    __shared__ float red[256];
    float m = -INFINITY;
    for (int i = tid; i < VV; i += 256) m = fmaxf(m, lr[i]);
    red[tid] = m; __syncthreads();
    for (int s = 128; s > 0; s >>= 1) { if (tid < s) red[tid] = fmaxf(red[tid], red[tid + s]); __syncthreads(); }
    m = red[0]; __syncthreads();
    float sum = 0.f;
    for (int i = tid; i < VV; i += 256) sum += expf(lr[i] - m);
    red[tid] = sum; __syncthreads();
    for (int s = 128; s > 0; s >>= 1) { if (tid < s) red[tid] += red[tid + s]; __syncthreads(); }
    if (tid == 0) {
        float lse = m + logf(red[0]);
        rl[row] = lse - lr[tgt[row]];
    }
}

__global__ void loss_final_k(const float* __restrict__ rl, float* __restrict__ out) {
    __shared__ float red[256];
    int tid = threadIdx.x;
    float s = 0.f;
    for (int i = tid; i < ROWS; i += 256) s += rl[i];
    red[tid] = s; __syncthreads();
    for (int k = 128; k > 0; k >>= 1) { if (tid < k) red[tid] += red[tid + k]; __syncthreads(); }
    if (tid == 0) out[0] = red[0] * (1.0f / ROWS);
}

__global__ void fill0_k(float* p, size_t n) {
    size_t i = (size_t)blockIdx.x * blockDim.x + threadIdx.x;
    if (i < n) p[i] = 0.f;
}

// ---------------- host-side launcher -------------------------------------------
static inline void gemm(const float* A, const float* B, float* C,
                        int M, int N, int K, int lda, int ldb, int ldc,
                        int Nh, size_t hs, const float* bias, int flags,
                        int batch = 1, int batchH = 1,
                        size_t aO = 0, size_t aI = 0,
                        size_t bO = 0, size_t bI = 0,
                        size_t cO = 0, size_t cI = 0) {
    dim3 grid(N / 128, M / 128, batch);
    gemm_tc<<<grid, 256, SMEM_BYTES>>>(A, B, C, K, lda, ldb, ldc, Nh, hs, bias, flags,
                                       batchH, aO, aI, bO, bI, cO, cI);
}

extern "C" void kernel_launch(void* const* d_in, const int* in_sizes, int n_in,
                              void* d_out, int out_size) {
    const int*   ids   = (const int*)d_in[0];
    const int*   tgt   = (const int*)d_in[1];
    const float* tok   = (const float*)d_in[2];
    const float* pos   = (const float*)d_in[3];
    const float* Wq_i  = (const float*)d_in[4];
    const float* Wk_i  = (const float*)d_in[5];
    const float* Wv_i  = (const float*)d_in[6];
    const float* Wp_i  = (const float*)d_in[7];
    const float* bproj = (const float*)d_in[8];
    const float* ln1g  = (const float*)d_in[9];
    const float* ln1b  = (const float*)d_in[10];
    const float* ln2g  = (const float*)d_in[11];
    const float* ln2b  = (const float*)d_in[12];
    const float* W1_i  = (const float*)d_in[13];
    const float* b1    = (const float*)d_in[14];
    const float* W2_i  = (const float*)d_in[15];
    const float* b2    = (const float*)d_in[16];
    const float* lnfg  = (const float*)d_in[17];
    const float* lnfb  = (const float*)d_in[18];
    const float* Wh_i  = (const float*)d_in[19];
    const float* bhead = (const float*)d_in[20];

    float *x, *h, *q, *k, *v, *o, *p, *f, *rl, *wc;
    cudaGetSymbolAddress((void**)&x, g_x);
    cudaGetSymbolAddress((void**)&h, g_h);
    cudaGetSymbolAddress((void**)&q, g_q);
    cudaGetSymbolAddress((void**)&k, g_k);
    cudaGetSymbolAddress((void**)&v, g_v);
    cudaGetSymbolAddress((void**)&o, g_o);
    cudaGetSymbolAddress((void**)&p, g_p);
    cudaGetSymbolAddress((void**)&f, g_f);
    cudaGetSymbolAddress((void**)&rl, g_rl);
    cudaGetSymbolAddress((void**)&wc, g_wc);

    static bool attrSet = false;
    if (!attrSet) {
        cudaFuncSetAttribute(gemm_tc, cudaFuncAttributeMaxDynamicSharedMemorySize, SMEM_BYTES);
        cudaFuncSetAttribute(score_tc, cudaFuncAttributeMaxDynamicSharedMemorySize, SCORE_SMEM);
        attrSet = true;
    }

    float* Wq = wc + O_WQ;  float* Wk = wc + O_WK;  float* Wv = wc + O_WV;
    float* Wp = wc + O_WP;  float* W1 = wc + O_W1;  float* W2 = wc + O_W2;
    float* Wh = wc + O_WH;

    cvt_k<<<2048, 256>>>(Wq_i, Wq, (size_t)WQ_SZ);
    cvt_k<<<2048, 256>>>(Wk_i, Wk, (size_t)WQ_SZ);
    cvt_k<<<4096, 256>>>(Wv_i, Wv, (size_t)WV_SZ);
    cvt_k<<<4096, 256>>>(Wp_i, Wp, (size_t)WP_SZ);
    cvt_k<<<2048, 256>>>(W1_i, W1, (size_t)W1_SZ);
    cvt_k<<<2048, 256>>>(W2_i, W2, (size_t)W1_SZ);
    cvt_k<<<4096, 256>>>(Wh_i, Wh, (size_t)WH_SZ);

    float* out = (float*)d_out;
    const size_t NL = (size_t)ROWS * VV;

    embed_k<<<ROWS, 256>>>(ids, tok, pos, x);

    for (int l = 0; l < LL; l++) {
        ln_k<<<ROWS, 256>>>(x, h, ln1g + l * DD, ln1b + l * DD);
        gemm(h, Wq + (size_t)l * HH * DD * KH, q, ROWS, DD, DD, DD, KH, DD,
             KH, (size_t)DD * KH, nullptr, 0);
        gemm(h, Wk + (size_t)l * HH * DD * KH, k, ROWS, DD, DD, DD, KH, DD,
             KH, (size_t)DD * KH, nullptr, 0);
        gemm(h, Wv + (size_t)l * HH * DD * DD, v, ROWS, HD, DD, DD, DD, HD,
             DD, (size_t)DD * DD, nullptr, 16);
        // scores: S = Q K^T (tensor cores, causal tile skip), then softmax
        {
            dim3 grid(TT / 128, TT / 128, BSZ * HH);
            score_tc<<<grid, 256, SCORE_SMEM>>>(q, k, p);
            dim3 grid2(TT, HH, BSZ);
            attn_sm<<<grid2, 256>>>(p);
        }
        gemm(p, v, o, TT, DD, TT, TT, HD, HD, DD, 0, nullptr, 8 | 16,
             BSZ * HH, HH,
             (size_t)HH * TT * TT, (size_t)TT * TT,
             (size_t)TT * HD, (size_t)DD,
             (size_t)TT * HD, (size_t)DD);
        gemm(o, Wp + (size_t)l * HD * DD, x, ROWS, DD, HD, HD, DD, DD,
             DD, 0, bproj + l * DD, 1 | 4);
        ln_k<<<ROWS, 256>>>(x, h, ln2g + l * DD, ln2b + l * DD);
        gemm(h, W1 + (size_t)l * DD * FF, f, ROWS, FF, DD, DD, FF, FF,
             FF, 0, b1 + l * FF, 1 | 2 | 16);
        gemm(f, W2 + (size_t)l * FF * DD, x, ROWS, DD, FF, FF, DD, DD,
             DD, 0, b2 + l * DD, 1 | 4);
    }

    ln_k<<<ROWS, 256>>>(x, h, lnfg, lnfb);

    gemm(h, Wh, out, ROWS, VV, DD, DD, VV, VV, VV, 0, bhead, 1);
    loss_row_k<<<ROWS, 256>>>(out, tgt, rl);
    if ((size_t)out_size >= NL + 1) {
        loss_final_k<<<1, 256>>>(rl, out + NL);
        size_t tail = (size_t)out_size - (NL + 1);
        if (tail > 0)
            fill0_k<<<(int)((tail + 255) / 256), 256>>>(out + NL + 1, tail);
    }
}

// round 7
// speedup vs baseline: 6.5481x; 1.0307x over previous
#include <cuda_runtime.h>
#include <math.h>
#include <stdint.h>
#include <cuda_bf16.h>

// Problem constants
#define BSZ 4
#define TT 1024
#define DD 768
#define HH 12
#define KH 64
#define LL 6
#define VV 32000
#define FF 3072
#define HD 9216
#define ROWS (BSZ*TT)  // 4096

// ---------------- scratch ------------------------------------------------------
__device__ float g_x[(size_t)ROWS*DD];
__device__ float g_h[(size_t)ROWS*DD];
__device__ float g_q[(size_t)ROWS*DD];
__device__ float g_k[(size_t)ROWS*DD];
__device__ float g_v[(size_t)ROWS*HD];
__device__ float g_o[(size_t)ROWS*HD];
__device__ float g_p[(size_t)BSZ*HH*TT*TT];
__device__ float g_f[(size_t)ROWS*FF];
__device__ float g_rl[ROWS];

// tf32-rounded weights
#define WQ_SZ  3538944
#define WV_SZ  42467328
#define WP_SZ  42467328
#define W1_SZ  14155776
#define WH_SZ  24576000
#define O_WQ   0
#define O_WK   (O_WQ + WQ_SZ)
#define O_WV   (O_WK + WQ_SZ)
#define O_WP   (O_WV + WV_SZ)
#define O_W1   (O_WP + WP_SZ)
#define O_W2   (O_W1 + W1_SZ)
#define O_WH   (O_W2 + W1_SZ)
#define WC_TOTAL (O_WH + WH_SZ)
__device__ float g_wc[(size_t)WC_TOTAL];

// ---------------- helpers ------------------------------------------------------
__device__ __forceinline__ uint32_t f2tf32(float f) {
    uint32_t r;
    asm("cvt.rna.tf32.f32 %0, %1;" : "=r"(r) : "f"(f));
    return r;
}
__device__ __forceinline__ float roundtf(float f) { return __uint_as_float(f2tf32(f)); }

__device__ __forceinline__ void mma_tf32(float c[4], const uint32_t a[4], uint32_t b0, uint32_t b1) {
    asm volatile(
        "mma.sync.aligned.m16n8k8.row.col.f32.tf32.tf32.f32 "
        "{%0,%1,%2,%3},{%4,%5,%6,%7},{%8,%9},{%0,%1,%2,%3};"
        : "+f"(c[0]), "+f"(c[1]), "+f"(c[2]), "+f"(c[3])
        : "r"(a[0]), "r"(a[1]), "r"(a[2]), "r"(a[3]), "r"(b0), "r"(b1));
}
__device__ __forceinline__ void ldsm4(uint32_t r[4], uint32_t addr) {
    asm volatile("ldmatrix.sync.aligned.m8n8.x4.shared.b16 {%0,%1,%2,%3}, [%4];"
        : "=r"(r[0]), "=r"(r[1]), "=r"(r[2]), "=r"(r[3]) : "r"(addr));
}
#define CP16(dst, src) asm volatile("cp.async.cg.shared.global [%0], [%1], 16;" :: "r"(dst), "l"(src))
#define CP_COMMIT() asm volatile("cp.async.commit_group;")
#define CP_WAIT2() asm volatile("cp.async.wait_group 2;")
#define CP_WAIT0() asm volatile("cp.async.wait_group 0;")

// ---------------- small kernels ------------------------------------------------
__global__ void cvt_k(const float4* __restrict__ s, float4* __restrict__ d, size_t n4) {
    size_t i = (size_t)blockIdx.x * blockDim.x + threadIdx.x;
    size_t stride = (size_t)gridDim.x * blockDim.x;
    for (; i < n4; i += stride) {
        float4 v = s[i];
        v.x = roundtf(v.x); v.y = roundtf(v.y);
        v.z = roundtf(v.z); v.w = roundtf(v.w);
        d[i] = v;
    }
}

__global__ void embed_k(const int* __restrict__ ids, const float* __restrict__ tok,
                        const float* __restrict__ pos, float* __restrict__ x) {
    int row = blockIdx.x;
    int t = row % TT;
    int id = ids[row];
    const float* te = tok + (size_t)id * DD;
    const float* pe = pos + (size_t)t * DD;
    float* xr = x + (size_t)row * DD;
    for (int i = threadIdx.x; i < DD; i += blockDim.x)
        xr[i] = te[i] + pe[i];
}

__global__ void ln_k(const float* __restrict__ x, float* __restrict__ y,
                     const float* __restrict__ g, const float* __restrict__ b) {
    __shared__ float s1[256], s2[256];
    int row = blockIdx.x, tid = threadIdx.x;
    const float* xr = x + (size_t)row * DD;
    float sum = 0.f, sq = 0.f;
    for (int i = tid; i < DD; i += 256) { float v = xr[i]; sum += v; sq += v * v; }
    s1[tid] = sum; s2[tid] = sq; __syncthreads();
    for (int s = 128; s > 0; s >>= 1) {
        if (tid < s) { s1[tid] += s1[tid + s]; s2[tid] += s2[tid + s]; }
        __syncthreads();
    }
    float mu = s1[0] * (1.0f / DD);
    float var = s2[0] * (1.0f / DD) - mu * mu;
    float rstd = rsqrtf(var + 1e-5f);
    float* yr = y + (size_t)row * DD;
    for (int i = tid; i < DD; i += 256)
        yr[i] = roundtf((xr[i] - mu) * rstd * g[i] + b[i]);
}

// ---------------- tensor-core GEMM (tf32, cp.async 4-stage) --------------------
// flags: 1 bias, 2 relu, 4 accumulate, 8 causal-K, 16 round-store-tf32
#define APITCH 20
#define BPITCH 136
#define AWORDS (128*APITCH)
#define BWORDS (16*BPITCH)
#define STG_WORDS (AWORDS + BWORDS)   // 4736
#define NSTG 4
#define SMEM_BYTES (NSTG*STG_WORDS*4) // 75776
__global__ __launch_bounds__(256, 2)
void gemm_tc(const float* __restrict__ A, const float* __restrict__ Bm,
             float* __restrict__ C,
             int K, int lda, int ldb, int ldc,
             int Nh, size_t hstride,
             const float* __restrict__ bias, int flags,
             int batchH,
             size_t aOuter, size_t aInner,
             size_t bOuter, size_t bInner,
             size_t cOuter, size_t cInner) {
    extern __shared__ __align__(16) uint32_t smem[];
    int z = blockIdx.z;
    int zo = z / batchH, zi = z - zo * batchH;
    A  += zo * aOuter + zi * aInner;
    Bm += zo * bOuter + zi * bInner;
    C  += zo * cOuter + zi * cInner;

    const int tid  = threadIdx.x;
    const int lane = tid & 31;
    const int warp = tid >> 5;
    const int wm = warp >> 2;
    const int wn = warp & 3;
    const int m0 = blockIdx.y * 128;
    const int n0 = blockIdx.x * 128;

    int Kc = K;
    if (flags & 8) { int ke = (blockIdx.y + 1) * 128; if (ke < Kc) Kc = ke; }
    const int steps = Kc >> 4;

    const int ar = tid >> 2;
    const int ac = (tid & 3) << 2;
    const int brr = tid >> 5;
    const int bcc = (tid & 31) << 2;
    const float* aP = A + (size_t)(m0 + ar) * lda + ac;
    const int gcol = n0 + bcc;
    const float* bP = Bm + (size_t)(gcol / Nh) * hstride + (size_t)(gcol % Nh);

    const uint32_t smemBase = (uint32_t)__cvta_generic_to_shared(smem);
    const uint32_t aDst0 = smemBase + (uint32_t)((ar * APITCH + ac) * 4);
    const uint32_t aDst1 = smemBase + (uint32_t)(((ar + 64) * APITCH + ac) * 4);
    const uint32_t bDst0 = smemBase + (uint32_t)((AWORDS + brr * BPITCH + bcc) * 4);
    const uint32_t bDst1 = smemBase + (uint32_t)((AWORDS + (brr + 8) * BPITCH + bcc) * 4);

    float acc[4][4][4];
#pragma unroll
    for (int mt = 0; mt < 4; mt++)
#pragma unroll
        for (int nt = 0; nt < 4; nt++)
#pragma unroll
            for (int i = 0; i < 4; i++) acc[mt][nt][i] = 0.f;

    const int aRowF = wm * 64 + (lane & 7) + ((lane >> 3) & 1) * 8;
    const int aColF = ((lane >> 4) & 1) * 4;
    const uint32_t aFragBase = smemBase + (uint32_t)((aRowF * APITCH + aColF) * 4);
    const int bRowF = lane & 3;
    const int bColF = wn * 32 + (lane >> 2);

    // prologue: issue loads for tiles 0..2
#pragma unroll
    for (int pt = 0; pt < NSTG - 1; pt++) {
        if (pt < steps) {
            const uint32_t so = (uint32_t)(pt * STG_WORDS * 4);
            const int k0 = pt << 4;
            CP16(aDst0 + so, aP + k0);
            CP16(aDst1 + so, aP + (size_t)64 * lda + k0);
            CP16(bDst0 + so, bP + (size_t)(k0 + brr) * ldb);
            CP16(bDst1 + so, bP + (size_t)(k0 + brr + 8) * ldb);
        }
        CP_COMMIT();
    }

    int stg = 0;
    for (int s = 0; s < steps; s++) {
        CP_WAIT2();
        __syncthreads();   // all warps done with iter s-1; stage s resident

        // refill the stage vacated at iter s-1 (stage (s+3)%4 == (s-1)%4)
        {
            const int nt_ = s + NSTG - 1;
            if (nt_ < steps) {
                int ns = stg + NSTG - 1; if (ns >= NSTG) ns -= NSTG;
                const uint32_t so = (uint32_t)(ns * STG_WORDS * 4);
                const int k0 = nt_ << 4;
                CP16(aDst0 + so, aP + k0);
                CP16(aDst1 + so, aP + (size_t)64 * lda + k0);
                CP16(bDst0 + so, bP + (size_t)(k0 + brr) * ldb);
                CP16(bDst1 + so, bP + (size_t)(k0 + brr + 8) * ldb);
            }
            CP_COMMIT();
        }

        const uint32_t aSt = aFragBase + (uint32_t)(stg * STG_WORDS * 4);
        const uint32_t* bBase = smem + stg * STG_WORDS + AWORDS;
#pragma unroll
        for (int ks = 0; ks < 2; ks++) {
            uint32_t af[4][4];
#pragma unroll
            for (int mt = 0; mt < 4; mt++)
                ldsm4(af[mt], aSt + (uint32_t)((mt * 16 * APITCH + ks * 8) * 4));
            const uint32_t* b0p = bBase + (ks * 8 + bRowF) * BPITCH + bColF;
            const uint32_t* b1p = b0p + 4 * BPITCH;
#pragma unroll
            for (int nt = 0; nt < 4; nt++) {
                uint32_t b0 = b0p[nt * 8];
                uint32_t b1 = b1p[nt * 8];
#pragma unroll
                for (int mt = 0; mt < 4; mt++)
                    mma_tf32(acc[mt][nt], af[mt], b0, b1);
            }
        }
        stg++; if (stg >= NSTG) stg = 0;
    }

    // epilogue
#pragma unroll
    for (int mt = 0; mt < 4; mt++) {
        const int row = m0 + wm * 64 + mt * 16 + (lane >> 2);
#pragma unroll
        for (int nt = 0; nt < 4; nt++) {
            const int col = n0 + wn * 32 + nt * 8 + (lane & 3) * 2;
            float2 bi = make_float2(0.f, 0.f);
            if (flags & 1) bi = *(const float2*)(bias + col);
            float2 v0 = make_float2(acc[mt][nt][0] + bi.x, acc[mt][nt][1] + bi.y);
            float2 v1 = make_float2(acc[mt][nt][2] + bi.x, acc[mt][nt][3] + bi.y);
            if (flags & 2) {
                v0.x = fmaxf(v0.x, 0.f); v0.y = fmaxf(v0.y, 0.f);
                v1.x = fmaxf(v1.x, 0.f); v1.y = fmaxf(v1.y, 0.f);
            }
            float* c0 = C + (size_t)row * ldc + col;
            float* c1 = C + (size_t)(row + 8) * ldc + col;
            if (flags & 4) {
                float2 o0 = *(float2*)c0, o1 = *(float2*)c1;
                v0.x += o0.x; v0.y += o0.y; v1.x += o1.x; v1.y += o1.y;
            }
            if (flags & 16) {
                v0.x = roundtf(v0.x); v0.y = roundtf(v0.y);
                v1.x = roundtf(v1.x); v1.y = roundtf(v1.y);
            }
            *(float2*)c0 = v0;
            *(float2*)c1 = v1;
        }
    }
}

// ---------------- attention scores on tensor cores ------------------------------
#define SPITCH 68
#define S_AWORDS (128*SPITCH)
#define SCORE_SMEM (2*S_AWORDS*4)   // 69632 bytes
__global__ __launch_bounds__(256, 2)
void score_tc(const float* __restrict__ q, const float* __restrict__ k,
              float* __restrict__ p) {
    extern __shared__ __align__(16) uint32_t ss[];
    const int z = blockIdx.z;           // b*HH + h
    const int b = z / HH, h = z - b * HH;
    const int m0 = blockIdx.y * 128;
    const int n0 = blockIdx.x * 128;
    if (n0 > m0 + 127) return;          // fully masked tile

    const int tid  = threadIdx.x;
    const int lane = tid & 31;
    const int warp = tid >> 5;
    const int wm = warp >> 2;
    const int wn = warp & 3;

    const float* qb = q + ((size_t)(b * TT + m0)) * DD + h * KH;
    const float* kb = k + ((size_t)(b * TT + n0)) * DD + h * KH;

    const uint32_t base = (uint32_t)__cvta_generic_to_shared(ss);
#pragma unroll
    for (int i = 0; i < 8; i++) {
        int lin = tid + i * 256;
        int row = lin >> 4;
        int col = (lin & 15) << 2;
        CP16(base + (uint32_t)((row * SPITCH + col) * 4), qb + (size_t)row * DD + col);
        CP16(base + (uint32_t)((S_AWORDS + row * SPITCH + col) * 4), kb + (size_t)row * DD + col);
    }
    CP_COMMIT();
    CP_WAIT0();
    __syncthreads();

    float acc[4][4][4];
#pragma unroll
    for (int mt = 0; mt < 4; mt++)
#pragma unroll
        for (int nt = 0; nt < 4; nt++)
#pragma unroll
            for (int i = 0; i < 4; i++) acc[mt][nt][i] = 0.f;

    const uint32_t aFragBase = base +
        (uint32_t)(((wm * 64 + (lane & 7) + ((lane >> 3) & 1) * 8) * SPITCH +
                    ((lane >> 4) & 1) * 4) * 4);
    const uint32_t* Ks = ss + S_AWORDS;
    const int bN = wn * 32 + (lane >> 2);
    const int bK = lane & 3;

#pragma unroll
    for (int ks = 0; ks < 8; ks++) {
        uint32_t af[4][4];
#pragma unroll
        for (int mt = 0; mt < 4; mt++)
            ldsm4(af[mt], aFragBase + (uint32_t)((mt * 16 * SPITCH + ks * 8) * 4));
#pragma unroll
        for (int nt = 0; nt < 4; nt++) {
            uint32_t b0 = Ks[(bN + nt * 8) * SPITCH + ks * 8 + bK];
            uint32_t b1 = Ks[(bN + nt * 8) * SPITCH + ks * 8 + 4 + bK];
#pragma unroll
            for (int mt = 0; mt < 4; mt++)
                mma_tf32(acc[mt][nt], af[mt], b0, b1);
        }
    }

    float* pz = p + (size_t)z * TT * TT;
#pragma unroll
    for (int mt = 0; mt < 4; mt++) {
        const int row = m0 + wm * 64 + mt * 16 + (lane >> 2);
#pragma unroll
        for (int nt = 0; nt < 4; nt++) {
            const int col = n0 + wn * 32 + nt * 8 + (lane & 3) * 2;
            float2 v0 = make_float2(acc[mt][nt][0] * 0.125f, acc[mt][nt][1] * 0.125f);
            float2 v1 = make_float2(acc[mt][nt][2] * 0.125f, acc[mt][nt][3] * 0.125f);
            *(float2*)(pz + (size_t)row * TT + col) = v0;
            *(float2*)(pz + (size_t)(row + 8) * TT + col) = v1;
        }
    }
}

// ---------------- causal softmax (bounded, fast exp, in place) ------------------
__global__ void attn_sm(float* __restrict__ p) {
    int t = blockIdx.x, h = blockIdx.y, b = blockIdx.z;
    int tid = threadIdx.x;  // 256
    __shared__ float red[256];
    float* row = p + ((size_t)((b * HH + h) * TT + t)) * TT;
    const int valid = t + 1;
    const int rowEnd = ((t >> 7) + 1) << 7;   // 128-tile boundary (AV reads up to here)

    float sc[4];
#pragma unroll
    for (int i = 0; i < 4; i++) {
        int s = tid + i * 256;
        sc[i] = (s < valid) ? row[s] : -INFINITY;
    }
    float m = fmaxf(fmaxf(sc[0], sc[1]), fmaxf(sc[2], sc[3]));
    red[tid] = m; __syncthreads();
    for (int s = 128; s > 0; s >>= 1) { if (tid < s) red[tid] = fmaxf(red[tid], red[tid + s]); __syncthreads(); }
    m = red[0]; __syncthreads();
    float lsum = 0.f;
#pragma unroll
    for (int i = 0; i < 4; i++) {
        int s = tid + i * 256;
        sc[i] = (s < valid) ? __expf(sc[i] - m) : 0.f;
        lsum += sc[i];
    }
    red[tid] = lsum; __syncthreads();
    for (int s = 128; s > 0; s >>= 1) { if (tid < s) red[tid] += red[tid + s]; __syncthreads(); }
    float inv = 1.f / red[0];
#pragma unroll
    for (int i = 0; i < 4; i++) {
        int s = tid + i * 256;
        if (s < rowEnd) row[s] = roundtf(sc[i] * inv);
    }
}

// ---------------- loss ----------------------------------------------------------
__global__ void loss_row_k(const float* __restrict__ logits, const int* __restrict__ tgt,
                           float* __restrict__ rl) {
    int row = blockIdx.x, tid = threadIdx.x;
    const float* lr = logits + (size_t)row * VV;
    __shared__ float red[256];
    float m = -INFINITY;
    for (int i = tid; i < VV; i += 256) m = fmaxf(m, lr[i]);
    red[tid] = m; __syncthreads();
    for (int s = 128; s > 0; s >>= 1) { if (tid < s) red[tid] = fmaxf(red[tid], red[tid + s]); __syncthreads(); }
    m = red[0]; __syncthreads();
    float sum = 0.f;
    for (int i = tid; i < VV; i += 256) sum += __expf(lr[i] - m);
    red[tid] = sum; __syncthreads();
    for (int s = 128; s > 0; s >>= 1) { if (tid < s) red[tid] += red[tid + s]; __syncthreads(); }
    if (tid == 0) {
        float lse = m + logf(red[0]);
        rl[row] = lse - lr[tgt[row]];
    }
}

__global__ void loss_final_k(const float* __restrict__ rl, float* __restrict__ out) {
    __shared__ float red[256];
    int tid = threadIdx.x;
    float s = 0.f;
    for (int i = tid; i < ROWS; i += 256) s += rl[i];
    red[tid] = s; __syncthreads();
    for (int k = 128; k > 0; k >>= 1) { if (tid < k) red[tid] += red[tid + k]; __syncthreads(); }
    if (tid == 0) out[0] = red[0] * (1.0f / ROWS);
}

__global__ void fill0_k(float* p, size_t n) {
    size_t i = (size_t)blockIdx.x * blockDim.x + threadIdx.x;
    if (i < n) p[i] = 0.f;
}

// ---------------- host-side launcher -------------------------------------------
static inline void gemm(const float* A, const float* B, float* C,
                        int M, int N, int K, int lda, int ldb, int ldc,
                        int Nh, size_t hs, const float* bias, int flags,
                        int batch = 1, int batchH = 1,
                        size_t aO = 0, size_t aI = 0,
                        size_t bO = 0, size_t bI = 0,
                        size_t cO = 0, size_t cI = 0) {
    dim3 grid(N / 128, M / 128, batch);
    gemm_tc<<<grid, 256, SMEM_BYTES>>>(A, B, C, K, lda, ldb, ldc, Nh, hs, bias, flags,
                                       batchH, aO, aI, bO, bI, cO, cI);
}

extern "C" void kernel_launch(void* const* d_in, const int* in_sizes, int n_in,
                              void* d_out, int out_size) {
    const int*   ids   = (const int*)d_in[0];
    const int*   tgt   = (const int*)d_in[1];
    const float* tok   = (const float*)d_in[2];
    const float* pos   = (const float*)d_in[3];
    const float* Wq_i  = (const float*)d_in[4];
    const float* Wk_i  = (const float*)d_in[5];
    const float* Wv_i  = (const float*)d_in[6];
    const float* Wp_i  = (const float*)d_in[7];
    const float* bproj = (const float*)d_in[8];
    const float* ln1g  = (const float*)d_in[9];
    const float* ln1b  = (const float*)d_in[10];
    const float* ln2g  = (const float*)d_in[11];
    const float* ln2b  = (const float*)d_in[12];
    const float* W1_i  = (const float*)d_in[13];
    const float* b1    = (const float*)d_in[14];
    const float* W2_i  = (const float*)d_in[15];
    const float* b2    = (const float*)d_in[16];
    const float* lnfg  = (const float*)d_in[17];
    const float* lnfb  = (const float*)d_in[18];
    const float* Wh_i  = (const float*)d_in[19];
    const float* bhead = (const float*)d_in[20];

    float *x, *h, *q, *k, *v, *o, *p, *f, *rl, *wc;
    cudaGetSymbolAddress((void**)&x, g_x);
    cudaGetSymbolAddress((void**)&h, g_h);
    cudaGetSymbolAddress((void**)&q, g_q);
    cudaGetSymbolAddress((void**)&k, g_k);
    cudaGetSymbolAddress((void**)&v, g_v);
    cudaGetSymbolAddress((void**)&o, g_o);
    cudaGetSymbolAddress((void**)&p, g_p);
    cudaGetSymbolAddress((void**)&f, g_f);
    cudaGetSymbolAddress((void**)&rl, g_rl);
    cudaGetSymbolAddress((void**)&wc, g_wc);

    static bool attrSet = false;
    if (!attrSet) {
        cudaFuncSetAttribute(gemm_tc, cudaFuncAttributeMaxDynamicSharedMemorySize, SMEM_BYTES);
        cudaFuncSetAttribute(score_tc, cudaFuncAttributeMaxDynamicSharedMemorySize, SCORE_SMEM);
        attrSet = true;
    }

    float* Wq = wc + O_WQ;  float* Wk = wc + O_WK;  float* Wv = wc + O_WV;
    float* Wp = wc + O_WP;  float* W1 = wc + O_W1;  float* W2 = wc + O_W2;
    float* Wh = wc + O_WH;

    cvt_k<<<1024, 256>>>((const float4*)Wq_i, (float4*)Wq, (size_t)WQ_SZ / 4);
    cvt_k<<<1024, 256>>>((const float4*)Wk_i, (float4*)Wk, (size_t)WQ_SZ / 4);
    cvt_k<<<2048, 256>>>((const float4*)Wv_i, (float4*)Wv, (size_t)WV_SZ / 4);
    cvt_k<<<2048, 256>>>((const float4*)Wp_i, (float4*)Wp, (size_t)WP_SZ / 4);
    cvt_k<<<1024, 256>>>((const float4*)W1_i, (float4*)W1, (size_t)W1_SZ / 4);
    cvt_k<<<1024, 256>>>((const float4*)W2_i, (float4*)W2, (size_t)W1_SZ / 4);
    cvt_k<<<2048, 256>>>((const float4*)Wh_i, (float4*)Wh, (size_t)WH_SZ / 4);

    float* out = (float*)d_out;
    const size_t NL = (size_t)ROWS * VV;

    embed_k<<<ROWS, 256>>>(ids, tok, pos, x);

    for (int l = 0; l < LL; l++) {
        ln_k<<<ROWS, 256>>>(x, h, ln1g + l * DD, ln1b + l * DD);
        gemm(h, Wq + (size_t)l * HH * DD * KH, q, ROWS, DD, DD, DD, KH, DD,
             KH, (size_t)DD * KH, nullptr, 0);
        gemm(h, Wk + (size_t)l * HH * DD * KH, k, ROWS, DD, DD, DD, KH, DD,
             KH, (size_t)DD * KH, nullptr, 0);
        gemm(h, Wv + (size_t)l * HH * DD * DD, v, ROWS, HD, DD, DD, DD, HD,
             DD, (size_t)DD * DD, nullptr, 16);
        {
            dim3 grid(TT / 128, TT / 128, BSZ * HH);
            score_tc<<<grid, 256, SCORE_SMEM>>>(q, k, p);
            dim3 grid2(TT, HH, BSZ);
            attn_sm<<<grid2, 256>>>(p);
        }
        gemm(p, v, o, TT, DD, TT, TT, HD, HD, DD, 0, nullptr, 8 | 16,
             BSZ * HH, HH,
             (size_t)HH * TT * TT, (size_t)TT * TT,
             (size_t)TT * HD, (size_t)DD,
             (size_t)TT * HD, (size_t)DD);
        gemm(o, Wp + (size_t)l * HD * DD, x, ROWS, DD, HD, HD, DD, DD,
             DD, 0, bproj + l * DD, 1 | 4);
        ln_k<<<ROWS, 256>>>(x, h, ln2g + l * DD, ln2b + l * DD);
        gemm(h, W1 + (size_t)l * DD * FF, f, ROWS, FF, DD, DD, FF, FF,
             FF, 0, b1 + l * FF, 1 | 2 | 16);
        gemm(f, W2 + (size_t)l * FF * DD, x, ROWS, DD, FF, FF, DD, DD,
             DD, 0, b2 + l * DD, 1 | 4);
    }

    ln_k<<<ROWS, 256>>>(x, h, lnfg, lnfb);

    gemm(h, Wh, out, ROWS, VV, DD, DD, VV, VV, VV, 0, bhead, 1);
    loss_row_k<<<ROWS, 256>>>(out, tgt, rl);
    if ((size_t)out_size >= NL + 1) {
        loss_final_k<<<1, 256>>>(rl, out + NL);
        size_t tail = (size_t)out_size - (NL + 1);
        if (tail > 0)
            fill0_k<<<(int)((tail + 255) / 256), 256>>>(out + NL + 1, tail);
    }
}

// round 8
// speedup vs baseline: 6.6378x; 1.0137x over previous
#include <cuda_runtime.h>
#include <math.h>
#include <stdint.h>
#include <cuda_bf16.h>
#include <cuda_fp16.h>

// Problem constants
#define BSZ 4
#define TT 1024
#define DD 768
#define HH 12
#define KH 64
#define LL 6
#define VV 32000
#define FF 3072
#define HD 9216
#define ROWS (BSZ*TT)  // 4096
#define L2E 1.44269504088896340736f

// ---------------- scratch ------------------------------------------------------
__device__ float g_x[(size_t)ROWS*DD];
__device__ float g_h[(size_t)ROWS*DD];
__device__ float g_qk[(size_t)2*ROWS*DD];   // q then k
__device__ float g_v[(size_t)ROWS*HD];
__device__ float g_o[(size_t)ROWS*HD];
__device__ float g_p[(size_t)BSZ*HH*TT*TT];
__device__ float g_f[(size_t)ROWS*FF];
__device__ float g_rl[ROWS];

// tf32-rounded weights
#define WQ_SZ  3538944
#define WV_SZ  42467328
#define WP_SZ  42467328
#define W1_SZ  14155776
#define WH_SZ  24576000
#define O_WQ   0
#define O_WK   (O_WQ + WQ_SZ)
#define O_WV   (O_WK + WQ_SZ)
#define O_WP   (O_WV + WV_SZ)
#define O_W1   (O_WP + WP_SZ)
#define O_W2   (O_W1 + W1_SZ)
#define O_WH   (O_W2 + W1_SZ)
#define WC_TOTAL (O_WH + WH_SZ)
__device__ float g_wc[(size_t)WC_TOTAL];

// ---------------- helpers ------------------------------------------------------
__device__ __forceinline__ uint32_t f2tf32(float f) {
    uint32_t r;
    asm("cvt.rna.tf32.f32 %0, %1;" : "=r"(r) : "f"(f));
    return r;
}
__device__ __forceinline__ float roundtf(float f) { return __uint_as_float(f2tf32(f)); }

// two exp2's through one MUFU op (f16x2)
__device__ __forceinline__ float2 exp2_pair(float a, float b) {
    __half2 p = __floats2half2_rn(a, b);   // .x=a, .y=b
    __half2 e = h2exp2(p);
    return __half22float2(e);
}

__device__ __forceinline__ void mma_tf32(float c[4], const uint32_t a[4], uint32_t b0, uint32_t b1) {
    asm volatile(
        "mma.sync.aligned.m16n8k8.row.col.f32.tf32.tf32.f32 "
        "{%0,%1,%2,%3},{%4,%5,%6,%7},{%8,%9},{%0,%1,%2,%3};"
        : "+f"(c[0]), "+f"(c[1]), "+f"(c[2]), "+f"(c[3])
        : "r"(a[0]), "r"(a[1]), "r"(a[2]), "r"(a[3]), "r"(b0), "r"(b1));
}
__device__ __forceinline__ void ldsm4(uint32_t r[4], uint32_t addr) {
    asm volatile("ldmatrix.sync.aligned.m8n8.x4.shared.b16 {%0,%1,%2,%3}, [%4];"
        : "=r"(r[0]), "=r"(r[1]), "=r"(r[2]), "=r"(r[3]) : "r"(addr));
}
#define CP16(dst, src) asm volatile("cp.async.cg.shared.global [%0], [%1], 16;" :: "r"(dst), "l"(src))
#define CP_COMMIT() asm volatile("cp.async.commit_group;")
#define CP_WAIT2() asm volatile("cp.async.wait_group 2;")
#define CP_WAIT0() asm volatile("cp.async.wait_group 0;")

// ---------------- small kernels ------------------------------------------------
__global__ void cvt_k(const float4* __restrict__ s, float4* __restrict__ d, size_t n4) {
    size_t i = (size_t)blockIdx.x * blockDim.x + threadIdx.x;
    size_t stride = (size_t)gridDim.x * blockDim.x;
    for (; i < n4; i += stride) {
        float4 v = s[i];
        v.x = roundtf(v.x); v.y = roundtf(v.y);
        v.z = roundtf(v.z); v.w = roundtf(v.w);
        d[i] = v;
    }
}

__global__ void embed_k(const int* __restrict__ ids, const float* __restrict__ tok,
                        const float* __restrict__ pos, float* __restrict__ x) {
    int row = blockIdx.x;
    int t = row % TT;
    int id = ids[row];
    const float* te = tok + (size_t)id * DD;
    const float* pe = pos + (size_t)t * DD;
    float* xr = x + (size_t)row * DD;
    for (int i = threadIdx.x; i < DD; i += blockDim.x)
        xr[i] = te[i] + pe[i];
}

__global__ void ln_k(const float* __restrict__ x, float* __restrict__ y,
                     const float* __restrict__ g, const float* __restrict__ b) {
    __shared__ float s1[256], s2[256];
    int row = blockIdx.x, tid = threadIdx.x;
    const float* xr = x + (size_t)row * DD;
    float sum = 0.f, sq = 0.f;
    for (int i = tid; i < DD; i += 256) { float v = xr[i]; sum += v; sq += v * v; }
    s1[tid] = sum; s2[tid] = sq; __syncthreads();
    for (int s = 128; s > 0; s >>= 1) {
        if (tid < s) { s1[tid] += s1[tid + s]; s2[tid] += s2[tid + s]; }
        __syncthreads();
    }
    float mu = s1[0] * (1.0f / DD);
    float var = s2[0] * (1.0f / DD) - mu * mu;
    float rstd = rsqrtf(var + 1e-5f);
    float* yr = y + (size_t)row * DD;
    for (int i = tid; i < DD; i += 256)
        yr[i] = roundtf((xr[i] - mu) * rstd * g[i] + b[i]);
}

// ---------------- tensor-core GEMM (tf32, cp.async 4-stage) --------------------
// flags: 1 bias, 2 relu, 4 accumulate, 8 causal-K, 16 round-store-tf32
#define APITCH 20
#define BPITCH 136
#define AWORDS (128*APITCH)
#define BWORDS (16*BPITCH)
#define STG_WORDS (AWORDS + BWORDS)   // 4736
#define NSTG 4
#define SMEM_BYTES (NSTG*STG_WORDS*4) // 75776
__global__ __launch_bounds__(256, 2)
void gemm_tc(const float* __restrict__ A, const float* __restrict__ Bm,
             float* __restrict__ C,
             int K, int lda, int ldb, int ldc,
             int Nh, size_t hstride,
             const float* __restrict__ bias, int flags,
             int batchH,
             size_t aOuter, size_t aInner,
             size_t bOuter, size_t bInner,
             size_t cOuter, size_t cInner) {
    extern __shared__ __align__(16) uint32_t smem[];
    int z = blockIdx.z;
    int zo = z / batchH, zi = z - zo * batchH;
    A  += zo * aOuter + zi * aInner;
    Bm += zo * bOuter + zi * bInner;
    C  += zo * cOuter + zi * cInner;

    const int tid  = threadIdx.x;
    const int lane = tid & 31;
    const int warp = tid >> 5;
    const int wm = warp >> 2;
    const int wn = warp & 3;
    const int m0 = blockIdx.y * 128;
    const int n0 = blockIdx.x * 128;

    int Kc = K;
    if (flags & 8) { int ke = (blockIdx.y + 1) * 128; if (ke < Kc) Kc = ke; }
    const int steps = Kc >> 4;

    const int ar = tid >> 2;
    const int ac = (tid & 3) << 2;
    const int brr = tid >> 5;
    const int bcc = (tid & 31) << 2;
    const float* aP = A + (size_t)(m0 + ar) * lda + ac;
    const int gcol = n0 + bcc;
    const float* bP = Bm + (size_t)(gcol / Nh) * hstride + (size_t)(gcol % Nh);

    const uint32_t smemBase = (uint32_t)__cvta_generic_to_shared(smem);
    const uint32_t aDst0 = smemBase + (uint32_t)((ar * APITCH + ac) * 4);
    const uint32_t aDst1 = smemBase + (uint32_t)(((ar + 64) * APITCH + ac) * 4);
    const uint32_t bDst0 = smemBase + (uint32_t)((AWORDS + brr * BPITCH + bcc) * 4);
    const uint32_t bDst1 = smemBase + (uint32_t)((AWORDS + (brr + 8) * BPITCH + bcc) * 4);

    float acc[4][4][4];
#pragma unroll
    for (int mt = 0; mt < 4; mt++)
#pragma unroll
        for (int nt = 0; nt < 4; nt++)
#pragma unroll
            for (int i = 0; i < 4; i++) acc[mt][nt][i] = 0.f;

    const int aRowF = wm * 64 + (lane & 7) + ((lane >> 3) & 1) * 8;
    const int aColF = ((lane >> 4) & 1) * 4;
    const uint32_t aFragBase = smemBase + (uint32_t)((aRowF * APITCH + aColF) * 4);
    const int bRowF = lane & 3;
    const int bColF = wn * 32 + (lane >> 2);

    // prologue: issue loads for tiles 0..2
#pragma unroll
    for (int pt = 0; pt < NSTG - 1; pt++) {
        if (pt < steps) {
            const uint32_t so = (uint32_t)(pt * STG_WORDS * 4);
            const int k0 = pt << 4;
            CP16(aDst0 + so, aP + k0);
            CP16(aDst1 + so, aP + (size_t)64 * lda + k0);
            CP16(bDst0 + so, bP + (size_t)(k0 + brr) * ldb);
            CP16(bDst1 + so, bP + (size_t)(k0 + brr + 8) * ldb);
        }
        CP_COMMIT();
    }

    int stg = 0;
    for (int s = 0; s < steps; s++) {
        CP_WAIT2();
        __syncthreads();

        {
            const int nt_ = s + NSTG - 1;
            if (nt_ < steps) {
                int ns = stg + NSTG - 1; if (ns >= NSTG) ns -= NSTG;
                const uint32_t so = (uint32_t)(ns * STG_WORDS * 4);
                const int k0 = nt_ << 4;
                CP16(aDst0 + so, aP + k0);
                CP16(aDst1 + so, aP + (size_t)64 * lda + k0);
                CP16(bDst0 + so, bP + (size_t)(k0 + brr) * ldb);
                CP16(bDst1 + so, bP + (size_t)(k0 + brr + 8) * ldb);
            }
            CP_COMMIT();
        }

        const uint32_t aSt = aFragBase + (uint32_t)(stg * STG_WORDS * 4);
        const uint32_t* bBase = smem + stg * STG_WORDS + AWORDS;
#pragma unroll
        for (int ks = 0; ks < 2; ks++) {
            uint32_t af[4][4];
#pragma unroll
            for (int mt = 0; mt < 4; mt++)
                ldsm4(af[mt], aSt + (uint32_t)((mt * 16 * APITCH + ks * 8) * 4));
            const uint32_t* b0p = bBase + (ks * 8 + bRowF) * BPITCH + bColF;
            const uint32_t* b1p = b0p + 4 * BPITCH;
#pragma unroll
            for (int nt = 0; nt < 4; nt++) {
                uint32_t b0 = b0p[nt * 8];
                uint32_t b1 = b1p[nt * 8];
#pragma unroll
                for (int mt = 0; mt < 4; mt++)
                    mma_tf32(acc[mt][nt], af[mt], b0, b1);
            }
        }
        stg++; if (stg >= NSTG) stg = 0;
    }

    // epilogue
#pragma unroll
    for (int mt = 0; mt < 4; mt++) {
        const int row = m0 + wm * 64 + mt * 16 + (lane >> 2);
#pragma unroll
        for (int nt = 0; nt < 4; nt++) {
            const int col = n0 + wn * 32 + nt * 8 + (lane & 3) * 2;
            float2 bi = make_float2(0.f, 0.f);
            if (flags & 1) bi = *(const float2*)(bias + col);
            float2 v0 = make_float2(acc[mt][nt][0] + bi.x, acc[mt][nt][1] + bi.y);
            float2 v1 = make_float2(acc[mt][nt][2] + bi.x, acc[mt][nt][3] + bi.y);
            if (flags & 2) {
                v0.x = fmaxf(v0.x, 0.f); v0.y = fmaxf(v0.y, 0.f);
                v1.x = fmaxf(v1.x, 0.f); v1.y = fmaxf(v1.y, 0.f);
            }
            float* c0 = C + (size_t)row * ldc + col;
            float* c1 = C + (size_t)(row + 8) * ldc + col;
            if (flags & 4) {
                float2 o0 = *(float2*)c0, o1 = *(float2*)c1;
                v0.x += o0.x; v0.y += o0.y; v1.x += o1.x; v1.y += o1.y;
            }
            if (flags & 16) {
                v0.x = roundtf(v0.x); v0.y = roundtf(v0.y);
                v1.x = roundtf(v1.x); v1.y = roundtf(v1.y);
            }
            *(float2*)c0 = v0;
            *(float2*)c1 = v1;
        }
    }
}

// ---------------- attention scores on tensor cores ------------------------------
#define SPITCH 68
#define S_AWORDS (128*SPITCH)
#define SCORE_SMEM (2*S_AWORDS*4)   // 69632 bytes
__global__ __launch_bounds__(256, 2)
void score_tc(const float* __restrict__ q, const float* __restrict__ k,
              float* __restrict__ p) {
    extern __shared__ __align__(16) uint32_t ss[];
    const int z = blockIdx.z;           // b*HH + h
    const int b = z / HH, h = z - b * HH;
    const int m0 = blockIdx.y * 128;
    const int n0 = blockIdx.x * 128;
    if (n0 > m0 + 127) return;

    const int tid  = threadIdx.x;
    const int lane = tid & 31;
    const int warp = tid >> 5;
    const int wm = warp >> 2;
    const int wn = warp & 3;

    const float* qb = q + ((size_t)(b * TT + m0)) * DD + h * KH;
    const float* kb = k + ((size_t)(b * TT + n0)) * DD + h * KH;

    const uint32_t base = (uint32_t)__cvta_generic_to_shared(ss);
#pragma unroll
    for (int i = 0; i < 8; i++) {
        int lin = tid + i * 256;
        int row = lin >> 4;
        int col = (lin & 15) << 2;
        CP16(base + (uint32_t)((row * SPITCH + col) * 4), qb + (size_t)row * DD + col);
        CP16(base + (uint32_t)((S_AWORDS + row * SPITCH + col) * 4), kb + (size_t)row * DD + col);
    }
    CP_COMMIT();
    CP_WAIT0();
    __syncthreads();

    float acc[4][4][4];
#pragma unroll
    for (int mt = 0; mt < 4; mt++)
#pragma unroll
        for (int nt = 0; nt < 4; nt++)
#pragma unroll
            for (int i = 0; i < 4; i++) acc[mt][nt][i] = 0.f;

    const uint32_t aFragBase = base +
        (uint32_t)(((wm * 64 + (lane & 7) + ((lane >> 3) & 1) * 8) * SPITCH +
                    ((lane >> 4) & 1) * 4) * 4);
    const uint32_t* Ks = ss + S_AWORDS;
    const int bN = wn * 32 + (lane >> 2);
    const int bK = lane & 3;

#pragma unroll
    for (int ks = 0; ks < 8; ks++) {
        uint32_t af[4][4];
#pragma unroll
        for (int mt = 0; mt < 4; mt++)
            ldsm4(af[mt], aFragBase + (uint32_t)((mt * 16 * SPITCH + ks * 8) * 4));
#pragma unroll
        for (int nt = 0; nt < 4; nt++) {
            uint32_t b0 = Ks[(bN + nt * 8) * SPITCH + ks * 8 + bK];
            uint32_t b1 = Ks[(bN + nt * 8) * SPITCH + ks * 8 + 4 + bK];
#pragma unroll
            for (int mt = 0; mt < 4; mt++)
                mma_tf32(acc[mt][nt], af[mt], b0, b1);
        }
    }

    float* pz = p + (size_t)z * TT * TT;
#pragma unroll
    for (int mt = 0; mt < 4; mt++) {
        const int row = m0 + wm * 64 + mt * 16 + (lane >> 2);
#pragma unroll
        for (int nt = 0; nt < 4; nt++) {
            const int col = n0 + wn * 32 + nt * 8 + (lane & 3) * 2;
            float2 v0 = make_float2(acc[mt][nt][0] * 0.125f, acc[mt][nt][1] * 0.125f);
            float2 v1 = make_float2(acc[mt][nt][2] * 0.125f, acc[mt][nt][3] * 0.125f);
            *(float2*)(pz + (size_t)row * TT + col) = v0;
            *(float2*)(pz + (size_t)(row + 8) * TT + col) = v1;
        }
    }
}

// ---------------- causal softmax (bounded, f16x2 exp2, in place) ---------------
__global__ void attn_sm(float* __restrict__ p) {
    int t = blockIdx.x, h = blockIdx.y, b = blockIdx.z;
    int tid = threadIdx.x;  // 256
    __shared__ float red[256];
    float* row = p + ((size_t)((b * HH + h) * TT + t)) * TT;
    const int valid = t + 1;
    const int rowEnd = ((t >> 7) + 1) << 7;

    float sc[4];
#pragma unroll
    for (int i = 0; i < 4; i++) {
        int s = tid + i * 256;
        sc[i] = (s < valid) ? row[s] : -INFINITY;
    }
    float m = fmaxf(fmaxf(sc[0], sc[1]), fmaxf(sc[2], sc[3]));
    red[tid] = m; __syncthreads();
    for (int s = 128; s > 0; s >>= 1) { if (tid < s) red[tid] = fmaxf(red[tid], red[tid + s]); __syncthreads(); }
    m = red[0]; __syncthreads();

    // exp via f16x2 MUFU (2 per op); -inf inputs give exactly 0
    float2 e01 = exp2_pair((sc[0] - m) * L2E, (sc[1] - m) * L2E);
    float2 e23 = exp2_pair((sc[2] - m) * L2E, (sc[3] - m) * L2E);
    sc[0] = e01.x; sc[1] = e01.y; sc[2] = e23.x; sc[3] = e23.y;
    float lsum = sc[0] + sc[1] + sc[2] + sc[3];

    red[tid] = lsum; __syncthreads();
    for (int s = 128; s > 0; s >>= 1) { if (tid < s) red[tid] += red[tid + s]; __syncthreads(); }
    float inv = 1.f / red[0];
#pragma unroll
    for (int i = 0; i < 4; i++) {
        int s = tid + i * 256;
        if (s < rowEnd) row[s] = roundtf(sc[i] * inv);
    }
}

// ---------------- loss ----------------------------------------------------------
__global__ void loss_row_k(const float* __restrict__ logits, const int* __restrict__ tgt,
                           float* __restrict__ rl) {
    int row = blockIdx.x, tid = threadIdx.x;
    const float* lr = logits + (size_t)row * VV;
    __shared__ float red[256];
    float m = -INFINITY;
    for (int i = tid * 2; i < VV; i += 512) {
        float2 v = *(const float2*)(lr + i);
        m = fmaxf(m, fmaxf(v.x, v.y));
    }
    red[tid] = m; __syncthreads();
    for (int s = 128; s > 0; s >>= 1) { if (tid < s) red[tid] = fmaxf(red[tid], red[tid + s]); __syncthreads(); }
    m = red[0]; __syncthreads();
    float sum = 0.f;
    for (int i = tid * 2; i < VV; i += 512) {
        float2 v = *(const float2*)(lr + i);
        float2 e = exp2_pair((v.x - m) * L2E, (v.y - m) * L2E);
        sum += e.x + e.y;
    }
    red[tid] = sum; __syncthreads();
    for (int s = 128; s > 0; s >>= 1) { if (tid < s) red[tid] += red[tid + s]; __syncthreads(); }
    if (tid == 0) {
        float lse = m + logf(red[0]);
        rl[row] = lse - lr[tgt[row]];
    }
}

__global__ void loss_final_k(const float* __restrict__ rl, float* __restrict__ out) {
    __shared__ float red[256];
    int tid = threadIdx.x;
    float s = 0.f;
    for (int i = tid; i < ROWS; i += 256) s += rl[i];
    red[tid] = s; __syncthreads();
    for (int k = 128; k > 0; k >>= 1) { if (tid < k) red[tid] += red[tid + k]; __syncthreads(); }
    if (tid == 0) out[0] = red[0] * (1.0f / ROWS);
}

__global__ void fill0_k(float* p, size_t n) {
    size_t i = (size_t)blockIdx.x * blockDim.x + threadIdx.x;
    if (i < n) p[i] = 0.f;
}

// ---------------- host-side launcher -------------------------------------------
static inline void gemm(const float* A, const float* B, float* C,
                        int M, int N, int K, int lda, int ldb, int ldc,
                        int Nh, size_t hs, const float* bias, int flags,
                        int batch = 1, int batchH = 1,
                        size_t aO = 0, size_t aI = 0,
                        size_t bO = 0, size_t bI = 0,
                        size_t cO = 0, size_t cI = 0) {
    dim3 grid(N / 128, M / 128, batch);
    gemm_tc<<<grid, 256, SMEM_BYTES>>>(A, B, C, K, lda, ldb, ldc, Nh, hs, bias, flags,
                                       batchH, aO, aI, bO, bI, cO, cI);
}

extern "C" void kernel_launch(void* const* d_in, const int* in_sizes, int n_in,
                              void* d_out, int out_size) {
    const int*   ids   = (const int*)d_in[0];
    const int*   tgt   = (const int*)d_in[1];
    const float* tok   = (const float*)d_in[2];
    const float* pos   = (const float*)d_in[3];
    const float* Wq_i  = (const float*)d_in[4];
    const float* Wk_i  = (const float*)d_in[5];
    const float* Wv_i  = (const float*)d_in[6];
    const float* Wp_i  = (const float*)d_in[7];
    const float* bproj = (const float*)d_in[8];
    const float* ln1g  = (const float*)d_in[9];
    const float* ln1b  = (const float*)d_in[10];
    const float* ln2g  = (const float*)d_in[11];
    const float* ln2b  = (const float*)d_in[12];
    const float* W1_i  = (const float*)d_in[13];
    const float* b1    = (const float*)d_in[14];
    const float* W2_i  = (const float*)d_in[15];
    const float* b2    = (const float*)d_in[16];
    const float* lnfg  = (const float*)d_in[17];
    const float* lnfb  = (const float*)d_in[18];
    const float* Wh_i  = (const float*)d_in[19];
    const float* bhead = (const float*)d_in[20];

    float *x, *h, *qk, *v, *o, *p, *f, *rl, *wc;
    cudaGetSymbolAddress((void**)&x, g_x);
    cudaGetSymbolAddress((void**)&h, g_h);
    cudaGetSymbolAddress((void**)&qk, g_qk);
    cudaGetSymbolAddress((void**)&v, g_v);
    cudaGetSymbolAddress((void**)&o, g_o);
    cudaGetSymbolAddress((void**)&p, g_p);
    cudaGetSymbolAddress((void**)&f, g_f);
    cudaGetSymbolAddress((void**)&rl, g_rl);
    cudaGetSymbolAddress((void**)&wc, g_wc);

    static bool attrSet = false;
    if (!attrSet) {
        cudaFuncSetAttribute(gemm_tc, cudaFuncAttributeMaxDynamicSharedMemorySize, SMEM_BYTES);
        cudaFuncSetAttribute(score_tc, cudaFuncAttributeMaxDynamicSharedMemorySize, SCORE_SMEM);
        attrSet = true;
    }

    float* Wq = wc + O_WQ;  float* Wk = wc + O_WK;  float* Wv = wc + O_WV;
    float* Wp = wc + O_WP;  float* W1 = wc + O_W1;  float* W2 = wc + O_W2;
    float* Wh = wc + O_WH;
    float* q = qk;
    float* k = qk + (size_t)ROWS * DD;

    cvt_k<<<1024, 256>>>((const float4*)Wq_i, (float4*)Wq, (size_t)WQ_SZ / 4);
    cvt_k<<<1024, 256>>>((const float4*)Wk_i, (float4*)Wk, (size_t)WQ_SZ / 4);
    cvt_k<<<2048, 256>>>((const float4*)Wv_i, (float4*)Wv, (size_t)WV_SZ / 4);
    cvt_k<<<2048, 256>>>((const float4*)Wp_i, (float4*)Wp, (size_t)WP_SZ / 4);
    cvt_k<<<1024, 256>>>((const float4*)W1_i, (float4*)W1, (size_t)W1_SZ / 4);
    cvt_k<<<1024, 256>>>((const float4*)W2_i, (float4*)W2, (size_t)W1_SZ / 4);
    cvt_k<<<2048, 256>>>((const float4*)Wh_i, (float4*)Wh, (size_t)WH_SZ / 4);

    float* out = (float*)d_out;
    const size_t NL = (size_t)ROWS * VV;

    embed_k<<<ROWS, 256>>>(ids, tok, pos, x);

    for (int l = 0; l < LL; l++) {
        ln_k<<<ROWS, 256>>>(x, h, ln1g + l * DD, ln1b + l * DD);
        // q and k projections in ONE batched launch (z=0 -> q, z=1 -> k)
        gemm(h, Wq + (size_t)l * HH * DD * KH, q, ROWS, DD, DD, DD, KH, DD,
             KH, (size_t)DD * KH, nullptr, 0,
             2, 1,
             0, 0,                       // A identical for both
             (size_t)WQ_SZ, 0,           // B: Wk = Wq + WQ_SZ
             (size_t)ROWS * DD, 0);      // C: k = q + ROWS*DD
        gemm(h, Wv + (size_t)l * HH * DD * DD, v, ROWS, HD, DD, DD, DD, HD,
             DD, (size_t)DD * DD, nullptr, 16);
        {
            dim3 grid(TT / 128, TT / 128, BSZ * HH);
            score_tc<<<grid, 256, SCORE_SMEM>>>(q, k, p);
            dim3 grid2(TT, HH, BSZ);
            attn_sm<<<grid2, 256>>>(p);
        }
        gemm(p, v, o, TT, DD, TT, TT, HD, HD, DD, 0, nullptr, 8 | 16,
             BSZ * HH, HH,
             (size_t)HH * TT * TT, (size_t)TT * TT,
             (size_t)TT * HD, (size_t)DD,
             (size_t)TT * HD, (size_t)DD);
        gemm(o, Wp + (size_t)l * HD * DD, x, ROWS, DD, HD, HD, DD, DD,
             DD, 0, bproj + l * DD, 1 | 4);
        ln_k<<<ROWS, 256>>>(x, h, ln2g + l * DD, ln2b + l * DD);
        gemm(h, W1 + (size_t)l * DD * FF, f, ROWS, FF, DD, DD, FF, FF,
             FF, 0, b1 + l * FF, 1 | 2 | 16);
        gemm(f, W2 + (size_t)l * FF * DD, x, ROWS, DD, FF, FF, DD, DD,
             DD, 0, b2 + l * DD, 1 | 4);
    }

    ln_k<<<ROWS, 256>>>(x, h, lnfg, lnfb);

    gemm(h, Wh, out, ROWS, VV, DD, DD, VV, VV, VV, 0, bhead, 1);
    loss_row_k<<<ROWS, 256>>>(out, tgt, rl);
    if ((size_t)out_size >= NL + 1) {
        loss_final_k<<<1, 256>>>(rl, out + NL);
        size_t tail = (size_t)out_size - (NL + 1);
        if (tail > 0)
            fill0_k<<<(int)((tail + 255) / 256), 256>>>(out + NL + 1, tail);
    }
}

// round 9
// speedup vs baseline: 7.5326x; 1.1348x over previous
#include <cuda_runtime.h>
#include <math.h>
#include <stdint.h>
#include <cuda_bf16.h>
#include <cuda_fp16.h>

// Problem constants
#define BSZ 4
#define TT 1024
#define DD 768
#define HH 12
#define KH 64
#define LL 6
#define VV 32000
#define FF 3072
#define HD 9216
#define ROWS (BSZ*TT)  // 4096
#define L2E 1.44269504088896340736f

// ---------------- scratch ------------------------------------------------------
__device__ float g_x[(size_t)ROWS*DD];
__device__ float g_h[(size_t)ROWS*DD];
__device__ float g_qk[(size_t)2*ROWS*DD];   // q then k
__device__ float g_v[(size_t)ROWS*HD];
__device__ float g_o[(size_t)ROWS*HD];
__device__ float g_p[(size_t)BSZ*HH*TT*TT];
__device__ float g_f[(size_t)ROWS*FF];
__device__ float g_sk[(size_t)2*ROWS*DD];   // split-K partials
__device__ float g_rl[ROWS];

// tf32-rounded weights
#define WQ_SZ  3538944
#define WV_SZ  42467328
#define WP_SZ  42467328
#define W1_SZ  14155776
#define WH_SZ  24576000
#define O_WQ   0
#define O_WK   (O_WQ + WQ_SZ)
#define O_WV   (O_WK + WQ_SZ)
#define O_WP   (O_WV + WV_SZ)
#define O_W1   (O_WP + WP_SZ)
#define O_W2   (O_W1 + W1_SZ)
#define O_WH   (O_W2 + W1_SZ)
#define WC_TOTAL (O_WH + WH_SZ)
__device__ float g_wc[(size_t)WC_TOTAL];

// ---------------- helpers ------------------------------------------------------
__device__ __forceinline__ uint32_t f2tf32(float f) {
    uint32_t r;
    asm("cvt.rna.tf32.f32 %0, %1;" : "=r"(r) : "f"(f));
    return r;
}
__device__ __forceinline__ float roundtf(float f) { return __uint_as_float(f2tf32(f)); }

__device__ __forceinline__ float2 exp2_pair(float a, float b) {
    __half2 p = __floats2half2_rn(a, b);
    __half2 e = h2exp2(p);
    return __half22float2(e);
}

__device__ __forceinline__ void mma_tf32(float c[4], const uint32_t a[4], uint32_t b0, uint32_t b1) {
    asm volatile(
        "mma.sync.aligned.m16n8k8.row.col.f32.tf32.tf32.f32 "
        "{%0,%1,%2,%3},{%4,%5,%6,%7},{%8,%9},{%0,%1,%2,%3};"
        : "+f"(c[0]), "+f"(c[1]), "+f"(c[2]), "+f"(c[3])
        : "r"(a[0]), "r"(a[1]), "r"(a[2]), "r"(a[3]), "r"(b0), "r"(b1));
}
__device__ __forceinline__ void ldsm4(uint32_t r[4], uint32_t addr) {
    asm volatile("ldmatrix.sync.aligned.m8n8.x4.shared.b16 {%0,%1,%2,%3}, [%4];"
        : "=r"(r[0]), "=r"(r[1]), "=r"(r[2]), "=r"(r[3]) : "r"(addr));
}
#define CP16(dst, src) asm volatile("cp.async.cg.shared.global [%0], [%1], 16;" :: "r"(dst), "l"(src))
#define CP_COMMIT() asm volatile("cp.async.commit_group;")
#define CP_WAIT2() asm volatile("cp.async.wait_group 2;")
#define CP_WAIT0() asm volatile("cp.async.wait_group 0;")

// ---------------- small kernels ------------------------------------------------
__global__ void cvt_k(const float4* __restrict__ s, float4* __restrict__ d, size_t n4) {
    size_t i = (size_t)blockIdx.x * blockDim.x + threadIdx.x;
    size_t stride = (size_t)gridDim.x * blockDim.x;
    for (; i < n4; i += stride) {
        float4 v = s[i];
        v.x = roundtf(v.x); v.y = roundtf(v.y);
        v.z = roundtf(v.z); v.w = roundtf(v.w);
        d[i] = v;
    }
}

__global__ void embed_k(const int* __restrict__ ids, const float* __restrict__ tok,
                        const float* __restrict__ pos, float* __restrict__ x) {
    int row = blockIdx.x;
    int t = row % TT;
    int id = ids[row];
    const float* te = tok + (size_t)id * DD;
    const float* pe = pos + (size_t)t * DD;
    float* xr = x + (size_t)row * DD;
    for (int i = threadIdx.x; i < DD; i += blockDim.x)
        xr[i] = te[i] + pe[i];
}

// warp-per-row layernorm (768 = 32 lanes x 6 float4)
__global__ __launch_bounds__(256)
void ln_k(const float* __restrict__ x, float* __restrict__ y,
          const float* __restrict__ g, const float* __restrict__ b) {
    int wid = threadIdx.x >> 5, lane = threadIdx.x & 31;
    int row = blockIdx.x * 8 + wid;
    const float* xr = x + (size_t)row * DD;
    float4 vv[6];
    float sum = 0.f, sq = 0.f;
#pragma unroll
    for (int i = 0; i < 6; i++) {
        vv[i] = *(const float4*)(xr + i * 128 + lane * 4);
        sum += vv[i].x + vv[i].y + vv[i].z + vv[i].w;
        sq  += vv[i].x*vv[i].x + vv[i].y*vv[i].y + vv[i].z*vv[i].z + vv[i].w*vv[i].w;
    }
#pragma unroll
    for (int o = 16; o; o >>= 1) {
        sum += __shfl_xor_sync(~0u, sum, o);
        sq  += __shfl_xor_sync(~0u, sq, o);
    }
    float mu = sum * (1.0f / DD);
    float var = sq * (1.0f / DD) - mu * mu;
    float rstd = rsqrtf(var + 1e-5f);
    float* yr = y + (size_t)row * DD;
#pragma unroll
    for (int i = 0; i < 6; i++) {
        int c = i * 128 + lane * 4;
        float4 gg = *(const float4*)(g + c);
        float4 bb = *(const float4*)(b + c);
        float4 o4;
        o4.x = roundtf((vv[i].x - mu) * rstd * gg.x + bb.x);
        o4.y = roundtf((vv[i].y - mu) * rstd * gg.y + bb.y);
        o4.z = roundtf((vv[i].z - mu) * rstd * gg.z + bb.z);
        o4.w = roundtf((vv[i].w - mu) * rstd * gg.w + bb.w);
        *(float4*)(yr + c) = o4;
    }
}

// split-K combine: x += s0 + s1 + bias
__global__ __launch_bounds__(256)
void addsk_k(const float4* __restrict__ s0, const float4* __restrict__ s1,
             const float* __restrict__ bias, float4* __restrict__ x) {
    int idx = blockIdx.x * 256 + threadIdx.x;   // ROWS*DD/4 total
    int col4 = (idx % (DD / 4)) * 4;
    float4 a = s0[idx], b = s1[idx], c = x[idx];
    float4 bi = *(const float4*)(bias + col4);
    c.x += a.x + b.x + bi.x;
    c.y += a.y + b.y + bi.y;
    c.z += a.z + b.z + bi.z;
    c.w += a.w + b.w + bi.w;
    x[idx] = c;
}

// ---------------- tensor-core GEMM (tf32, cp.async 4-stage) --------------------
// flags: 1 bias, 2 relu, 4 accumulate, 8 causal-K, 16 round-store-tf32
#define APITCH 20
#define BPITCH 136
#define AWORDS (128*APITCH)
#define BWORDS (16*BPITCH)
#define STG_WORDS (AWORDS + BWORDS)   // 4736
#define NSTG 4
#define SMEM_BYTES (NSTG*STG_WORDS*4) // 75776
__global__ __launch_bounds__(256, 2)
void gemm_tc(const float* __restrict__ A, const float* __restrict__ Bm,
             float* __restrict__ C,
             int K, int lda, int ldb, int ldc,
             int Nh, size_t hstride,
             const float* __restrict__ bias, int flags,
             int batchH,
             size_t aOuter, size_t aInner,
             size_t bOuter, size_t bInner,
             size_t cOuter, size_t cInner) {
    extern __shared__ __align__(16) uint32_t smem[];
    int z = blockIdx.z;
    int zo = z / batchH, zi = z - zo * batchH;
    A  += zo * aOuter + zi * aInner;
    Bm += zo * bOuter + zi * bInner;
    C  += zo * cOuter + zi * cInner;

    const int tid  = threadIdx.x;
    const int lane = tid & 31;
    const int warp = tid >> 5;
    const int wm = warp >> 2;
    const int wn = warp & 3;
    const int m0 = blockIdx.y * 128;
    const int n0 = blockIdx.x * 128;

    int Kc = K;
    if (flags & 8) { int ke = (blockIdx.y + 1) * 128; if (ke < Kc) Kc = ke; }
    const int steps = Kc >> 4;

    const int ar = tid >> 2;
    const int ac = (tid & 3) << 2;
    const int brr = tid >> 5;
    const int bcc = (tid & 31) << 2;
    const float* aP = A + (size_t)(m0 + ar) * lda + ac;
    const int gcol = n0 + bcc;
    const float* bP = Bm + (size_t)(gcol / Nh) * hstride + (size_t)(gcol % Nh);

    const uint32_t smemBase = (uint32_t)__cvta_generic_to_shared(smem);
    const uint32_t aDst0 = smemBase + (uint32_t)((ar * APITCH + ac) * 4);
    const uint32_t aDst1 = smemBase + (uint32_t)(((ar + 64) * APITCH + ac) * 4);
    const uint32_t bDst0 = smemBase + (uint32_t)((AWORDS + brr * BPITCH + bcc) * 4);
    const uint32_t bDst1 = smemBase + (uint32_t)((AWORDS + (brr + 8) * BPITCH + bcc) * 4);

    float acc[4][4][4];
#pragma unroll
    for (int mt = 0; mt < 4; mt++)
#pragma unroll
        for (int nt = 0; nt < 4; nt++)
#pragma unroll
            for (int i = 0; i < 4; i++) acc[mt][nt][i] = 0.f;

    const int aRowF = wm * 64 + (lane & 7) + ((lane >> 3) & 1) * 8;
    const int aColF = ((lane >> 4) & 1) * 4;
    const uint32_t aFragBase = smemBase + (uint32_t)((aRowF * APITCH + aColF) * 4);
    const int bRowF = lane & 3;
    const int bColF = wn * 32 + (lane >> 2);

#pragma unroll
    for (int pt = 0; pt < NSTG - 1; pt++) {
        if (pt < steps) {
            const uint32_t so = (uint32_t)(pt * STG_WORDS * 4);
            const int k0 = pt << 4;
            CP16(aDst0 + so, aP + k0);
            CP16(aDst1 + so, aP + (size_t)64 * lda + k0);
            CP16(bDst0 + so, bP + (size_t)(k0 + brr) * ldb);
            CP16(bDst1 + so, bP + (size_t)(k0 + brr + 8) * ldb);
        }
        CP_COMMIT();
    }

    int stg = 0;
    for (int s = 0; s < steps; s++) {
        CP_WAIT2();
        __syncthreads();

        {
            const int nt_ = s + NSTG - 1;
            if (nt_ < steps) {
                int ns = stg + NSTG - 1; if (ns >= NSTG) ns -= NSTG;
                const uint32_t so = (uint32_t)(ns * STG_WORDS * 4);
                const int k0 = nt_ << 4;
                CP16(aDst0 + so, aP + k0);
                CP16(aDst1 + so, aP + (size_t)64 * lda + k0);
                CP16(bDst0 + so, bP + (size_t)(k0 + brr) * ldb);
                CP16(bDst1 + so, bP + (size_t)(k0 + brr + 8) * ldb);
            }
            CP_COMMIT();
        }

        const uint32_t aSt = aFragBase + (uint32_t)(stg * STG_WORDS * 4);
        const uint32_t* bBase = smem + stg * STG_WORDS + AWORDS;
#pragma unroll
        for (int ks = 0; ks < 2; ks++) {
            uint32_t af[4][4];
#pragma unroll
            for (int mt = 0; mt < 4; mt++)
                ldsm4(af[mt], aSt + (uint32_t)((mt * 16 * APITCH + ks * 8) * 4));
            const uint32_t* b0p = bBase + (ks * 8 + bRowF) * BPITCH + bColF;
            const uint32_t* b1p = b0p + 4 * BPITCH;
#pragma unroll
            for (int nt = 0; nt < 4; nt++) {
                uint32_t b0 = b0p[nt * 8];
                uint32_t b1 = b1p[nt * 8];
#pragma unroll
                for (int mt = 0; mt < 4; mt++)
                    mma_tf32(acc[mt][nt], af[mt], b0, b1);
            }
        }
        stg++; if (stg >= NSTG) stg = 0;
    }

#pragma unroll
    for (int mt = 0; mt < 4; mt++) {
        const int row = m0 + wm * 64 + mt * 16 + (lane >> 2);
#pragma unroll
        for (int nt = 0; nt < 4; nt++) {
            const int col = n0 + wn * 32 + nt * 8 + (lane & 3) * 2;
            float2 bi = make_float2(0.f, 0.f);
            if (flags & 1) bi = *(const float2*)(bias + col);
            float2 v0 = make_float2(acc[mt][nt][0] + bi.x, acc[mt][nt][1] + bi.y);
            float2 v1 = make_float2(acc[mt][nt][2] + bi.x, acc[mt][nt][3] + bi.y);
            if (flags & 2) {
                v0.x = fmaxf(v0.x, 0.f); v0.y = fmaxf(v0.y, 0.f);
                v1.x = fmaxf(v1.x, 0.f); v1.y = fmaxf(v1.y, 0.f);
            }
            float* c0 = C + (size_t)row * ldc + col;
            float* c1 = C + (size_t)(row + 8) * ldc + col;
            if (flags & 4) {
                float2 o0 = *(float2*)c0, o1 = *(float2*)c1;
                v0.x += o0.x; v0.y += o0.y; v1.x += o1.x; v1.y += o1.y;
            }
            if (flags & 16) {
                v0.x = roundtf(v0.x); v0.y = roundtf(v0.y);
                v1.x = roundtf(v1.x); v1.y = roundtf(v1.y);
            }
            *(float2*)c0 = v0;
            *(float2*)c1 = v1;
        }
    }
}

// ---------------- attention scores on tensor cores ------------------------------
#define SPITCH 68
#define S_AWORDS (128*SPITCH)
#define SCORE_SMEM (2*S_AWORDS*4)   // 69632 bytes
__global__ __launch_bounds__(256, 2)
void score_tc(const float* __restrict__ q, const float* __restrict__ k,
              float* __restrict__ p) {
    extern __shared__ __align__(16) uint32_t ss[];
    const int z = blockIdx.z;
    const int b = z / HH, h = z - b * HH;
    const int m0 = blockIdx.y * 128;
    const int n0 = blockIdx.x * 128;
    if (n0 > m0 + 127) return;

    const int tid  = threadIdx.x;
    const int lane = tid & 31;
    const int warp = tid >> 5;
    const int wm = warp >> 2;
    const int wn = warp & 3;

    const float* qb = q + ((size_t)(b * TT + m0)) * DD + h * KH;
    const float* kb = k + ((size_t)(b * TT + n0)) * DD + h * KH;

    const uint32_t base = (uint32_t)__cvta_generic_to_shared(ss);
#pragma unroll
    for (int i = 0; i < 8; i++) {
        int lin = tid + i * 256;
        int row = lin >> 4;
        int col = (lin & 15) << 2;
        CP16(base + (uint32_t)((row * SPITCH + col) * 4), qb + (size_t)row * DD + col);
        CP16(base + (uint32_t)((S_AWORDS + row * SPITCH + col) * 4), kb + (size_t)row * DD + col);
    }
    CP_COMMIT();
    CP_WAIT0();
    __syncthreads();

    float acc[4][4][4];
#pragma unroll
    for (int mt = 0; mt < 4; mt++)
#pragma unroll
        for (int nt = 0; nt < 4; nt++)
#pragma unroll
            for (int i = 0; i < 4; i++) acc[mt][nt][i] = 0.f;

    const uint32_t aFragBase = base +
        (uint32_t)(((wm * 64 + (lane & 7) + ((lane >> 3) & 1) * 8) * SPITCH +
                    ((lane >> 4) & 1) * 4) * 4);
    const uint32_t* Ks = ss + S_AWORDS;
    const int bN = wn * 32 + (lane >> 2);
    const int bK = lane & 3;

#pragma unroll
    for (int ks = 0; ks < 8; ks++) {
        uint32_t af[4][4];
#pragma unroll
        for (int mt = 0; mt < 4; mt++)
            ldsm4(af[mt], aFragBase + (uint32_t)((mt * 16 * SPITCH + ks * 8) * 4));
#pragma unroll
        for (int nt = 0; nt < 4; nt++) {
            uint32_t b0 = Ks[(bN + nt * 8) * SPITCH + ks * 8 + bK];
            uint32_t b1 = Ks[(bN + nt * 8) * SPITCH + ks * 8 + 4 + bK];
#pragma unroll
            for (int mt = 0; mt < 4; mt++)
                mma_tf32(acc[mt][nt], af[mt], b0, b1);
        }
    }

    float* pz = p + (size_t)z * TT * TT;
#pragma unroll
    for (int mt = 0; mt < 4; mt++) {
        const int row = m0 + wm * 64 + mt * 16 + (lane >> 2);
#pragma unroll
        for (int nt = 0; nt < 4; nt++) {
            const int col = n0 + wn * 32 + nt * 8 + (lane & 3) * 2;
            float2 v0 = make_float2(acc[mt][nt][0] * 0.125f, acc[mt][nt][1] * 0.125f);
            float2 v1 = make_float2(acc[mt][nt][2] * 0.125f, acc[mt][nt][3] * 0.125f);
            *(float2*)(pz + (size_t)row * TT + col) = v0;
            *(float2*)(pz + (size_t)(row + 8) * TT + col) = v1;
        }
    }
}

// ---------------- causal softmax: one warp per row, no block barriers -----------
__global__ __launch_bounds__(256)
void attn_sm(float* __restrict__ p) {
    const int wid = threadIdx.x >> 5, lane = threadIdx.x & 31;
    const int t = blockIdx.x * 8 + wid;
    const int h = blockIdx.y, b = blockIdx.z;
    float* row = p + ((size_t)((b * HH + h) * TT + t)) * TT;
    const int valid = t + 1;
    const int nj = (t >> 7) + 1;   // 128-col groups to process

    float4 v[8];
    float m = -INFINITY;
#pragma unroll
    for (int j = 0; j < 8; j++) {
        if (j < nj) {
            int c0 = j * 128 + lane * 4;
            float4 val = *(const float4*)(row + c0);
            val.x = (c0 + 0 < valid) ? val.x : -INFINITY;
            val.y = (c0 + 1 < valid) ? val.y : -INFINITY;
            val.z = (c0 + 2 < valid) ? val.z : -INFINITY;
            val.w = (c0 + 3 < valid) ? val.w : -INFINITY;
            v[j] = val;
            m = fmaxf(m, fmaxf(fmaxf(val.x, val.y), fmaxf(val.z, val.w)));
        }
    }
#pragma unroll
    for (int o = 16; o; o >>= 1) m = fmaxf(m, __shfl_xor_sync(~0u, m, o));

    float sum = 0.f;
#pragma unroll
    for (int j = 0; j < 8; j++) {
        if (j < nj) {
            float2 e0 = exp2_pair((v[j].x - m) * L2E, (v[j].y - m) * L2E);
            float2 e1 = exp2_pair((v[j].z - m) * L2E, (v[j].w - m) * L2E);
            v[j] = make_float4(e0.x, e0.y, e1.x, e1.y);
            sum += e0.x + e0.y + e1.x + e1.y;
        }
    }
#pragma unroll
    for (int o = 16; o; o >>= 1) sum += __shfl_xor_sync(~0u, sum, o);
    float inv = 1.f / sum;
#pragma unroll
    for (int j = 0; j < 8; j++) {
        if (j < nj) {
            int c0 = j * 128 + lane * 4;
            float4 val = v[j];
            val.x = roundtf(val.x * inv);
            val.y = roundtf(val.y * inv);
            val.z = roundtf(val.z * inv);
            val.w = roundtf(val.w * inv);
            *(float4*)(row + c0) = val;
        }
    }
}

// ---------------- loss ----------------------------------------------------------
__global__ void loss_row_k(const float* __restrict__ logits, const int* __restrict__ tgt,
                           float* __restrict__ rl) {
    int row = blockIdx.x, tid = threadIdx.x;
    const float* lr = logits + (size_t)row * VV;
    __shared__ float red[256];
    float m = -INFINITY;
    for (int i = tid * 2; i < VV; i += 512) {
        float2 v = *(const float2*)(lr + i);
        m = fmaxf(m, fmaxf(v.x, v.y));
    }
    red[tid] = m; __syncthreads();
    for (int s = 128; s > 0; s >>= 1) { if (tid < s) red[tid] = fmaxf(red[tid], red[tid + s]); __syncthreads(); }
    m = red[0]; __syncthreads();
    float sum = 0.f;
    for (int i = tid * 2; i < VV; i += 512) {
        float2 v = *(const float2*)(lr + i);
        float2 e = exp2_pair((v.x - m) * L2E, (v.y - m) * L2E);
        sum += e.x + e.y;
    }
    red[tid] = sum; __syncthreads();
    for (int s = 128; s > 0; s >>= 1) { if (tid < s) red[tid] += red[tid + s]; __syncthreads(); }
    if (tid == 0) {
        float lse = m + logf(red[0]);
        rl[row] = lse - lr[tgt[row]];
    }
}

__global__ void loss_final_k(const float* __restrict__ rl, float* __restrict__ out) {
    __shared__ float red[256];
    int tid = threadIdx.x;
    float s = 0.f;
    for (int i = tid; i < ROWS; i += 256) s += rl[i];
    red[tid] = s; __syncthreads();
    for (int k = 128; k > 0; k >>= 1) { if (tid < k) red[tid] += red[tid + k]; __syncthreads(); }
    if (tid == 0) out[0] = red[0] * (1.0f / ROWS);
}

__global__ void fill0_k(float* p, size_t n) {
    size_t i = (size_t)blockIdx.x * blockDim.x + threadIdx.x;
    if (i < n) p[i] = 0.f;
}

// ---------------- host-side launcher -------------------------------------------
static inline void gemm(const float* A, const float* B, float* C,
                        int M, int N, int K, int lda, int ldb, int ldc,
                        int Nh, size_t hs, const float* bias, int flags,
                        int batch = 1, int batchH = 1,
                        size_t aO = 0, size_t aI = 0,
                        size_t bO = 0, size_t bI = 0,
                        size_t cO = 0, size_t cI = 0) {
    dim3 grid(N / 128, M / 128, batch);
    gemm_tc<<<grid, 256, SMEM_BYTES>>>(A, B, C, K, lda, ldb, ldc, Nh, hs, bias, flags,
                                       batchH, aO, aI, bO, bI, cO, cI);
}

extern "C" void kernel_launch(void* const* d_in, const int* in_sizes, int n_in,
                              void* d_out, int out_size) {
    const int*   ids   = (const int*)d_in[0];
    const int*   tgt   = (const int*)d_in[1];
    const float* tok   = (const float*)d_in[2];
    const float* pos   = (const float*)d_in[3];
    const float* Wq_i  = (const float*)d_in[4];
    const float* Wk_i  = (const float*)d_in[5];
    const float* Wv_i  = (const float*)d_in[6];
    const float* Wp_i  = (const float*)d_in[7];
    const float* bproj = (const float*)d_in[8];
    const float* ln1g  = (const float*)d_in[9];
    const float* ln1b  = (const float*)d_in[10];
    const float* ln2g  = (const float*)d_in[11];
    const float* ln2b  = (const float*)d_in[12];
    const float* W1_i  = (const float*)d_in[13];
    const float* b1    = (const float*)d_in[14];
    const float* W2_i  = (const float*)d_in[15];
    const float* b2    = (const float*)d_in[16];
    const float* lnfg  = (const float*)d_in[17];
    const float* lnfb  = (const float*)d_in[18];
    const float* Wh_i  = (const float*)d_in[19];
    const float* bhead = (const float*)d_in[20];

    float *x, *h, *qk, *v, *o, *p, *f, *sk, *rl, *wc;
    cudaGetSymbolAddress((void**)&x, g_x);
    cudaGetSymbolAddress((void**)&h, g_h);
    cudaGetSymbolAddress((void**)&qk, g_qk);
    cudaGetSymbolAddress((void**)&v, g_v);
    cudaGetSymbolAddress((void**)&o, g_o);
    cudaGetSymbolAddress((void**)&p, g_p);
    cudaGetSymbolAddress((void**)&f, g_f);
    cudaGetSymbolAddress((void**)&sk, g_sk);
    cudaGetSymbolAddress((void**)&rl, g_rl);
    cudaGetSymbolAddress((void**)&wc, g_wc);

    static bool attrSet = false;
    if (!attrSet) {
        cudaFuncSetAttribute(gemm_tc, cudaFuncAttributeMaxDynamicSharedMemorySize, SMEM_BYTES);
        cudaFuncSetAttribute(score_tc, cudaFuncAttributeMaxDynamicSharedMemorySize, SCORE_SMEM);
        attrSet = true;
    }

    float* Wq = wc + O_WQ;  float* Wk = wc + O_WK;  float* Wv = wc + O_WV;
    float* Wp = wc + O_WP;  float* W1 = wc + O_W1;  float* W2 = wc + O_W2;
    float* Wh = wc + O_WH;
    float* q = qk;
    float* k = qk + (size_t)ROWS * DD;

    float* out = (float*)d_out;
    const size_t NL = (size_t)ROWS * VV;

    // launch order arranged so ncu (-s 5) profiles the first big GEMM
    embed_k<<<ROWS, 256>>>(ids, tok, pos, x);                                   // 0
    cvt_k<<<1024, 256>>>((const float4*)Wq_i, (float4*)Wq, (size_t)WQ_SZ / 4);  // 1
    cvt_k<<<1024, 256>>>((const float4*)Wk_i, (float4*)Wk, (size_t)WQ_SZ / 4);  // 2
    ln_k<<<ROWS / 8, 256>>>(x, h, ln1g, ln1b);                                  // 3
    cvt_k<<<2048, 256>>>((const float4*)Wv_i, (float4*)Wv, (size_t)WV_SZ / 4);  // 4
    // 5: merged q/k projection for layer 0 (PROFILED LAUNCH)
    gemm(h, Wq, q, ROWS, DD, DD, DD, KH, DD, KH, (size_t)DD * KH, nullptr, 0,
         2, 1, 0, 0, (size_t)WQ_SZ, 0, (size_t)ROWS * DD, 0);
    cvt_k<<<2048, 256>>>((const float4*)Wp_i, (float4*)Wp, (size_t)WP_SZ / 4);
    cvt_k<<<1024, 256>>>((const float4*)W1_i, (float4*)W1, (size_t)W1_SZ / 4);
    cvt_k<<<1024, 256>>>((const float4*)W2_i, (float4*)W2, (size_t)W1_SZ / 4);
    cvt_k<<<2048, 256>>>((const float4*)Wh_i, (float4*)Wh, (size_t)WH_SZ / 4);

    for (int l = 0; l < LL; l++) {
        if (l > 0) {
            ln_k<<<ROWS / 8, 256>>>(x, h, ln1g + l * DD, ln1b + l * DD);
            gemm(h, Wq + (size_t)l * HH * DD * KH, q, ROWS, DD, DD, DD, KH, DD,
                 KH, (size_t)DD * KH, nullptr, 0,
                 2, 1, 0, 0, (size_t)WQ_SZ, 0, (size_t)ROWS * DD, 0);
        }
        gemm(h, Wv + (size_t)l * HH * DD * DD, v, ROWS, HD, DD, DD, DD, HD,
             DD, (size_t)DD * DD, nullptr, 16);
        {
            dim3 grid(TT / 128, TT / 128, BSZ * HH);
            score_tc<<<grid, 256, SCORE_SMEM>>>(q, k, p);
            dim3 grid2(TT / 8, HH, BSZ);
            attn_sm<<<grid2, 256>>>(p);
        }
        gemm(p, v, o, TT, DD, TT, TT, HD, HD, DD, 0, nullptr, 8 | 16,
             BSZ * HH, HH,
             (size_t)HH * TT * TT, (size_t)TT * TT,
             (size_t)TT * HD, (size_t)DD,
             (size_t)TT * HD, (size_t)DD);
        // proj: split-K x2 into sk, then combine (x += sk0 + sk1 + bproj)
        gemm(o, Wp + (size_t)l * HD * DD, sk, ROWS, DD, HD / 2, HD, DD, DD,
             DD, 0, nullptr, 0,
             2, 1, (size_t)(HD / 2), 0, (size_t)(HD / 2) * DD, 0, (size_t)ROWS * DD, 0);
        addsk_k<<<ROWS * DD / 1024, 256>>>((const float4*)sk,
                                           (const float4*)(sk + (size_t)ROWS * DD),
                                           bproj + l * DD, (float4*)x);
        ln_k<<<ROWS / 8, 256>>>(x, h, ln2g + l * DD, ln2b + l * DD);
        gemm(h, W1 + (size_t)l * DD * FF, f, ROWS, FF, DD, DD, FF, FF,
             FF, 0, b1 + l * FF, 1 | 2 | 16);
        // W2: split-K x2 into sk, then combine (x += sk0 + sk1 + b2)
        gemm(f, W2 + (size_t)l * FF * DD, sk, ROWS, DD, FF / 2, FF, DD, DD,
             DD, 0, nullptr, 0,
             2, 1, (size_t)(FF / 2), 0, (size_t)(FF / 2) * DD, 0, (size_t)ROWS * DD, 0);
        addsk_k<<<ROWS * DD / 1024, 256>>>((const float4*)sk,
                                           (const float4*)(sk + (size_t)ROWS * DD),
                                           b2 + l * DD, (float4*)x);
    }

    ln_k<<<ROWS / 8, 256>>>(x, h, lnfg, lnfb);

    gemm(h, Wh, out, ROWS, VV, DD, DD, VV, VV, VV, 0, bhead, 1);
    loss_row_k<<<ROWS, 256>>>(out, tgt, rl);
    if ((size_t)out_size >= NL + 1) {
        loss_final_k<<<1, 256>>>(rl, out + NL);
        size_t tail = (size_t)out_size - (NL + 1);
        if (tail > 0)
            fill0_k<<<(int)((tail + 255) / 256), 256>>>(out + NL + 1, tail);
    }
}

// round 10
// speedup vs baseline: 13.8608x; 1.8401x over previous
#include <cuda_runtime.h>
#include <math.h>
#include <stdint.h>
#include <cuda_fp16.h>

// Problem constants
#define BSZ 4
#define TT 1024
#define DD 768
#define HH 12
#define KH 64
#define LL 6
#define VV 32000
#define FF 3072
#define HD 9216
#define ROWS (BSZ*TT)  // 4096
#define L2E 1.44269504088896340736f

// ---------------- scratch ------------------------------------------------------
__device__ float  g_x[(size_t)ROWS*DD];          // residual (fp32)
__device__ __half g_h[(size_t)ROWS*DD];          // ln output
__device__ __half g_qk[(size_t)2*ROWS*DD];       // q then k
__device__ __half g_v[(size_t)ROWS*HD];
__device__ __half g_o[(size_t)ROWS*HD];
__device__ __half g_p[(size_t)BSZ*HH*TT*TT];     // scores/probs
__device__ __half g_f[(size_t)ROWS*FF];
__device__ float  g_sk[(size_t)2*ROWS*DD];       // split-K fp32 partials
__device__ float  g_rl[ROWS];

// half weight cache
#define WQ_SZ  3538944
#define WV_SZ  42467328
#define WP_SZ  42467328
#define W1_SZ  14155776
#define WH_SZ  24576000
#define O_WQ   0
#define O_WK   (O_WQ + WQ_SZ)
#define O_WV   (O_WK + WQ_SZ)
#define O_WP   (O_WV + WV_SZ)
#define O_W1   (O_WP + WP_SZ)
#define O_W2   (O_W1 + W1_SZ)
#define O_WH   (O_W2 + W1_SZ)
#define WC_TOTAL (O_WH + WH_SZ)
__device__ __half g_wc[(size_t)WC_TOTAL];

// ---------------- helpers ------------------------------------------------------
__device__ __forceinline__ float2 exp2_pair(float a, float b) {
    __half2 p = __floats2half2_rn(a, b);
    __half2 e = h2exp2(p);
    return __half22float2(e);
}

__device__ __forceinline__ void mma_f16(float c[4], const uint32_t a[4], uint32_t b0, uint32_t b1) {
    asm volatile(
        "mma.sync.aligned.m16n8k16.row.col.f32.f16.f16.f32 "
        "{%0,%1,%2,%3},{%4,%5,%6,%7},{%8,%9},{%0,%1,%2,%3};"
        : "+f"(c[0]), "+f"(c[1]), "+f"(c[2]), "+f"(c[3])
        : "r"(a[0]), "r"(a[1]), "r"(a[2]), "r"(a[3]), "r"(b0), "r"(b1));
}
__device__ __forceinline__ void ldsm4(uint32_t r[4], uint32_t addr) {
    asm volatile("ldmatrix.sync.aligned.m8n8.x4.shared.b16 {%0,%1,%2,%3}, [%4];"
        : "=r"(r[0]), "=r"(r[1]), "=r"(r[2]), "=r"(r[3]) : "r"(addr));
}
__device__ __forceinline__ void ldsm4t(uint32_t r[4], uint32_t addr) {
    asm volatile("ldmatrix.sync.aligned.m8n8.x4.trans.shared.b16 {%0,%1,%2,%3}, [%4];"
        : "=r"(r[0]), "=r"(r[1]), "=r"(r[2]), "=r"(r[3]) : "r"(addr));
}
#define CP16(dst, src) asm volatile("cp.async.cg.shared.global [%0], [%1], 16;" :: "r"(dst), "l"(src))
#define CP_COMMIT() asm volatile("cp.async.commit_group;")
#define CP_WAIT2() asm volatile("cp.async.wait_group 2;")
#define CP_WAIT0() asm volatile("cp.async.wait_group 0;")

// ---------------- small kernels ------------------------------------------------
// fp32 -> fp16 weight conversion (float4 in, 4 halves out)
__global__ void cvt_k(const float4* __restrict__ s, uint2* __restrict__ d, size_t n4) {
    size_t i = (size_t)blockIdx.x * blockDim.x + threadIdx.x;
    size_t stride = (size_t)gridDim.x * blockDim.x;
    for (; i < n4; i += stride) {
        float4 v = s[i];
        __half2 h0 = __floats2half2_rn(v.x, v.y);
        __half2 h1 = __floats2half2_rn(v.z, v.w);
        uint2 o;
        o.x = *(uint32_t*)&h0;
        o.y = *(uint32_t*)&h1;
        d[i] = o;
    }
}

__global__ void embed_k(const int* __restrict__ ids, const float* __restrict__ tok,
                        const float* __restrict__ pos, float* __restrict__ x) {
    int row = blockIdx.x;
    int t = row % TT;
    int id = ids[row];
    const float* te = tok + (size_t)id * DD;
    const float* pe = pos + (size_t)t * DD;
    float* xr = x + (size_t)row * DD;
    for (int i = threadIdx.x; i < DD; i += blockDim.x)
        xr[i] = te[i] + pe[i];
}

// warp-per-row layernorm; fp32 in, half out
__global__ __launch_bounds__(256)
void ln_k(const float* __restrict__ x, __half* __restrict__ y,
          const float* __restrict__ g, const float* __restrict__ b) {
    int wid = threadIdx.x >> 5, lane = threadIdx.x & 31;
    int row = blockIdx.x * 8 + wid;
    const float* xr = x + (size_t)row * DD;
    float4 vv[6];
    float sum = 0.f, sq = 0.f;
#pragma unroll
    for (int i = 0; i < 6; i++) {
        vv[i] = *(const float4*)(xr + i * 128 + lane * 4);
        sum += vv[i].x + vv[i].y + vv[i].z + vv[i].w;
        sq  += vv[i].x*vv[i].x + vv[i].y*vv[i].y + vv[i].z*vv[i].z + vv[i].w*vv[i].w;
    }
#pragma unroll
    for (int o = 16; o; o >>= 1) {
        sum += __shfl_xor_sync(~0u, sum, o);
        sq  += __shfl_xor_sync(~0u, sq, o);
    }
    float mu = sum * (1.0f / DD);
    float var = sq * (1.0f / DD) - mu * mu;
    float rstd = rsqrtf(var + 1e-5f);
    __half* yr = y + (size_t)row * DD;
#pragma unroll
    for (int i = 0; i < 6; i++) {
        int c = i * 128 + lane * 4;
        float4 gg = *(const float4*)(g + c);
        float4 bb = *(const float4*)(b + c);
        __half2 h0 = __floats2half2_rn((vv[i].x - mu) * rstd * gg.x + bb.x,
                                       (vv[i].y - mu) * rstd * gg.y + bb.y);
        __half2 h1 = __floats2half2_rn((vv[i].z - mu) * rstd * gg.z + bb.z,
                                       (vv[i].w - mu) * rstd * gg.w + bb.w);
        uint2 o;
        o.x = *(uint32_t*)&h0; o.y = *(uint32_t*)&h1;
        *(uint2*)(yr + c) = o;
    }
}

// split-K combine: x += s0 + s1 + bias
__global__ __launch_bounds__(256)
void addsk_k(const float4* __restrict__ s0, const float4* __restrict__ s1,
             const float* __restrict__ bias, float4* __restrict__ x) {
    int idx = blockIdx.x * 256 + threadIdx.x;
    int col4 = (idx % (DD / 4)) * 4;
    float4 a = s0[idx], b = s1[idx], c = x[idx];
    float4 bi = *(const float4*)(bias + col4);
    c.x += a.x + b.x + bi.x;
    c.y += a.y + b.y + bi.y;
    c.z += a.z + b.z + bi.z;
    c.w += a.w + b.w + bi.w;
    x[idx] = c;
}

// ---------------- fp16 tensor-core GEMM (cp.async 4-stage, BK=32) --------------
// C[M,N] (+)= A[M,K]*B[K,N]; B head-blocked: (k,j) at B + (j/Nh)*hstride + k*ldb + j%Nh
// flags: 1 bias, 2 relu, 4 accumulate(fp32 C), 8 causal-K, 32 store-half
#define AP 40                     // halves per A smem row
#define ABYTES (128*AP*2)         // 10240
#define BP 136                    // halves per B smem row
#define BBYTES (32*BP*2)          // 8704
#define STGB (ABYTES+BBYTES)      // 18944
#define NSTG 4
#define GSMEM (NSTG*STGB)         // 75776
__global__ __launch_bounds__(256, 2)
void gemm_hc(const __half* __restrict__ A, const __half* __restrict__ Bm,
             void* __restrict__ Cv,
             int K, int lda, int ldb, int ldc,
             int Nh, size_t hstride,
             const float* __restrict__ bias, int flags,
             int batchH,
             size_t aOuter, size_t aInner,
             size_t bOuter, size_t bInner,
             size_t cOuter, size_t cInner) {
    extern __shared__ __align__(16) char smem[];
    int z = blockIdx.z;
    int zo = z / batchH, zi = z - zo * batchH;
    A  += zo * aOuter + zi * aInner;
    Bm += zo * bOuter + zi * bInner;
    const size_t cOff = (size_t)zo * cOuter + (size_t)zi * cInner;

    const int tid  = threadIdx.x;
    const int lane = tid & 31;
    const int warp = tid >> 5;
    const int wm = warp >> 2;       // 0..1
    const int wn = warp & 3;        // 0..3
    const int m0 = blockIdx.y * 128;
    const int n0 = blockIdx.x * 128;

    int Kc = K;
    if (flags & 8) { int ke = (blockIdx.y + 1) * 128; if (ke < Kc) Kc = ke; }
    const int steps = Kc >> 5;      // BK = 32

    // loaders: A 128x32 halves (2 chunks/thread), B 32x128 halves (2 chunks/thread)
    const int ar0 = tid >> 2,  ac8 = (tid & 3);          // chunk i=0: rows 0..63? no: c=tid -> row=tid>>2 (0..63), i=1: +64
    const int br0 = tid >> 4,  bc8 = (tid & 15);         // i=0 rows 0..15, i=1 +16
    const __half* aP0 = A + (size_t)(m0 + ar0) * lda + ac8 * 8;
    const __half* aP1 = A + (size_t)(m0 + ar0 + 64) * lda + ac8 * 8;
    const int gcol = n0 + bc8 * 8;
    const __half* bPB = Bm + (size_t)(gcol / Nh) * hstride + (size_t)(gcol % Nh);

    const uint32_t base = (uint32_t)__cvta_generic_to_shared(smem);
    const uint32_t aD0 = base + (uint32_t)(ar0 * 80 + ac8 * 16);
    const uint32_t aD1 = aD0 + 64 * 80;
    const uint32_t bD0 = base + (uint32_t)(ABYTES + br0 * 272 + bc8 * 16);
    const uint32_t bD1 = bD0 + 16 * 272;

    float acc[4][4][4];
#pragma unroll
    for (int mt = 0; mt < 4; mt++)
#pragma unroll
        for (int nt = 0; nt < 4; nt++)
#pragma unroll
            for (int i = 0; i < 4; i++) acc[mt][nt][i] = 0.f;

    // A fragment base: rows (lane&15), k-col (lane>>4)*8
    const uint32_t aF = base + (uint32_t)(((wm * 64 + (lane & 15)) * AP + (lane >> 4) * 8) * 2);
    // B fragment (trans): krow = (lane&7) + ((lane>>3)&1)*8, ncol = wn*32 + (lane>>4)*8
    const uint32_t bF = base + (uint32_t)(ABYTES +
        (((lane & 7) + ((lane >> 3) & 1) * 8) * BP + wn * 32 + (lane >> 4) * 8) * 2);

#pragma unroll
    for (int pt = 0; pt < NSTG - 1; pt++) {
        if (pt < steps) {
            const uint32_t so = (uint32_t)(pt * STGB);
            const int k0 = pt << 5;
            CP16(aD0 + so, aP0 + k0);
            CP16(aD1 + so, aP1 + k0);
            CP16(bD0 + so, bPB + (size_t)(k0 + br0) * ldb);
            CP16(bD1 + so, bPB + (size_t)(k0 + br0 + 16) * ldb);
        }
        CP_COMMIT();
    }

    int stg = 0;
    for (int s = 0; s < steps; s++) {
        CP_WAIT2();
        __syncthreads();

        {
            const int nt_ = s + NSTG - 1;
            if (nt_ < steps) {
                int ns = stg + NSTG - 1; if (ns >= NSTG) ns -= NSTG;
                const uint32_t so = (uint32_t)(ns * STGB);
                const int k0 = nt_ << 5;
                CP16(aD0 + so, aP0 + k0);
                CP16(aD1 + so, aP1 + k0);
                CP16(bD0 + so, bPB + (size_t)(k0 + br0) * ldb);
                CP16(bD1 + so, bPB + (size_t)(k0 + br0 + 16) * ldb);
            }
            CP_COMMIT();
        }

        const uint32_t aS = aF + (uint32_t)(stg * STGB);
        const uint32_t bS = bF + (uint32_t)(stg * STGB);
#pragma unroll
        for (int ks = 0; ks < 2; ks++) {
            uint32_t af[4][4];
#pragma unroll
            for (int mt = 0; mt < 4; mt++)
                ldsm4(af[mt], aS + (uint32_t)(mt * 16 * AP * 2 + ks * 32));
            uint32_t bf[2][4];
            ldsm4t(bf[0], bS + (uint32_t)(ks * 16 * BP * 2));
            ldsm4t(bf[1], bS + (uint32_t)(ks * 16 * BP * 2 + 32));
#pragma unroll
            for (int nt = 0; nt < 4; nt++) {
                uint32_t b0 = bf[nt >> 1][(nt & 1) * 2];
                uint32_t b1 = bf[nt >> 1][(nt & 1) * 2 + 1];
#pragma unroll
                for (int mt = 0; mt < 4; mt++)
                    mma_f16(acc[mt][nt], af[mt], b0, b1);
            }
        }
        stg++; if (stg >= NSTG) stg = 0;
    }

    // epilogue
#pragma unroll
    for (int mt = 0; mt < 4; mt++) {
        const int row = m0 + wm * 64 + mt * 16 + (lane >> 2);
#pragma unroll
        for (int nt = 0; nt < 4; nt++) {
            const int col = n0 + wn * 32 + nt * 8 + (lane & 3) * 2;
            float2 bi = make_float2(0.f, 0.f);
            if (flags & 1) bi = *(const float2*)(bias + col);
            float2 v0 = make_float2(acc[mt][nt][0] + bi.x, acc[mt][nt][1] + bi.y);
            float2 v1 = make_float2(acc[mt][nt][2] + bi.x, acc[mt][nt][3] + bi.y);
            if (flags & 2) {
                v0.x = fmaxf(v0.x, 0.f); v0.y = fmaxf(v0.y, 0.f);
                v1.x = fmaxf(v1.x, 0.f); v1.y = fmaxf(v1.y, 0.f);
            }
            if (flags & 32) {
                __half* Ch = (__half*)Cv + cOff;
                __half2 h0 = __floats2half2_rn(v0.x, v0.y);
                __half2 h1 = __floats2half2_rn(v1.x, v1.y);
                *(__half2*)(Ch + (size_t)row * ldc + col) = h0;
                *(__half2*)(Ch + (size_t)(row + 8) * ldc + col) = h1;
            } else {
                float* Cf = (float*)Cv + cOff;
                float* c0 = Cf + (size_t)row * ldc + col;
                float* c1 = Cf + (size_t)(row + 8) * ldc + col;
                if (flags & 4) {
                    float2 o0 = *(float2*)c0, o1 = *(float2*)c1;
                    v0.x += o0.x; v0.y += o0.y; v1.x += o1.x; v1.y += o1.y;
                }
                *(float2*)c0 = v0;
                *(float2*)c1 = v1;
            }
        }
    }
}

// ---------------- attention scores (fp16 tensor cores) --------------------------
#define QP 72
#define QBYTES (128*QP*2)      // 18432
#define SSMEM (2*QBYTES)       // 36864
__global__ __launch_bounds__(256, 2)
void score_tc(const __half* __restrict__ q, const __half* __restrict__ k,
              __half* __restrict__ p) {
    extern __shared__ __align__(16) char ss[];
    const int z = blockIdx.z;
    const int b = z / HH, h = z - b * HH;
    const int m0 = blockIdx.y * 128;
    const int n0 = blockIdx.x * 128;
    if (n0 > m0 + 127) return;

    const int tid  = threadIdx.x;
    const int lane = tid & 31;
    const int warp = tid >> 5;
    const int wm = warp >> 2;
    const int wn = warp & 3;

    const __half* qb = q + ((size_t)(b * TT + m0)) * DD + h * KH;
    const __half* kb = k + ((size_t)(b * TT + n0)) * DD + h * KH;

    const uint32_t base = (uint32_t)__cvta_generic_to_shared(ss);
    // 128 rows x 64 halves (128 B) each, 8 chunks/row -> 1024 chunks per tile
#pragma unroll
    for (int i = 0; i < 4; i++) {
        int c = tid + i * 256;
        int row = c >> 3;
        int cg = c & 7;
        CP16(base + (uint32_t)(row * 144 + cg * 16), qb + (size_t)row * DD + cg * 8);
        CP16(base + (uint32_t)(QBYTES + row * 144 + cg * 16), kb + (size_t)row * DD + cg * 8);
    }
    CP_COMMIT();
    CP_WAIT0();
    __syncthreads();

    float acc[4][4][4];
#pragma unroll
    for (int mt = 0; mt < 4; mt++)
#pragma unroll
        for (int nt = 0; nt < 4; nt++)
#pragma unroll
            for (int i = 0; i < 4; i++) acc[mt][nt][i] = 0.f;

    const uint32_t qF = base + (uint32_t)(((wm * 64 + (lane & 15)) * QP + (lane >> 4) * 8) * 2);
    // K non-trans: nrow = (lane&7) + (lane>>4)*8, dcol = ((lane>>3)&1)*8
    const uint32_t kF = base + (uint32_t)(QBYTES +
        ((wn * 32 + (lane & 7) + (lane >> 4) * 8) * QP + ((lane >> 3) & 1) * 8) * 2);

#pragma unroll
    for (int ks = 0; ks < 4; ks++) {   // d = 64 = 4 x k16
        uint32_t af[4][4];
#pragma unroll
        for (int mt = 0; mt < 4; mt++)
            ldsm4(af[mt], qF + (uint32_t)(mt * 16 * QP * 2 + ks * 32));
        uint32_t bf[2][4];
        ldsm4(bf[0], kF + (uint32_t)(ks * 32));
        ldsm4(bf[1], kF + (uint32_t)(16 * QP * 2 + ks * 32));
#pragma unroll
        for (int nt = 0; nt < 4; nt++) {
            uint32_t b0 = bf[nt >> 1][(nt & 1) * 2];
            uint32_t b1 = bf[nt >> 1][(nt & 1) * 2 + 1];
#pragma unroll
            for (int mt = 0; mt < 4; mt++)
                mma_f16(acc[mt][nt], af[mt], b0, b1);
        }
    }

    __half* pz = p + (size_t)z * TT * TT;
#pragma unroll
    for (int mt = 0; mt < 4; mt++) {
        const int row = m0 + wm * 64 + mt * 16 + (lane >> 2);
#pragma unroll
        for (int nt = 0; nt < 4; nt++) {
            const int col = n0 + wn * 32 + nt * 8 + (lane & 3) * 2;
            __half2 h0 = __floats2half2_rn(acc[mt][nt][0] * 0.125f, acc[mt][nt][1] * 0.125f);
            __half2 h1 = __floats2half2_rn(acc[mt][nt][2] * 0.125f, acc[mt][nt][3] * 0.125f);
            *(__half2*)(pz + (size_t)row * TT + col) = h0;
            *(__half2*)(pz + (size_t)(row + 8) * TT + col) = h1;
        }
    }
}

// ---------------- causal softmax: one warp per row (half in/out) ----------------
__global__ __launch_bounds__(256)
void attn_sm(__half* __restrict__ p) {
    const int wid = threadIdx.x >> 5, lane = threadIdx.x & 31;
    const int t = blockIdx.x * 8 + wid;
    const int h = blockIdx.y, b = blockIdx.z;
    __half* row = p + ((size_t)((b * HH + h) * TT + t)) * TT;
    const int valid = t + 1;
    const int nj = (t >> 7) + 1;

    float4 v[8];
    float m = -INFINITY;
#pragma unroll
    for (int j = 0; j < 8; j++) {
        if (j < nj) {
            int c0 = j * 128 + lane * 4;
            uint2 u = *(const uint2*)(row + c0);
            float2 f0 = __half22float2(*(__half2*)&u.x);
            float2 f1 = __half22float2(*(__half2*)&u.y);
            float4 val;
            val.x = (c0 + 0 < valid) ? f0.x : -INFINITY;
            val.y = (c0 + 1 < valid) ? f0.y : -INFINITY;
            val.z = (c0 + 2 < valid) ? f1.x : -INFINITY;
            val.w = (c0 + 3 < valid) ? f1.y : -INFINITY;
            v[j] = val;
            m = fmaxf(m, fmaxf(fmaxf(val.x, val.y), fmaxf(val.z, val.w)));
        }
    }
#pragma unroll
    for (int o = 16; o; o >>= 1) m = fmaxf(m, __shfl_xor_sync(~0u, m, o));

    float sum = 0.f;
#pragma unroll
    for (int j = 0; j < 8; j++) {
        if (j < nj) {
            float2 e0 = exp2_pair((v[j].x - m) * L2E, (v[j].y - m) * L2E);
            float2 e1 = exp2_pair((v[j].z - m) * L2E, (v[j].w - m) * L2E);
            v[j] = make_float4(e0.x, e0.y, e1.x, e1.y);
            sum += e0.x + e0.y + e1.x + e1.y;
        }
    }
#pragma unroll
    for (int o = 16; o; o >>= 1) sum += __shfl_xor_sync(~0u, sum, o);
    float inv = 1.f / sum;
#pragma unroll
    for (int j = 0; j < 8; j++) {
        if (j < nj) {
            int c0 = j * 128 + lane * 4;
            __half2 h0 = __floats2half2_rn(v[j].x * inv, v[j].y * inv);
            __half2 h1 = __floats2half2_rn(v[j].z * inv, v[j].w * inv);
            uint2 u;
            u.x = *(uint32_t*)&h0; u.y = *(uint32_t*)&h1;
            *(uint2*)(row + c0) = u;
        }
    }
}

// ---------------- loss ----------------------------------------------------------
__global__ void loss_row_k(const float* __restrict__ logits, const int* __restrict__ tgt,
                           float* __restrict__ rl) {
    int row = blockIdx.x, tid = threadIdx.x;
    const float* lr = logits + (size_t)row * VV;
    __shared__ float red[256];
    float m = -INFINITY;
    for (int i = tid * 2; i < VV; i += 512) {
        float2 v = *(const float2*)(lr + i);
        m = fmaxf(m, fmaxf(v.x, v.y));
    }
    red[tid] = m; __syncthreads();
    for (int s = 128; s > 0; s >>= 1) { if (tid < s) red[tid] = fmaxf(red[tid], red[tid + s]); __syncthreads(); }
    m = red[0]; __syncthreads();
    float sum = 0.f;
    for (int i = tid * 2; i < VV; i += 512) {
        float2 v = *(const float2*)(lr + i);
        float2 e = exp2_pair((v.x - m) * L2E, (v.y - m) * L2E);
        sum += e.x + e.y;
    }
    red[tid] = sum; __syncthreads();
    for (int s = 128; s > 0; s >>= 1) { if (tid < s) red[tid] += red[tid + s]; __syncthreads(); }
    if (tid == 0) {
        float lse = m + logf(red[0]);
        rl[row] = lse - lr[tgt[row]];
    }
}

__global__ void loss_final_k(const float* __restrict__ rl, float* __restrict__ out) {
    __shared__ float red[256];
    int tid = threadIdx.x;
    float s = 0.f;
    for (int i = tid; i < ROWS; i += 256) s += rl[i];
    red[tid] = s; __syncthreads();
    for (int k = 128; k > 0; k >>= 1) { if (tid < k) red[tid] += red[tid + k]; __syncthreads(); }
    if (tid == 0) out[0] = red[0] * (1.0f / ROWS);
}

__global__ void fill0_k(float* p, size_t n) {
    size_t i = (size_t)blockIdx.x * blockDim.x + threadIdx.x;
    if (i < n) p[i] = 0.f;
}

// ---------------- host-side launcher -------------------------------------------
static inline void gemm(const __half* A, const __half* B, void* C,
                        int M, int N, int K, int lda, int ldb, int ldc,
                        int Nh, size_t hs, const float* bias, int flags,
                        int batch = 1, int batchH = 1,
                        size_t aO = 0, size_t aI = 0,
                        size_t bO = 0, size_t bI = 0,
                        size_t cO = 0, size_t cI = 0) {
    dim3 grid(N / 128, M / 128, batch);
    gemm_hc<<<grid, 256, GSMEM>>>(A, B, C, K, lda, ldb, ldc, Nh, hs, bias, flags,
                                  batchH, aO, aI, bO, bI, cO, cI);
}

extern "C" void kernel_launch(void* const* d_in, const int* in_sizes, int n_in,
                              void* d_out, int out_size) {
    const int*   ids   = (const int*)d_in[0];
    const int*   tgt   = (const int*)d_in[1];
    const float* tok   = (const float*)d_in[2];
    const float* pos   = (const float*)d_in[3];
    const float* Wq_i  = (const float*)d_in[4];
    const float* Wk_i  = (const float*)d_in[5];
    const float* Wv_i  = (const float*)d_in[6];
    const float* Wp_i  = (const float*)d_in[7];
    const float* bproj = (const float*)d_in[8];
    const float* ln1g  = (const float*)d_in[9];
    const float* ln1b  = (const float*)d_in[10];
    const float* ln2g  = (const float*)d_in[11];
    const float* ln2b  = (const float*)d_in[12];
    const float* W1_i  = (const float*)d_in[13];
    const float* b1    = (const float*)d_in[14];
    const float* W2_i  = (const float*)d_in[15];
    const float* b2    = (const float*)d_in[16];
    const float* lnfg  = (const float*)d_in[17];
    const float* lnfb  = (const float*)d_in[18];
    const float* Wh_i  = (const float*)d_in[19];
    const float* bhead = (const float*)d_in[20];

    float *x, *sk, *rl;
    __half *h, *qk, *v, *o, *p, *f, *wc;
    cudaGetSymbolAddress((void**)&x, g_x);
    cudaGetSymbolAddress((void**)&h, g_h);
    cudaGetSymbolAddress((void**)&qk, g_qk);
    cudaGetSymbolAddress((void**)&v, g_v);
    cudaGetSymbolAddress((void**)&o, g_o);
    cudaGetSymbolAddress((void**)&p, g_p);
    cudaGetSymbolAddress((void**)&f, g_f);
    cudaGetSymbolAddress((void**)&sk, g_sk);
    cudaGetSymbolAddress((void**)&rl, g_rl);
    cudaGetSymbolAddress((void**)&wc, g_wc);

    static bool attrSet = false;
    if (!attrSet) {
        cudaFuncSetAttribute(gemm_hc, cudaFuncAttributeMaxDynamicSharedMemorySize, GSMEM);
        cudaFuncSetAttribute(score_tc, cudaFuncAttributeMaxDynamicSharedMemorySize, SSMEM);
        attrSet = true;
    }

    __half* Wq = wc + O_WQ;  __half* Wk = wc + O_WK;  __half* Wv = wc + O_WV;
    __half* Wp = wc + O_WP;  __half* W1 = wc + O_W1;  __half* W2 = wc + O_W2;
    __half* Wh = wc + O_WH;
    __half* q = qk;
    __half* k = qk + (size_t)ROWS * DD;

    float* out = (float*)d_out;
    const size_t NL = (size_t)ROWS * VV;

    embed_k<<<ROWS, 256>>>(ids, tok, pos, x);
    cvt_k<<<1024, 256>>>((const float4*)Wq_i, (uint2*)Wq, (size_t)WQ_SZ / 4);
    cvt_k<<<1024, 256>>>((const float4*)Wk_i, (uint2*)Wk, (size_t)WQ_SZ / 4);
    ln_k<<<ROWS / 8, 256>>>(x, h, ln1g, ln1b);
    cvt_k<<<2048, 256>>>((const float4*)Wv_i, (uint2*)Wv, (size_t)WV_SZ / 4);
    // merged q/k projection for layer 0
    gemm(h, Wq, q, ROWS, DD, DD, DD, KH, DD, KH, (size_t)DD * KH, nullptr, 32,
         2, 1, 0, 0, (size_t)WQ_SZ, 0, (size_t)ROWS * DD, 0);
    cvt_k<<<2048, 256>>>((const float4*)Wp_i, (uint2*)Wp, (size_t)WP_SZ / 4);
    cvt_k<<<1024, 256>>>((const float4*)W1_i, (uint2*)W1, (size_t)W1_SZ / 4);
    cvt_k<<<1024, 256>>>((const float4*)W2_i, (uint2*)W2, (size_t)W1_SZ / 4);
    cvt_k<<<2048, 256>>>((const float4*)Wh_i, (uint2*)Wh, (size_t)WH_SZ / 4);

    for (int l = 0; l < LL; l++) {
        if (l > 0) {
            ln_k<<<ROWS / 8, 256>>>(x, h, ln1g + l * DD, ln1b + l * DD);
            gemm(h, Wq + (size_t)l * HH * DD * KH, q, ROWS, DD, DD, DD, KH, DD,
                 KH, (size_t)DD * KH, nullptr, 32,
                 2, 1, 0, 0, (size_t)WQ_SZ, 0, (size_t)ROWS * DD, 0);
        }
        gemm(h, Wv + (size_t)l * HH * DD * DD, v, ROWS, HD, DD, DD, DD, HD,
             DD, (size_t)DD * DD, nullptr, 32);
        {
            dim3 grid(TT / 128, TT / 128, BSZ * HH);
            score_tc<<<grid, 256, SSMEM>>>(q, k, p);
            dim3 grid2(TT / 8, HH, BSZ);
            attn_sm<<<grid2, 256>>>(p);
        }
        gemm(p, v, o, TT, DD, TT, TT, HD, HD, DD, 0, nullptr, 8 | 32,
             BSZ * HH, HH,
             (size_t)HH * TT * TT, (size_t)TT * TT,
             (size_t)TT * HD, (size_t)DD,
             (size_t)TT * HD, (size_t)DD);
        // proj: split-K x2 (fp32 partials), combine into x
        gemm(o, Wp + (size_t)l * HD * DD, sk, ROWS, DD, HD / 2, HD, DD, DD,
             DD, 0, nullptr, 0,
             2, 1, (size_t)(HD / 2), 0, (size_t)(HD / 2) * DD, 0, (size_t)ROWS * DD, 0);
        addsk_k<<<ROWS * DD / 1024, 256>>>((const float4*)sk,
                                           (const float4*)(sk + (size_t)ROWS * DD),
                                           bproj + l * DD, (float4*)x);
        ln_k<<<ROWS / 8, 256>>>(x, h, ln2g + l * DD, ln2b + l * DD);
        gemm(h, W1 + (size_t)l * DD * FF, f, ROWS, FF, DD, DD, FF, FF,
             FF, 0, b1 + l * FF, 1 | 2 | 32);
        gemm(f, W2 + (size_t)l * FF * DD, sk, ROWS, DD, FF / 2, FF, DD, DD,
             DD, 0, nullptr, 0,
             2, 1, (size_t)(FF / 2), 0, (size_t)(FF / 2) * DD, 0, (size_t)ROWS * DD, 0);
        addsk_k<<<ROWS * DD / 1024, 256>>>((const float4*)sk,
                                           (const float4*)(sk + (size_t)ROWS * DD),
                                           b2 + l * DD, (float4*)x);
    }

    ln_k<<<ROWS / 8, 256>>>(x, h, lnfg, lnfb);

    gemm(h, Wh, out, ROWS, VV, DD, DD, VV, VV, VV, 0, bhead, 1);
    loss_row_k<<<ROWS, 256>>>(out, tgt, rl);
    if ((size_t)out_size >= NL + 1) {
        loss_final_k<<<1, 256>>>(rl, out + NL);
        size_t tail = (size_t)out_size - (NL + 1);
        if (tail > 0)
            fill0_k<<<(int)((tail + 255) / 256), 256>>>(out + NL + 1, tail);
    }
}